// round 1
// baseline (speedup 1.0000x reference)
#include <cuda_runtime.h>
#include <math.h>

#define D_MODEL 1024
#define NUM_HEADS 16
#define DK 64
#define BATCH 4
#define SEQ 2048
#define MROWS (BATCH * SEQ)   /* 8192 */

// -------- scratch (static device arrays; no allocation allowed) --------
__device__ float g_Q[BATCH * NUM_HEADS * SEQ * DK];
__device__ float g_K[BATCH * NUM_HEADS * SEQ * DK];
__device__ float g_V[BATCH * NUM_HEADS * SEQ * DK];
__device__ float g_ctx[MROWS * D_MODEL];

// ============================================================================
// GEMM: C = A[M,K] @ W[N,K]^T + bias   (torch Linear semantics)
// Block tile 128x128, BK=16, 256 threads, 8x8 per-thread register tile.
// split==0: C row-major [M,N]
// split==1: C written split-heads: [B, H, S, DK], m=(b,s), n=(h,d)
// ============================================================================
__global__ __launch_bounds__(256) void gemm_bias_kernel(
    const float* __restrict__ A, const float* __restrict__ W,
    const float* __restrict__ bias, float* __restrict__ C,
    int M, int N, int K, int split)
{
    __shared__ float As[16][128];
    __shared__ float Bs[16][128];

    const int t  = threadIdx.x;
    const int tx = t & 15;
    const int ty = t >> 4;
    const int m0 = blockIdx.y * 128;
    const int n0 = blockIdx.x * 128;
    const int lr = t >> 2;          // 0..63
    const int lc = (t & 3) * 4;     // 0,4,8,12

    float acc[8][8];
#pragma unroll
    for (int i = 0; i < 8; i++)
#pragma unroll
        for (int j = 0; j < 8; j++) acc[i][j] = 0.0f;

    for (int k0 = 0; k0 < K; k0 += 16) {
#pragma unroll
        for (int rr = 0; rr < 2; rr++) {
            int r = lr + rr * 64;
            float4 va = *(const float4*)(A + (size_t)(m0 + r) * K + k0 + lc);
            As[lc + 0][r] = va.x; As[lc + 1][r] = va.y;
            As[lc + 2][r] = va.z; As[lc + 3][r] = va.w;
            float4 vb = *(const float4*)(W + (size_t)(n0 + r) * K + k0 + lc);
            Bs[lc + 0][r] = vb.x; Bs[lc + 1][r] = vb.y;
            Bs[lc + 2][r] = vb.z; Bs[lc + 3][r] = vb.w;
        }
        __syncthreads();

#pragma unroll
        for (int kk = 0; kk < 16; kk++) {
            float ra[8], rb[8];
            *(float4*)&ra[0] = *(const float4*)&As[kk][ty * 8];
            *(float4*)&ra[4] = *(const float4*)&As[kk][ty * 8 + 4];
            *(float4*)&rb[0] = *(const float4*)&Bs[kk][tx * 8];
            *(float4*)&rb[4] = *(const float4*)&Bs[kk][tx * 8 + 4];
#pragma unroll
            for (int i = 0; i < 8; i++)
#pragma unroll
                for (int j = 0; j < 8; j++)
                    acc[i][j] += ra[i] * rb[j];
        }
        __syncthreads();
    }

    // ---- epilogue ----
    const int nb = n0 + tx * 8;
    float bs[8];
#pragma unroll
    for (int j = 0; j < 8; j++) bs[j] = bias[nb + j];

#pragma unroll
    for (int i = 0; i < 8; i++) {
        int m = m0 + ty * 8 + i;
        float4 v0, v1;
        v0.x = acc[i][0] + bs[0]; v0.y = acc[i][1] + bs[1];
        v0.z = acc[i][2] + bs[2]; v0.w = acc[i][3] + bs[3];
        v1.x = acc[i][4] + bs[4]; v1.y = acc[i][5] + bs[5];
        v1.z = acc[i][6] + bs[6]; v1.w = acc[i][7] + bs[7];
        if (!split) {
            float* dst = C + (size_t)m * N + nb;
            *(float4*)dst = v0;
            *(float4*)(dst + 4) = v1;
        } else {
            int b = m >> 11;          // m / SEQ
            int s = m & 2047;         // m % SEQ
            int h = nb >> 6;          // nb / DK   (constant per thread)
            int d = nb & 63;          // nb % DK   (mult of 8, float4 safe)
            float* dst = C + (((size_t)(b * NUM_HEADS + h) * SEQ + s) * DK + d);
            *(float4*)dst = v0;
            *(float4*)(dst + 4) = v1;
        }
    }
}

// ============================================================================
// Flash-style attention. Grid: (SEQ/128 q-tiles, B*H). 256 threads.
// Per k-tile of 128 keys: S = Q K^T * scale  -> online softmax -> O += P V.
// Q/K staged d-major in smem, V row-major, P materialized in smem.
// ============================================================================
__global__ __launch_bounds__(256) void attn_kernel(float* __restrict__ ctx)
{
    extern __shared__ float sm[];
    float* Qs  = sm;                   // [64][128]  (d-major)
    float* Ks  = Qs + 64 * 128;        // [64][128]  (d-major)
    float* Vs  = Ks + 64 * 128;        // [128][68]  (key-major, padded)
    float* Ps  = Vs + 128 * 68;        // [128][132] (row-major, padded)
    float* red = Ps + 128 * 132;       // [128][16]

    const int t  = threadIdx.x;
    const int tx = t & 15;
    const int ty = t >> 4;
    const int qt = blockIdx.x;         // q tile 0..15
    const int bh = blockIdx.y;         // 0..63

    const float* Qg = g_Q + (size_t)bh * SEQ * DK + (size_t)qt * 128 * DK;
    const float* Kg = g_K + (size_t)bh * SEQ * DK;
    const float* Vg = g_V + (size_t)bh * SEQ * DK;

    // load Q tile (128 rows x 64 d) transposed -> Qs[d][row]
#pragma unroll
    for (int p = 0; p < 8; p++) {
        int idx = t + p * 256;
        int r = idx >> 4;
        int c = (idx & 15) * 4;
        float4 v = *(const float4*)(Qg + r * DK + c);
        Qs[(c + 0) * 128 + r] = v.x; Qs[(c + 1) * 128 + r] = v.y;
        Qs[(c + 2) * 128 + r] = v.z; Qs[(c + 3) * 128 + r] = v.w;
    }

    float m[8], l[8], acc[8][4];
#pragma unroll
    for (int i = 0; i < 8; i++) {
        m[i] = -1e30f; l[i] = 0.0f;
#pragma unroll
        for (int j = 0; j < 4; j++) acc[i][j] = 0.0f;
    }

    for (int kt = 0; kt < SEQ / 128; kt++) {
        __syncthreads();   // Q ready (kt=0) / prev-iter consumers done

        const float* kg = Kg + (size_t)kt * 128 * DK;
        const float* vg = Vg + (size_t)kt * 128 * DK;
#pragma unroll
        for (int p = 0; p < 8; p++) {
            int idx = t + p * 256;
            int r = idx >> 4;
            int c = (idx & 15) * 4;
            float4 v = *(const float4*)(kg + r * DK + c);
            Ks[(c + 0) * 128 + r] = v.x; Ks[(c + 1) * 128 + r] = v.y;
            Ks[(c + 2) * 128 + r] = v.z; Ks[(c + 3) * 128 + r] = v.w;
            float4 w = *(const float4*)(vg + r * DK + c);
            *(float4*)(Vs + r * 68 + c) = w;
        }
        __syncthreads();

        // ---- S = Q K^T (8x8 micro-tile per thread) ----
        float s[8][8];
#pragma unroll
        for (int i = 0; i < 8; i++)
#pragma unroll
            for (int j = 0; j < 8; j++) s[i][j] = 0.0f;

#pragma unroll 8
        for (int d = 0; d < 64; d++) {
            float qa[8], kb[8];
            *(float4*)&qa[0] = *(const float4*)(Qs + d * 128 + ty * 8);
            *(float4*)&qa[4] = *(const float4*)(Qs + d * 128 + ty * 8 + 4);
            *(float4*)&kb[0] = *(const float4*)(Ks + d * 128 + tx * 8);
            *(float4*)&kb[4] = *(const float4*)(Ks + d * 128 + tx * 8 + 4);
#pragma unroll
            for (int i = 0; i < 8; i++)
#pragma unroll
                for (int j = 0; j < 8; j++)
                    s[i][j] += qa[i] * kb[j];
        }

        const float scale = 0.125f;    // 1/sqrt(64)
#pragma unroll
        for (int i = 0; i < 8; i++)
#pragma unroll
            for (int j = 0; j < 8; j++) s[i][j] *= scale;

        // ---- row max (smem reduction across 16 tx threads) ----
#pragma unroll
        for (int i = 0; i < 8; i++) {
            float mx = s[i][0];
#pragma unroll
            for (int j = 1; j < 8; j++) mx = fmaxf(mx, s[i][j]);
            red[(ty * 8 + i) * 16 + tx] = mx;
        }
        __syncthreads();

        float newm[8], alpha[8];
#pragma unroll
        for (int i = 0; i < 8; i++) {
            int row = ty * 8 + i;
            float mx = -1e30f;
#pragma unroll
            for (int u = 0; u < 16; u++) mx = fmaxf(mx, red[row * 16 + u]);
            newm[i]  = fmaxf(m[i], mx);
            alpha[i] = __expf(m[i] - newm[i]);
            m[i]     = newm[i];
        }
        __syncthreads();   // everyone done reading red (max) before sum writes

        // ---- exp + row sum ----
#pragma unroll
        for (int i = 0; i < 8; i++) {
            float sum = 0.0f;
#pragma unroll
            for (int j = 0; j < 8; j++) {
                float p = __expf(s[i][j] - newm[i]);
                s[i][j] = p;
                sum += p;
            }
            red[(ty * 8 + i) * 16 + tx] = sum;
        }
        __syncthreads();

#pragma unroll
        for (int i = 0; i < 8; i++) {
            int row = ty * 8 + i;
            float tot = 0.0f;
#pragma unroll
            for (int u = 0; u < 16; u++) tot += red[row * 16 + u];
            l[i] = l[i] * alpha[i] + tot;
        }

        // ---- materialize P ----
#pragma unroll
        for (int i = 0; i < 8; i++) {
            int row = ty * 8 + i;
            float4 p0, p1;
            p0.x = s[i][0]; p0.y = s[i][1]; p0.z = s[i][2]; p0.w = s[i][3];
            p1.x = s[i][4]; p1.y = s[i][5]; p1.z = s[i][6]; p1.w = s[i][7];
            *(float4*)(Ps + row * 132 + tx * 8)     = p0;
            *(float4*)(Ps + row * 132 + tx * 8 + 4) = p1;
        }
        __syncthreads();

        // ---- rescale O, then O += P V ----
#pragma unroll
        for (int i = 0; i < 8; i++)
#pragma unroll
            for (int j = 0; j < 4; j++) acc[i][j] *= alpha[i];

#pragma unroll 4
        for (int kk = 0; kk < 128; kk += 4) {
            float pr[8][4];
#pragma unroll
            for (int i = 0; i < 8; i++) {
                float4 v = *(const float4*)(Ps + (ty * 8 + i) * 132 + kk);
                pr[i][0] = v.x; pr[i][1] = v.y; pr[i][2] = v.z; pr[i][3] = v.w;
            }
            float vr[4][4];
#pragma unroll
            for (int q = 0; q < 4; q++) {
                float4 v = *(const float4*)(Vs + (kk + q) * 68 + tx * 4);
                vr[q][0] = v.x; vr[q][1] = v.y; vr[q][2] = v.z; vr[q][3] = v.w;
            }
#pragma unroll
            for (int q = 0; q < 4; q++)
#pragma unroll
                for (int i = 0; i < 8; i++)
#pragma unroll
                    for (int j = 0; j < 4; j++)
                        acc[i][j] += pr[i][q] * vr[q][j];
        }
    }

    // ---- epilogue: normalize, write ctx in [B, S, H*DK] layout ----
    const int b = bh >> 4;
    const int h = bh & 15;
#pragma unroll
    for (int i = 0; i < 8; i++) {
        int srow = qt * 128 + ty * 8 + i;
        float inv = 1.0f / l[i];
        float4 o;
        o.x = acc[i][0] * inv; o.y = acc[i][1] * inv;
        o.z = acc[i][2] * inv; o.w = acc[i][3] * inv;
        *(float4*)(ctx + (size_t)(b * SEQ + srow) * D_MODEL + h * DK + tx * 4) = o;
    }
}

// ============================================================================
// launch
// ============================================================================
extern "C" void kernel_launch(void* const* d_in, const int* in_sizes, int n_in,
                              void* d_out, int out_size)
{
    const float* query  = (const float*)d_in[0];
    const float* key_in = (const float*)d_in[1];
    const float* value  = (const float*)d_in[2];
    const float* Wq = (const float*)d_in[3];
    const float* bq = (const float*)d_in[4];
    const float* Wk = (const float*)d_in[5];
    const float* bk = (const float*)d_in[6];
    const float* Wv = (const float*)d_in[7];
    const float* bv = (const float*)d_in[8];
    const float* Wo = (const float*)d_in[9];
    const float* bo = (const float*)d_in[10];
    float* out = (float*)d_out;

    float *qp, *kp, *vp, *cp;
    cudaGetSymbolAddress((void**)&qp, g_Q);
    cudaGetSymbolAddress((void**)&kp, g_K);
    cudaGetSymbolAddress((void**)&vp, g_V);
    cudaGetSymbolAddress((void**)&cp, g_ctx);

    dim3 gblk(256);
    dim3 ggrd(D_MODEL / 128, MROWS / 128);

    // Q/K/V projections (split-head output layout)
    gemm_bias_kernel<<<ggrd, gblk>>>(query,  Wq, bq, qp, MROWS, D_MODEL, D_MODEL, 1);
    gemm_bias_kernel<<<ggrd, gblk>>>(key_in, Wk, bk, kp, MROWS, D_MODEL, D_MODEL, 1);
    gemm_bias_kernel<<<ggrd, gblk>>>(value,  Wv, bv, vp, MROWS, D_MODEL, D_MODEL, 1);

    // attention
    size_t smem = (size_t)(64 * 128 + 64 * 128 + 128 * 68 + 128 * 132 + 128 * 16) * sizeof(float);
    cudaFuncSetAttribute(attn_kernel, cudaFuncAttributeMaxDynamicSharedMemorySize, (int)smem);
    attn_kernel<<<dim3(SEQ / 128, BATCH * NUM_HEADS), gblk, smem>>>(cp);

    // output projection (row-major output)
    gemm_bias_kernel<<<ggrd, gblk>>>(cp, Wo, bo, out, MROWS, D_MODEL, D_MODEL, 0);
}

// round 3
// speedup vs baseline: 2.4322x; 2.4322x over previous
#include <cuda_runtime.h>
#include <cuda_bf16.h>
#include <cstdint>

#define D_MODEL 1024
#define NUM_HEADS 16
#define DK 64
#define BATCH 4
#define SEQ 2048
#define MROWS (BATCH * SEQ)   /* 8192 */
#define KVTILES (SEQ / 128)   /* 16 */

// ---------------- scratch (bf16 hi/lo everywhere) ----------------
__device__ __nv_bfloat16 g_Qhi[BATCH * NUM_HEADS * SEQ * DK];
__device__ __nv_bfloat16 g_Qlo[BATCH * NUM_HEADS * SEQ * DK];
__device__ __nv_bfloat16 g_Khi[BATCH * NUM_HEADS * SEQ * DK];
__device__ __nv_bfloat16 g_Klo[BATCH * NUM_HEADS * SEQ * DK];
__device__ __nv_bfloat16 g_Vhi[BATCH * NUM_HEADS * SEQ * DK];
__device__ __nv_bfloat16 g_Vlo[BATCH * NUM_HEADS * SEQ * DK];
__device__ __nv_bfloat16 g_ahi[MROWS * D_MODEL];
__device__ __nv_bfloat16 g_alo[MROWS * D_MODEL];
__device__ __nv_bfloat16 g_whi[D_MODEL * D_MODEL];
__device__ __nv_bfloat16 g_wlo[D_MODEL * D_MODEL];

// ---------------- helpers ----------------
__device__ __forceinline__ uint32_t smem_u32(const void* p) {
    uint32_t a;
    asm("{ .reg .u64 t; cvta.to.shared.u64 t, %1; cvt.u32.u64 %0, t; }" : "=r"(a) : "l"(p));
    return a;
}
#define CP_ASYNC16(saddr, gptr) \
    asm volatile("cp.async.cg.shared.global [%0], [%1], 16;" :: "r"((uint32_t)(saddr)), "l"(gptr))
#define CP_ASYNC_COMMIT()    asm volatile("cp.async.commit_group;" ::: "memory")
#define CP_ASYNC_WAIT_ALL()  asm volatile("cp.async.wait_group 0;" ::: "memory")
#define CP_ASYNC_WAIT_1()    asm volatile("cp.async.wait_group 1;" ::: "memory")

__device__ __forceinline__ void ldsm4(uint32_t r[4], uint32_t a) {
    asm volatile("ldmatrix.sync.aligned.m8n8.x4.shared.b16 {%0,%1,%2,%3}, [%4];"
        : "=r"(r[0]), "=r"(r[1]), "=r"(r[2]), "=r"(r[3]) : "r"(a));
}
__device__ __forceinline__ void ldsm4t(uint32_t r[4], uint32_t a) {
    asm volatile("ldmatrix.sync.aligned.m8n8.x4.trans.shared.b16 {%0,%1,%2,%3}, [%4];"
        : "=r"(r[0]), "=r"(r[1]), "=r"(r[2]), "=r"(r[3]) : "r"(a));
}
__device__ __forceinline__ void mma16816(float c[4], const uint32_t a[4], uint32_t b0, uint32_t b1) {
    asm volatile("mma.sync.aligned.m16n8k16.row.col.f32.bf16.bf16.f32 "
        "{%0,%1,%2,%3}, {%4,%5,%6,%7}, {%8,%9}, {%0,%1,%2,%3};"
        : "+f"(c[0]), "+f"(c[1]), "+f"(c[2]), "+f"(c[3])
        : "r"(a[0]), "r"(a[1]), "r"(a[2]), "r"(a[3]), "r"(b0), "r"(b1));
}
__device__ __forceinline__ uint32_t pack_hi(float x, float y) {
    __nv_bfloat162 h = __floats2bfloat162_rn(x, y);
    return *(uint32_t*)&h;
}
__device__ __forceinline__ uint32_t pack_lo(float x, float y) {
    float xr = x - __bfloat162float(__float2bfloat16(x));
    float yr = y - __bfloat162float(__float2bfloat16(y));
    __nv_bfloat162 h = __floats2bfloat162_rn(xr, yr);
    return *(uint32_t*)&h;
}

// ============================================================================
// fp32 -> (bf16 hi, bf16 lo)
// ============================================================================
__global__ __launch_bounds__(256) void conv_hilo(const float* __restrict__ x,
                                                 __nv_bfloat16* __restrict__ hi,
                                                 __nv_bfloat16* __restrict__ lo, int n4)
{
    int i = blockIdx.x * blockDim.x + threadIdx.x;
    if (i >= n4) return;
    float4 v = ((const float4*)x)[i];
    uint2 H, L;
    H.x = pack_hi(v.x, v.y); H.y = pack_hi(v.z, v.w);
    L.x = pack_lo(v.x, v.y); L.y = pack_lo(v.z, v.w);
    ((uint2*)hi)[i] = H;
    ((uint2*)lo)[i] = L;
}

// ============================================================================
// HMMA GEMM: C[M,N] = (Ahi+Alo) @ (Whi+Wlo)^T + bias   (3-term hi/lo)
// BM=128 BN=128 BK=32, 8 warps (2x4), per-warp 64x32, double-buffered cp.async.
// split==0: fp32 row-major out. split==1: bf16 hi/lo out in [B,H,S,DK].
// ============================================================================
#define BK 32
#define GPAD 40                      /* row pad in bf16 elems */
#define MAT_B (128 * GPAD * 2)       /* one matrix stage: 10240 B */
#define STG_B (4 * MAT_B)            /* Ahi,Alo,Whi,Wlo */
#define NIT (D_MODEL / BK)           /* 32 */
#define GEMM_SMEM (2 * STG_B)        /* 81920 B */

__global__ __launch_bounds__(256) void gemm_tc(
    const __nv_bfloat16* __restrict__ Ahi, const __nv_bfloat16* __restrict__ Alo,
    const __nv_bfloat16* __restrict__ Whi, const __nv_bfloat16* __restrict__ Wlo,
    const float* __restrict__ bias,
    float* __restrict__ Cf,
    __nv_bfloat16* __restrict__ Chi, __nv_bfloat16* __restrict__ Clo,
    int split)
{
    extern __shared__ char smem[];
    const uint32_t sb = smem_u32(smem);
    const int t = threadIdx.x;
    const int lane = t & 31, wid = t >> 5;
    const int wm = wid >> 2, wn = wid & 3;
    const int m0 = blockIdx.y * 128, n0 = blockIdx.x * 128;

    float c[4][4][4];
#pragma unroll
    for (int i = 0; i < 4; i++)
#pragma unroll
        for (int j = 0; j < 4; j++)
#pragma unroll
            for (int k = 0; k < 4; k++) c[i][j][k] = 0.0f;

    auto load_stage = [&](int s, int it) {
        const int k0 = it * BK;
        const uint32_t st = sb + s * STG_B;
#pragma unroll
        for (int j = 0; j < 2; j++) {
            int idx = t + j * 256;
            int r = idx >> 2, cc = idx & 3;
            uint32_t so = (uint32_t)(r * (GPAD * 2) + cc * 16);
            const __nv_bfloat16* ga = Ahi + (size_t)(m0 + r) * D_MODEL + k0 + cc * 8;
            const __nv_bfloat16* gl = Alo + (size_t)(m0 + r) * D_MODEL + k0 + cc * 8;
            const __nv_bfloat16* gw = Whi + (size_t)(n0 + r) * D_MODEL + k0 + cc * 8;
            const __nv_bfloat16* gv = Wlo + (size_t)(n0 + r) * D_MODEL + k0 + cc * 8;
            CP_ASYNC16(st + 0 * MAT_B + so, ga);
            CP_ASYNC16(st + 1 * MAT_B + so, gl);
            CP_ASYNC16(st + 2 * MAT_B + so, gw);
            CP_ASYNC16(st + 3 * MAT_B + so, gv);
        }
    };

    load_stage(0, 0);
    CP_ASYNC_COMMIT();

    for (int it = 0; it < NIT; ++it) {
        const int s = it & 1;
        if (it + 1 < NIT) {
            load_stage(s ^ 1, it + 1);
            CP_ASYNC_COMMIT();
            CP_ASYNC_WAIT_1();
        } else {
            CP_ASYNC_WAIT_ALL();
        }
        __syncthreads();

        const uint32_t st = sb + s * STG_B;
#pragma unroll
        for (int kk = 0; kk < 2; kk++) {
            uint32_t ah[4][4], al[4][4];
#pragma unroll
            for (int mi = 0; mi < 4; mi++) {
                uint32_t ro = (uint32_t)((wm * 64 + mi * 16 + (lane & 15)) * (GPAD * 2)
                                         + (kk * 16 + (lane >> 4) * 8) * 2);
                ldsm4(ah[mi], st + 0 * MAT_B + ro);
                ldsm4(al[mi], st + 1 * MAT_B + ro);
            }
            uint32_t bh_[2][4], bl_[2][4];
#pragma unroll
            for (int nj = 0; nj < 2; nj++) {
                uint32_t ro = (uint32_t)((wn * 32 + nj * 16 + (lane & 7) + ((lane >> 4) * 8)) * (GPAD * 2)
                                         + (kk * 16 + ((lane >> 3) & 1) * 8) * 2);
                ldsm4(bh_[nj], st + 2 * MAT_B + ro);
                ldsm4(bl_[nj], st + 3 * MAT_B + ro);
            }
#pragma unroll
            for (int mi = 0; mi < 4; mi++)
#pragma unroll
                for (int ni = 0; ni < 4; ni++) {
                    const int nj = ni >> 1, ss = (ni & 1) * 2;
                    mma16816(c[mi][ni], ah[mi], bh_[nj][ss], bh_[nj][ss + 1]);
                    mma16816(c[mi][ni], ah[mi], bl_[nj][ss], bl_[nj][ss + 1]);
                    mma16816(c[mi][ni], al[mi], bh_[nj][ss], bh_[nj][ss + 1]);
                }
        }
        __syncthreads();
    }

    // ---- epilogue ----
#pragma unroll
    for (int mi = 0; mi < 4; mi++) {
        const int r0 = m0 + wm * 64 + mi * 16 + (lane >> 2);
#pragma unroll
        for (int ni = 0; ni < 4; ni++) {
            const int col = n0 + wn * 32 + ni * 8 + (lane & 3) * 2;
            const float b0 = bias[col], b1 = bias[col + 1];
            float v00 = c[mi][ni][0] + b0, v01 = c[mi][ni][1] + b1;
            float v10 = c[mi][ni][2] + b0, v11 = c[mi][ni][3] + b1;
            if (!split) {
                float2* d0 = (float2*)(Cf + (size_t)r0 * D_MODEL + col);
                float2* d1 = (float2*)(Cf + (size_t)(r0 + 8) * D_MODEL + col);
                *d0 = make_float2(v00, v01);
                *d1 = make_float2(v10, v11);
            } else {
                const int h = col >> 6, d = col & 63;
#pragma unroll
                for (int rr = 0; rr < 2; rr++) {
                    const int m = r0 + rr * 8;
                    const int b = m >> 11, sdx = m & 2047;
                    const size_t off = (((size_t)(b * NUM_HEADS + h) * SEQ + sdx) * DK + d);
                    const float x = rr ? v10 : v00, y = rr ? v11 : v01;
                    *(uint32_t*)(Chi + off) = pack_hi(x, y);
                    *(uint32_t*)(Clo + off) = pack_lo(x, y);
                }
            }
        }
    }
}

// ============================================================================
// HMMA flash attention. Grid (16 q-tiles, 64 bh). 256 threads (8 warps 2x4).
// S = QK^T (3-term hi/lo), fp32 online softmax in frags, P -> bf16 hi/lo smem,
// O += PV (3-term). Output written as bf16 hi/lo into g_ahi/g_alo [B,S,1024].
// ============================================================================
#define APAD 72                      /* Q/K/V row pad (bf16) */
#define AST  (APAD * 2)              /* 144 B row stride */
#define PPAD 136
#define PST  (PPAD * 2)              /* 272 B row stride */
#define OFF_QHI 0
#define OFF_QLO (OFF_QHI + 128 * AST)
#define OFF_KHI (OFF_QLO + 128 * AST)
#define OFF_KLO (OFF_KHI + 128 * AST)
#define OFF_VHI (OFF_KLO + 128 * AST)
#define OFF_VLO (OFF_VHI + 128 * AST)
#define OFF_PHI (OFF_VLO + 128 * AST)
#define OFF_PLO (OFF_PHI + 128 * PST)
#define OFF_RED (OFF_PLO + 128 * PST)
#define ATTN_SMEM (OFF_RED + 128 * 4 * 4)   /* 182272 B */

__global__ __launch_bounds__(256) void attn_tc()
{
    extern __shared__ char smem[];
    const uint32_t sb = smem_u32(smem);
    float* red = (float*)(smem + OFF_RED);
    const int t = threadIdx.x;
    const int lane = t & 31, wid = t >> 5;
    const int wm = wid >> 2, wn = wid & 3;
    const int qt = blockIdx.x, bh = blockIdx.y;

    const __nv_bfloat16* Qh = g_Qhi + ((size_t)bh * SEQ + qt * 128) * DK;
    const __nv_bfloat16* Ql = g_Qlo + ((size_t)bh * SEQ + qt * 128) * DK;
    const __nv_bfloat16* Kh = g_Khi + (size_t)bh * SEQ * DK;
    const __nv_bfloat16* Kl = g_Klo + (size_t)bh * SEQ * DK;
    const __nv_bfloat16* Vh = g_Vhi + (size_t)bh * SEQ * DK;
    const __nv_bfloat16* Vl = g_Vlo + (size_t)bh * SEQ * DK;

    auto ldtile = [&](uint32_t dstoff, const __nv_bfloat16* src) {   // 128x64 bf16
#pragma unroll
        for (int j = 0; j < 4; j++) {
            int idx = t + j * 256;
            int r = idx >> 3, cc = idx & 7;
            CP_ASYNC16(sb + dstoff + r * AST + cc * 16, src + r * DK + cc * 8);
        }
    };

    ldtile(OFF_QHI, Qh); ldtile(OFF_QLO, Ql);
    ldtile(OFF_KHI, Kh); ldtile(OFF_KLO, Kl);
    ldtile(OFF_VHI, Vh); ldtile(OFF_VLO, Vl);
    CP_ASYNC_COMMIT();
    CP_ASYNC_WAIT_ALL();
    __syncthreads();

    float o[4][2][4];
    float mrow[4][2], lrow[4][2];
#pragma unroll
    for (int mi = 0; mi < 4; mi++) {
        mrow[mi][0] = mrow[mi][1] = -1e30f;
        lrow[mi][0] = lrow[mi][1] = 0.0f;
#pragma unroll
        for (int nj = 0; nj < 2; nj++)
#pragma unroll
            for (int k = 0; k < 4; k++) o[mi][nj][k] = 0.0f;
    }

    for (int kt = 0; kt < KVTILES; kt++) {
        // ---- S = Q K^T ----
        float c[4][4][4];
#pragma unroll
        for (int i = 0; i < 4; i++)
#pragma unroll
            for (int j = 0; j < 4; j++)
#pragma unroll
                for (int k = 0; k < 4; k++) c[i][j][k] = 0.0f;

#pragma unroll
        for (int kk = 0; kk < 4; kk++) {
            uint32_t ah[4][4], al[4][4];
#pragma unroll
            for (int mi = 0; mi < 4; mi++) {
                uint32_t ro = (uint32_t)((wm * 64 + mi * 16 + (lane & 15)) * AST
                                         + (kk * 16 + (lane >> 4) * 8) * 2);
                ldsm4(ah[mi], sb + OFF_QHI + ro);
                ldsm4(al[mi], sb + OFF_QLO + ro);
            }
            uint32_t bh_[2][4], bl_[2][4];
#pragma unroll
            for (int nj = 0; nj < 2; nj++) {
                uint32_t ro = (uint32_t)((wn * 32 + nj * 16 + (lane & 7) + ((lane >> 4) * 8)) * AST
                                         + (kk * 16 + ((lane >> 3) & 1) * 8) * 2);
                ldsm4(bh_[nj], sb + OFF_KHI + ro);
                ldsm4(bl_[nj], sb + OFF_KLO + ro);
            }
#pragma unroll
            for (int mi = 0; mi < 4; mi++)
#pragma unroll
                for (int ni = 0; ni < 4; ni++) {
                    const int nj = ni >> 1, ss = (ni & 1) * 2;
                    mma16816(c[mi][ni], ah[mi], bh_[nj][ss], bh_[nj][ss + 1]);
                    mma16816(c[mi][ni], ah[mi], bl_[nj][ss], bl_[nj][ss + 1]);
                    mma16816(c[mi][ni], al[mi], bh_[nj][ss], bh_[nj][ss + 1]);
                }
        }

        const float scale = 0.125f;
#pragma unroll
        for (int i = 0; i < 4; i++)
#pragma unroll
            for (int j = 0; j < 4; j++)
#pragma unroll
                for (int k = 0; k < 4; k++) c[i][j][k] *= scale;

        // ---- row max ----
#pragma unroll
        for (int mi = 0; mi < 4; mi++) {
            float mx0 = -1e30f, mx1 = -1e30f;
#pragma unroll
            for (int ni = 0; ni < 4; ni++) {
                mx0 = fmaxf(mx0, fmaxf(c[mi][ni][0], c[mi][ni][1]));
                mx1 = fmaxf(mx1, fmaxf(c[mi][ni][2], c[mi][ni][3]));
            }
            mx0 = fmaxf(mx0, __shfl_xor_sync(0xffffffffu, mx0, 1));
            mx0 = fmaxf(mx0, __shfl_xor_sync(0xffffffffu, mx0, 2));
            mx1 = fmaxf(mx1, __shfl_xor_sync(0xffffffffu, mx1, 1));
            mx1 = fmaxf(mx1, __shfl_xor_sync(0xffffffffu, mx1, 2));
            if ((lane & 3) == 0) {
                const int r1 = wm * 64 + mi * 16 + (lane >> 2);
                red[r1 * 4 + wn] = mx0;
                red[(r1 + 8) * 4 + wn] = mx1;
            }
        }
        __syncthreads();

        float nm[4][2], alpha[4][2];
#pragma unroll
        for (int mi = 0; mi < 4; mi++) {
            const int r1 = wm * 64 + mi * 16 + (lane >> 2);
            float mx0 = fmaxf(fmaxf(red[r1 * 4 + 0], red[r1 * 4 + 1]),
                              fmaxf(red[r1 * 4 + 2], red[r1 * 4 + 3]));
            float mx1 = fmaxf(fmaxf(red[(r1 + 8) * 4 + 0], red[(r1 + 8) * 4 + 1]),
                              fmaxf(red[(r1 + 8) * 4 + 2], red[(r1 + 8) * 4 + 3]));
            nm[mi][0] = fmaxf(mrow[mi][0], mx0);
            nm[mi][1] = fmaxf(mrow[mi][1], mx1);
            alpha[mi][0] = __expf(mrow[mi][0] - nm[mi][0]);
            alpha[mi][1] = __expf(mrow[mi][1] - nm[mi][1]);
            mrow[mi][0] = nm[mi][0];
            mrow[mi][1] = nm[mi][1];
        }
        __syncthreads();   // red: max reads done before sum writes

        // ---- exp + row sum ----
#pragma unroll
        for (int mi = 0; mi < 4; mi++) {
            float s0 = 0.0f, s1 = 0.0f;
#pragma unroll
            for (int ni = 0; ni < 4; ni++) {
                c[mi][ni][0] = __expf(c[mi][ni][0] - nm[mi][0]);
                c[mi][ni][1] = __expf(c[mi][ni][1] - nm[mi][0]);
                c[mi][ni][2] = __expf(c[mi][ni][2] - nm[mi][1]);
                c[mi][ni][3] = __expf(c[mi][ni][3] - nm[mi][1]);
                s0 += c[mi][ni][0] + c[mi][ni][1];
                s1 += c[mi][ni][2] + c[mi][ni][3];
            }
            s0 += __shfl_xor_sync(0xffffffffu, s0, 1);
            s0 += __shfl_xor_sync(0xffffffffu, s0, 2);
            s1 += __shfl_xor_sync(0xffffffffu, s1, 1);
            s1 += __shfl_xor_sync(0xffffffffu, s1, 2);
            if ((lane & 3) == 0) {
                const int r1 = wm * 64 + mi * 16 + (lane >> 2);
                red[r1 * 4 + wn] = s0;
                red[(r1 + 8) * 4 + wn] = s1;
            }
        }
        __syncthreads();

#pragma unroll
        for (int mi = 0; mi < 4; mi++) {
            const int r1 = wm * 64 + mi * 16 + (lane >> 2);
            float s0 = red[r1 * 4 + 0] + red[r1 * 4 + 1] + red[r1 * 4 + 2] + red[r1 * 4 + 3];
            float s1 = red[(r1 + 8) * 4 + 0] + red[(r1 + 8) * 4 + 1]
                     + red[(r1 + 8) * 4 + 2] + red[(r1 + 8) * 4 + 3];
            lrow[mi][0] = lrow[mi][0] * alpha[mi][0] + s0;
            lrow[mi][1] = lrow[mi][1] * alpha[mi][1] + s1;
        }

        // ---- P -> smem (bf16 hi/lo) + O rescale ----
#pragma unroll
        for (int mi = 0; mi < 4; mi++) {
            const int r1 = wm * 64 + mi * 16 + (lane >> 2);
#pragma unroll
            for (int ni = 0; ni < 4; ni++) {
                const int col = wn * 32 + ni * 8 + (lane & 3) * 2;
                *(uint32_t*)(smem + OFF_PHI + r1 * PST + col * 2)       = pack_hi(c[mi][ni][0], c[mi][ni][1]);
                *(uint32_t*)(smem + OFF_PLO + r1 * PST + col * 2)       = pack_lo(c[mi][ni][0], c[mi][ni][1]);
                *(uint32_t*)(smem + OFF_PHI + (r1 + 8) * PST + col * 2) = pack_hi(c[mi][ni][2], c[mi][ni][3]);
                *(uint32_t*)(smem + OFF_PLO + (r1 + 8) * PST + col * 2) = pack_lo(c[mi][ni][2], c[mi][ni][3]);
            }
#pragma unroll
            for (int nj = 0; nj < 2; nj++) {
                o[mi][nj][0] *= alpha[mi][0]; o[mi][nj][1] *= alpha[mi][0];
                o[mi][nj][2] *= alpha[mi][1]; o[mi][nj][3] *= alpha[mi][1];
            }
        }
        __syncthreads();   // P visible; K buffers free

        // prefetch next K while PV computes
        if (kt + 1 < KVTILES) {
            ldtile(OFF_KHI, Kh + (size_t)(kt + 1) * 128 * DK);
            ldtile(OFF_KLO, Kl + (size_t)(kt + 1) * 128 * DK);
            CP_ASYNC_COMMIT();
        }

        // ---- O += P V ----
#pragma unroll
        for (int kk = 0; kk < 8; kk++) {
            uint32_t ph[4][4], pl[4][4];
#pragma unroll
            for (int mi = 0; mi < 4; mi++) {
                uint32_t ro = (uint32_t)((wm * 64 + mi * 16 + (lane & 15)) * PST
                                         + (kk * 16 + (lane >> 4) * 8) * 2);
                ldsm4(ph[mi], sb + OFF_PHI + ro);
                ldsm4(pl[mi], sb + OFF_PLO + ro);
            }
            uint32_t vh[4], vl[4];
            uint32_t ro = (uint32_t)((kk * 16 + (lane & 15)) * AST
                                     + (wn * 16 + (lane >> 4) * 8) * 2);
            ldsm4t(vh, sb + OFF_VHI + ro);
            ldsm4t(vl, sb + OFF_VLO + ro);
#pragma unroll
            for (int mi = 0; mi < 4; mi++)
#pragma unroll
                for (int nj = 0; nj < 2; nj++) {
                    mma16816(o[mi][nj], ph[mi], vh[nj * 2], vh[nj * 2 + 1]);
                    mma16816(o[mi][nj], ph[mi], vl[nj * 2], vl[nj * 2 + 1]);
                    mma16816(o[mi][nj], pl[mi], vh[nj * 2], vh[nj * 2 + 1]);
                }
        }
        __syncthreads();   // V consumed

        if (kt + 1 < KVTILES) {
            ldtile(OFF_VHI, Vh + (size_t)(kt + 1) * 128 * DK);
            ldtile(OFF_VLO, Vl + (size_t)(kt + 1) * 128 * DK);
            CP_ASYNC_COMMIT();
            CP_ASYNC_WAIT_ALL();
            __syncthreads();
        }
    }

    // ---- epilogue: normalize, emit bf16 hi/lo ctx in [B,S,1024] ----
    const int b = bh >> 4, h = bh & 15;
#pragma unroll
    for (int mi = 0; mi < 4; mi++) {
        const int r1 = wm * 64 + mi * 16 + (lane >> 2);
        const float inv0 = 1.0f / lrow[mi][0];
        const float inv1 = 1.0f / lrow[mi][1];
#pragma unroll
        for (int nj = 0; nj < 2; nj++) {
            const int colg = h * DK + wn * 16 + nj * 8 + (lane & 3) * 2;
            const float v00 = o[mi][nj][0] * inv0, v01 = o[mi][nj][1] * inv0;
            const float v10 = o[mi][nj][2] * inv1, v11 = o[mi][nj][3] * inv1;
            const size_t row0 = (size_t)(b * SEQ + qt * 128 + r1);
            *(uint32_t*)(g_ahi + row0 * D_MODEL + colg) = pack_hi(v00, v01);
            *(uint32_t*)(g_alo + row0 * D_MODEL + colg) = pack_lo(v00, v01);
            *(uint32_t*)(g_ahi + (row0 + 8) * D_MODEL + colg) = pack_hi(v10, v11);
            *(uint32_t*)(g_alo + (row0 + 8) * D_MODEL + colg) = pack_lo(v10, v11);
        }
    }
}

// ============================================================================
// launch
// ============================================================================
extern "C" void kernel_launch(void* const* d_in, const int* in_sizes, int n_in,
                              void* d_out, int out_size)
{
    const float* query  = (const float*)d_in[0];
    const float* key_in = (const float*)d_in[1];
    const float* value  = (const float*)d_in[2];
    const float* Wq = (const float*)d_in[3];
    const float* bq = (const float*)d_in[4];
    const float* Wk = (const float*)d_in[5];
    const float* bk = (const float*)d_in[6];
    const float* Wv = (const float*)d_in[7];
    const float* bv = (const float*)d_in[8];
    const float* Wo = (const float*)d_in[9];
    const float* bo = (const float*)d_in[10];
    float* out = (float*)d_out;

    __nv_bfloat16 *qhi, *qlo, *khi, *klo, *vhi, *vlo, *ahi, *alo, *whi, *wlo;
    cudaGetSymbolAddress((void**)&qhi, g_Qhi);
    cudaGetSymbolAddress((void**)&qlo, g_Qlo);
    cudaGetSymbolAddress((void**)&khi, g_Khi);
    cudaGetSymbolAddress((void**)&klo, g_Klo);
    cudaGetSymbolAddress((void**)&vhi, g_Vhi);
    cudaGetSymbolAddress((void**)&vlo, g_Vlo);
    cudaGetSymbolAddress((void**)&ahi, g_ahi);
    cudaGetSymbolAddress((void**)&alo, g_alo);
    cudaGetSymbolAddress((void**)&whi, g_whi);
    cudaGetSymbolAddress((void**)&wlo, g_wlo);

    cudaFuncSetAttribute(gemm_tc, cudaFuncAttributeMaxDynamicSharedMemorySize, GEMM_SMEM);
    cudaFuncSetAttribute(attn_tc, cudaFuncAttributeMaxDynamicSharedMemorySize, ATTN_SMEM);

    const int ACT4 = MROWS * D_MODEL / 4;
    const int W4   = D_MODEL * D_MODEL / 4;
    dim3 cgrdA((ACT4 + 255) / 256), cgrdW((W4 + 255) / 256), cblk(256);
    dim3 ggrd(D_MODEL / 128, MROWS / 128), gblk(256);

    // Q projection
    conv_hilo<<<cgrdW, cblk>>>(Wq, whi, wlo, W4);
    conv_hilo<<<cgrdA, cblk>>>(query, ahi, alo, ACT4);
    gemm_tc<<<ggrd, gblk, GEMM_SMEM>>>(ahi, alo, whi, wlo, bq, nullptr, qhi, qlo, 1);
    // K projection
    conv_hilo<<<cgrdW, cblk>>>(Wk, whi, wlo, W4);
    conv_hilo<<<cgrdA, cblk>>>(key_in, ahi, alo, ACT4);
    gemm_tc<<<ggrd, gblk, GEMM_SMEM>>>(ahi, alo, whi, wlo, bk, nullptr, khi, klo, 1);
    // V projection
    conv_hilo<<<cgrdW, cblk>>>(Wv, whi, wlo, W4);
    conv_hilo<<<cgrdA, cblk>>>(value, ahi, alo, ACT4);
    gemm_tc<<<ggrd, gblk, GEMM_SMEM>>>(ahi, alo, whi, wlo, bv, nullptr, vhi, vlo, 1);

    // attention (writes ctx hi/lo directly into g_ahi/g_alo)
    attn_tc<<<dim3(KVTILES, BATCH * NUM_HEADS), dim3(256), ATTN_SMEM>>>();

    // output projection
    conv_hilo<<<cgrdW, cblk>>>(Wo, whi, wlo, W4);
    gemm_tc<<<ggrd, gblk, GEMM_SMEM>>>(ahi, alo, whi, wlo, bo, out, nullptr, nullptr, 0);
}

// round 4
// speedup vs baseline: 2.4955x; 1.0260x over previous
#include <cuda_runtime.h>
#include <cuda_bf16.h>
#include <cstdint>

#define D_MODEL 1024
#define NUM_HEADS 16
#define DK 64
#define BATCH 4
#define SEQ 2048
#define MROWS (BATCH * SEQ)   /* 8192 */
#define KVTILES (SEQ / 128)   /* 16 */

// ---------------- scratch (bf16 hi/lo everywhere) ----------------
__device__ __nv_bfloat16 g_Qhi[BATCH * NUM_HEADS * SEQ * DK];
__device__ __nv_bfloat16 g_Qlo[BATCH * NUM_HEADS * SEQ * DK];
__device__ __nv_bfloat16 g_Khi[BATCH * NUM_HEADS * SEQ * DK];
__device__ __nv_bfloat16 g_Klo[BATCH * NUM_HEADS * SEQ * DK];
__device__ __nv_bfloat16 g_Vhi[BATCH * NUM_HEADS * SEQ * DK];
__device__ __nv_bfloat16 g_Vlo[BATCH * NUM_HEADS * SEQ * DK];
__device__ __nv_bfloat16 g_ahi[3 * MROWS * D_MODEL];
__device__ __nv_bfloat16 g_alo[3 * MROWS * D_MODEL];
__device__ __nv_bfloat16 g_whi[4 * D_MODEL * D_MODEL];
__device__ __nv_bfloat16 g_wlo[4 * D_MODEL * D_MODEL];

// ---------------- helpers ----------------
__device__ __forceinline__ uint32_t smem_u32(const void* p) {
    uint32_t a;
    asm("{ .reg .u64 t; cvta.to.shared.u64 t, %1; cvt.u32.u64 %0, t; }" : "=r"(a) : "l"(p));
    return a;
}
#define CP_ASYNC16(saddr, gptr) \
    asm volatile("cp.async.cg.shared.global [%0], [%1], 16;" :: "r"((uint32_t)(saddr)), "l"(gptr))
#define CP_ASYNC_COMMIT()    asm volatile("cp.async.commit_group;" ::: "memory")
#define CP_ASYNC_WAIT_ALL()  asm volatile("cp.async.wait_group 0;" ::: "memory")
#define CP_ASYNC_WAIT_1()    asm volatile("cp.async.wait_group 1;" ::: "memory")

__device__ __forceinline__ void ldsm4(uint32_t r[4], uint32_t a) {
    asm volatile("ldmatrix.sync.aligned.m8n8.x4.shared.b16 {%0,%1,%2,%3}, [%4];"
        : "=r"(r[0]), "=r"(r[1]), "=r"(r[2]), "=r"(r[3]) : "r"(a));
}
__device__ __forceinline__ void ldsm4t(uint32_t r[4], uint32_t a) {
    asm volatile("ldmatrix.sync.aligned.m8n8.x4.trans.shared.b16 {%0,%1,%2,%3}, [%4];"
        : "=r"(r[0]), "=r"(r[1]), "=r"(r[2]), "=r"(r[3]) : "r"(a));
}
__device__ __forceinline__ void mma16816(float c[4], const uint32_t a[4], uint32_t b0, uint32_t b1) {
    asm volatile("mma.sync.aligned.m16n8k16.row.col.f32.bf16.bf16.f32 "
        "{%0,%1,%2,%3}, {%4,%5,%6,%7}, {%8,%9}, {%0,%1,%2,%3};"
        : "+f"(c[0]), "+f"(c[1]), "+f"(c[2]), "+f"(c[3])
        : "r"(a[0]), "r"(a[1]), "r"(a[2]), "r"(a[3]), "r"(b0), "r"(b1));
}
__device__ __forceinline__ uint32_t pack_hi(float x, float y) {
    __nv_bfloat162 h = __floats2bfloat162_rn(x, y);
    return *(uint32_t*)&h;
}
__device__ __forceinline__ uint32_t pack_lo(float x, float y) {
    float xr = x - __bfloat162float(__float2bfloat16(x));
    float yr = y - __bfloat162float(__float2bfloat16(y));
    __nv_bfloat162 h = __floats2bfloat162_rn(xr, yr);
    return *(uint32_t*)&h;
}

// ============================================================================
// Batched fp32 -> (bf16 hi, bf16 lo). blockIdx.y selects which input tensor.
// ============================================================================
__global__ __launch_bounds__(256) void conv_hilo4(
    const float* __restrict__ x0, const float* __restrict__ x1,
    const float* __restrict__ x2, const float* __restrict__ x3,
    __nv_bfloat16* __restrict__ hi, __nv_bfloat16* __restrict__ lo, int n4)
{
    int i = blockIdx.x * blockDim.x + threadIdx.x;
    if (i >= n4) return;
    const float* x = (blockIdx.y == 0) ? x0 : (blockIdx.y == 1) ? x1
                   : (blockIdx.y == 2) ? x2 : x3;
    size_t o = (size_t)blockIdx.y * n4 + i;
    float4 v = ((const float4*)x)[i];
    uint2 H, L;
    H.x = pack_hi(v.x, v.y); H.y = pack_hi(v.z, v.w);
    L.x = pack_lo(v.x, v.y); L.y = pack_lo(v.z, v.w);
    ((uint2*)hi)[o] = H;
    ((uint2*)lo)[o] = L;
}

// ============================================================================
// HMMA GEMM: C[M,N] = (Ahi+Alo) @ (Whi+Wlo)^T + bias, then *oscale  (3-term)
// BM=128 BN=128 BK=32, 8 warps (2x4), double-buffered cp.async.
// split==0: fp32 row-major out. split==1: bf16 hi/lo out in [B,H,S,DK].
// ============================================================================
#define BK 32
#define GPAD 40
#define MAT_B (128 * GPAD * 2)
#define STG_B (4 * MAT_B)
#define NIT (D_MODEL / BK)
#define GEMM_SMEM (2 * STG_B)

__global__ __launch_bounds__(256) void gemm_tc(
    const __nv_bfloat16* __restrict__ Ahi, const __nv_bfloat16* __restrict__ Alo,
    const __nv_bfloat16* __restrict__ Whi, const __nv_bfloat16* __restrict__ Wlo,
    const float* __restrict__ bias,
    float* __restrict__ Cf,
    __nv_bfloat16* __restrict__ Chi, __nv_bfloat16* __restrict__ Clo,
    int split, float oscale)
{
    extern __shared__ char smem[];
    const uint32_t sb = smem_u32(smem);
    const int t = threadIdx.x;
    const int lane = t & 31, wid = t >> 5;
    const int wm = wid >> 2, wn = wid & 3;
    const int m0 = blockIdx.y * 128, n0 = blockIdx.x * 128;

    float c[4][4][4];
#pragma unroll
    for (int i = 0; i < 4; i++)
#pragma unroll
        for (int j = 0; j < 4; j++)
#pragma unroll
            for (int k = 0; k < 4; k++) c[i][j][k] = 0.0f;

    auto load_stage = [&](int s, int it) {
        const int k0 = it * BK;
        const uint32_t st = sb + s * STG_B;
#pragma unroll
        for (int j = 0; j < 2; j++) {
            int idx = t + j * 256;
            int r = idx >> 2, cc = idx & 3;
            uint32_t so = (uint32_t)(r * (GPAD * 2) + cc * 16);
            const __nv_bfloat16* ga = Ahi + (size_t)(m0 + r) * D_MODEL + k0 + cc * 8;
            const __nv_bfloat16* gl = Alo + (size_t)(m0 + r) * D_MODEL + k0 + cc * 8;
            const __nv_bfloat16* gw = Whi + (size_t)(n0 + r) * D_MODEL + k0 + cc * 8;
            const __nv_bfloat16* gv = Wlo + (size_t)(n0 + r) * D_MODEL + k0 + cc * 8;
            CP_ASYNC16(st + 0 * MAT_B + so, ga);
            CP_ASYNC16(st + 1 * MAT_B + so, gl);
            CP_ASYNC16(st + 2 * MAT_B + so, gw);
            CP_ASYNC16(st + 3 * MAT_B + so, gv);
        }
    };

    load_stage(0, 0);
    CP_ASYNC_COMMIT();

    for (int it = 0; it < NIT; ++it) {
        const int s = it & 1;
        if (it + 1 < NIT) {
            load_stage(s ^ 1, it + 1);
            CP_ASYNC_COMMIT();
            CP_ASYNC_WAIT_1();
        } else {
            CP_ASYNC_WAIT_ALL();
        }
        __syncthreads();

        const uint32_t st = sb + s * STG_B;
#pragma unroll
        for (int kk = 0; kk < 2; kk++) {
            uint32_t ah[4][4], al[4][4];
#pragma unroll
            for (int mi = 0; mi < 4; mi++) {
                uint32_t ro = (uint32_t)((wm * 64 + mi * 16 + (lane & 15)) * (GPAD * 2)
                                         + (kk * 16 + (lane >> 4) * 8) * 2);
                ldsm4(ah[mi], st + 0 * MAT_B + ro);
                ldsm4(al[mi], st + 1 * MAT_B + ro);
            }
            uint32_t bh_[2][4], bl_[2][4];
#pragma unroll
            for (int nj = 0; nj < 2; nj++) {
                uint32_t ro = (uint32_t)((wn * 32 + nj * 16 + (lane & 7) + ((lane >> 4) * 8)) * (GPAD * 2)
                                         + (kk * 16 + ((lane >> 3) & 1) * 8) * 2);
                ldsm4(bh_[nj], st + 2 * MAT_B + ro);
                ldsm4(bl_[nj], st + 3 * MAT_B + ro);
            }
#pragma unroll
            for (int mi = 0; mi < 4; mi++)
#pragma unroll
                for (int ni = 0; ni < 4; ni++) {
                    const int nj = ni >> 1, ss = (ni & 1) * 2;
                    mma16816(c[mi][ni], ah[mi], bh_[nj][ss], bh_[nj][ss + 1]);
                    mma16816(c[mi][ni], ah[mi], bl_[nj][ss], bl_[nj][ss + 1]);
                    mma16816(c[mi][ni], al[mi], bh_[nj][ss], bh_[nj][ss + 1]);
                }
        }
        __syncthreads();
    }

    // ---- epilogue ----
#pragma unroll
    for (int mi = 0; mi < 4; mi++) {
        const int r0 = m0 + wm * 64 + mi * 16 + (lane >> 2);
#pragma unroll
        for (int ni = 0; ni < 4; ni++) {
            const int col = n0 + wn * 32 + ni * 8 + (lane & 3) * 2;
            const float b0 = bias[col], b1 = bias[col + 1];
            float v00 = (c[mi][ni][0] + b0) * oscale, v01 = (c[mi][ni][1] + b1) * oscale;
            float v10 = (c[mi][ni][2] + b0) * oscale, v11 = (c[mi][ni][3] + b1) * oscale;
            if (!split) {
                float2* d0 = (float2*)(Cf + (size_t)r0 * D_MODEL + col);
                float2* d1 = (float2*)(Cf + (size_t)(r0 + 8) * D_MODEL + col);
                *d0 = make_float2(v00, v01);
                *d1 = make_float2(v10, v11);
            } else {
                const int h = col >> 6, d = col & 63;
#pragma unroll
                for (int rr = 0; rr < 2; rr++) {
                    const int m = r0 + rr * 8;
                    const int b = m >> 11, sdx = m & 2047;
                    const size_t off = (((size_t)(b * NUM_HEADS + h) * SEQ + sdx) * DK + d);
                    const float x = rr ? v10 : v00, y = rr ? v11 : v01;
                    *(uint32_t*)(Chi + off) = pack_hi(x, y);
                    *(uint32_t*)(Clo + off) = pack_lo(x, y);
                }
            }
        }
    }
}

// ============================================================================
// HMMA flash attention, 512 threads (16 warps, 4x4). Scale pre-folded into Q.
// V double-buffered; K prefetched in PV shadow. Output -> g_ahi/g_alo slot 0.
// ============================================================================
#define AST 144                      /* Q/K/V row stride bytes (72 bf16) */
#define PST 272                      /* P row stride bytes (136 bf16) */
#define OFF_QHI 0
#define OFF_QLO (OFF_QHI + 128 * AST)
#define OFF_KHI (OFF_QLO + 128 * AST)
#define OFF_KLO (OFF_KHI + 128 * AST)
#define OFF_V0H (OFF_KLO + 128 * AST)
#define OFF_V0L (OFF_V0H + 128 * AST)
#define OFF_V1H (OFF_V0L + 128 * AST)
#define OFF_V1L (OFF_V1H + 128 * AST)
#define OFF_PHI (OFF_V1L + 128 * AST)
#define OFF_PLO (OFF_PHI + 128 * PST)
#define OFF_RED (OFF_PLO + 128 * PST)
#define ATTN_SMEM (OFF_RED + 128 * 4 * 4)   /* 219136 B */
#define OFF_VH(vb) (OFF_V0H + (vb) * (2 * 128 * AST))
#define OFF_VL(vb) (OFF_VH(vb) + 128 * AST)

__global__ __launch_bounds__(512) void attn_tc()
{
    extern __shared__ char smem[];
    const uint32_t sb = smem_u32(smem);
    float* red = (float*)(smem + OFF_RED);
    const int t = threadIdx.x;
    const int lane = t & 31, wid = t >> 5;
    const int wm = wid >> 2, wn = wid & 3;     // both 0..3
    const int qt = blockIdx.x, bh = blockIdx.y;

    const __nv_bfloat16* Qh = g_Qhi + ((size_t)bh * SEQ + qt * 128) * DK;
    const __nv_bfloat16* Ql = g_Qlo + ((size_t)bh * SEQ + qt * 128) * DK;
    const __nv_bfloat16* Kh = g_Khi + (size_t)bh * SEQ * DK;
    const __nv_bfloat16* Kl = g_Klo + (size_t)bh * SEQ * DK;
    const __nv_bfloat16* Vh = g_Vhi + (size_t)bh * SEQ * DK;
    const __nv_bfloat16* Vl = g_Vlo + (size_t)bh * SEQ * DK;

    auto ldtile = [&](uint32_t dstoff, const __nv_bfloat16* src) {   // 128x64 bf16
#pragma unroll
        for (int j = 0; j < 2; j++) {
            int idx = t + j * 512;
            int r = idx >> 3, cc = idx & 7;
            CP_ASYNC16(sb + dstoff + r * AST + cc * 16, src + r * DK + cc * 8);
        }
    };

    ldtile(OFF_QHI, Qh); ldtile(OFF_QLO, Ql);
    ldtile(OFF_KHI, Kh); ldtile(OFF_KLO, Kl);
    ldtile(OFF_V0H, Vh); ldtile(OFF_V0L, Vl);
    CP_ASYNC_COMMIT();
    CP_ASYNC_WAIT_ALL();
    __syncthreads();

    float o[2][2][4];
    float mrow[2][2], lrow[2][2];
#pragma unroll
    for (int mi = 0; mi < 2; mi++) {
        mrow[mi][0] = mrow[mi][1] = -1e30f;
        lrow[mi][0] = lrow[mi][1] = 0.0f;
#pragma unroll
        for (int nj = 0; nj < 2; nj++)
#pragma unroll
            for (int k = 0; k < 4; k++) o[mi][nj][k] = 0.0f;
    }

    for (int kt = 0; kt < KVTILES; kt++) {
        const int vb = kt & 1;

        // prefetch next V (lands by end of this iteration)
        if (kt + 1 < KVTILES) {
            ldtile(OFF_VH(vb ^ 1), Vh + (size_t)(kt + 1) * 128 * DK);
            ldtile(OFF_VL(vb ^ 1), Vl + (size_t)(kt + 1) * 128 * DK);
            CP_ASYNC_COMMIT();
        }

        // ---- S = Q K^T (scale pre-folded into Q) ----
        float c[2][4][4];
#pragma unroll
        for (int i = 0; i < 2; i++)
#pragma unroll
            for (int j = 0; j < 4; j++)
#pragma unroll
                for (int k = 0; k < 4; k++) c[i][j][k] = 0.0f;

#pragma unroll
        for (int kk = 0; kk < 4; kk++) {
            uint32_t ah[2][4], al[2][4];
#pragma unroll
            for (int mi = 0; mi < 2; mi++) {
                uint32_t ro = (uint32_t)((wm * 32 + mi * 16 + (lane & 15)) * AST
                                         + (kk * 16 + (lane >> 4) * 8) * 2);
                ldsm4(ah[mi], sb + OFF_QHI + ro);
                ldsm4(al[mi], sb + OFF_QLO + ro);
            }
            uint32_t bh_[2][4], bl_[2][4];
#pragma unroll
            for (int nj = 0; nj < 2; nj++) {
                uint32_t ro = (uint32_t)((wn * 32 + nj * 16 + (lane & 7) + ((lane >> 4) * 8)) * AST
                                         + (kk * 16 + ((lane >> 3) & 1) * 8) * 2);
                ldsm4(bh_[nj], sb + OFF_KHI + ro);
                ldsm4(bl_[nj], sb + OFF_KLO + ro);
            }
#pragma unroll
            for (int mi = 0; mi < 2; mi++)
#pragma unroll
                for (int ni = 0; ni < 4; ni++) {
                    const int nj = ni >> 1, ss = (ni & 1) * 2;
                    mma16816(c[mi][ni], ah[mi], bh_[nj][ss], bh_[nj][ss + 1]);
                    mma16816(c[mi][ni], ah[mi], bl_[nj][ss], bl_[nj][ss + 1]);
                    mma16816(c[mi][ni], al[mi], bh_[nj][ss], bh_[nj][ss + 1]);
                }
        }

        // ---- row max ----
#pragma unroll
        for (int mi = 0; mi < 2; mi++) {
            float mx0 = -1e30f, mx1 = -1e30f;
#pragma unroll
            for (int ni = 0; ni < 4; ni++) {
                mx0 = fmaxf(mx0, fmaxf(c[mi][ni][0], c[mi][ni][1]));
                mx1 = fmaxf(mx1, fmaxf(c[mi][ni][2], c[mi][ni][3]));
            }
            mx0 = fmaxf(mx0, __shfl_xor_sync(0xffffffffu, mx0, 1));
            mx0 = fmaxf(mx0, __shfl_xor_sync(0xffffffffu, mx0, 2));
            mx1 = fmaxf(mx1, __shfl_xor_sync(0xffffffffu, mx1, 1));
            mx1 = fmaxf(mx1, __shfl_xor_sync(0xffffffffu, mx1, 2));
            if ((lane & 3) == 0) {
                const int r1 = wm * 32 + mi * 16 + (lane >> 2);
                red[r1 * 4 + wn] = mx0;
                red[(r1 + 8) * 4 + wn] = mx1;
            }
        }
        __syncthreads();

        float nm[2][2], alpha[2][2];
#pragma unroll
        for (int mi = 0; mi < 2; mi++) {
            const int r1 = wm * 32 + mi * 16 + (lane >> 2);
            float mx0 = fmaxf(fmaxf(red[r1 * 4 + 0], red[r1 * 4 + 1]),
                              fmaxf(red[r1 * 4 + 2], red[r1 * 4 + 3]));
            float mx1 = fmaxf(fmaxf(red[(r1 + 8) * 4 + 0], red[(r1 + 8) * 4 + 1]),
                              fmaxf(red[(r1 + 8) * 4 + 2], red[(r1 + 8) * 4 + 3]));
            nm[mi][0] = fmaxf(mrow[mi][0], mx0);
            nm[mi][1] = fmaxf(mrow[mi][1], mx1);
            alpha[mi][0] = __expf(mrow[mi][0] - nm[mi][0]);
            alpha[mi][1] = __expf(mrow[mi][1] - nm[mi][1]);
            mrow[mi][0] = nm[mi][0];
            mrow[mi][1] = nm[mi][1];
        }
        __syncthreads();   // max reads done before sum writes

        // ---- exp + row sum ----
#pragma unroll
        for (int mi = 0; mi < 2; mi++) {
            float s0 = 0.0f, s1 = 0.0f;
#pragma unroll
            for (int ni = 0; ni < 4; ni++) {
                c[mi][ni][0] = __expf(c[mi][ni][0] - nm[mi][0]);
                c[mi][ni][1] = __expf(c[mi][ni][1] - nm[mi][0]);
                c[mi][ni][2] = __expf(c[mi][ni][2] - nm[mi][1]);
                c[mi][ni][3] = __expf(c[mi][ni][3] - nm[mi][1]);
                s0 += c[mi][ni][0] + c[mi][ni][1];
                s1 += c[mi][ni][2] + c[mi][ni][3];
            }
            s0 += __shfl_xor_sync(0xffffffffu, s0, 1);
            s0 += __shfl_xor_sync(0xffffffffu, s0, 2);
            s1 += __shfl_xor_sync(0xffffffffu, s1, 1);
            s1 += __shfl_xor_sync(0xffffffffu, s1, 2);
            if ((lane & 3) == 0) {
                const int r1 = wm * 32 + mi * 16 + (lane >> 2);
                red[r1 * 4 + wn] = s0;
                red[(r1 + 8) * 4 + wn] = s1;
            }
        }
        __syncthreads();

#pragma unroll
        for (int mi = 0; mi < 2; mi++) {
            const int r1 = wm * 32 + mi * 16 + (lane >> 2);
            float s0 = red[r1 * 4 + 0] + red[r1 * 4 + 1] + red[r1 * 4 + 2] + red[r1 * 4 + 3];
            float s1 = red[(r1 + 8) * 4 + 0] + red[(r1 + 8) * 4 + 1]
                     + red[(r1 + 8) * 4 + 2] + red[(r1 + 8) * 4 + 3];
            lrow[mi][0] = lrow[mi][0] * alpha[mi][0] + s0;
            lrow[mi][1] = lrow[mi][1] * alpha[mi][1] + s1;
        }

        // ---- P -> smem (bf16 hi/lo) + O rescale ----
#pragma unroll
        for (int mi = 0; mi < 2; mi++) {
            const int r1 = wm * 32 + mi * 16 + (lane >> 2);
#pragma unroll
            for (int ni = 0; ni < 4; ni++) {
                const int col = wn * 32 + ni * 8 + (lane & 3) * 2;
                *(uint32_t*)(smem + OFF_PHI + r1 * PST + col * 2)       = pack_hi(c[mi][ni][0], c[mi][ni][1]);
                *(uint32_t*)(smem + OFF_PLO + r1 * PST + col * 2)       = pack_lo(c[mi][ni][0], c[mi][ni][1]);
                *(uint32_t*)(smem + OFF_PHI + (r1 + 8) * PST + col * 2) = pack_hi(c[mi][ni][2], c[mi][ni][3]);
                *(uint32_t*)(smem + OFF_PLO + (r1 + 8) * PST + col * 2) = pack_lo(c[mi][ni][2], c[mi][ni][3]);
            }
#pragma unroll
            for (int nj = 0; nj < 2; nj++) {
                o[mi][nj][0] *= alpha[mi][0]; o[mi][nj][1] *= alpha[mi][0];
                o[mi][nj][2] *= alpha[mi][1]; o[mi][nj][3] *= alpha[mi][1];
            }
        }
        __syncthreads();   // P visible; K fully consumed

        // prefetch next K in PV shadow
        if (kt + 1 < KVTILES) {
            ldtile(OFF_KHI, Kh + (size_t)(kt + 1) * 128 * DK);
            ldtile(OFF_KLO, Kl + (size_t)(kt + 1) * 128 * DK);
            CP_ASYNC_COMMIT();
        }

        // ---- O += P V ----
#pragma unroll
        for (int kk = 0; kk < 8; kk++) {
            uint32_t ph[2][4], pl[2][4];
#pragma unroll
            for (int mi = 0; mi < 2; mi++) {
                uint32_t ro = (uint32_t)((wm * 32 + mi * 16 + (lane & 15)) * PST
                                         + (kk * 16 + (lane >> 4) * 8) * 2);
                ldsm4(ph[mi], sb + OFF_PHI + ro);
                ldsm4(pl[mi], sb + OFF_PLO + ro);
            }
            uint32_t vh[4], vl[4];
            uint32_t ro = (uint32_t)((kk * 16 + (lane & 15)) * AST
                                     + (wn * 16 + (lane >> 4) * 8) * 2);
            ldsm4t(vh, sb + OFF_VH(vb) + ro);
            ldsm4t(vl, sb + OFF_VL(vb) + ro);
#pragma unroll
            for (int mi = 0; mi < 2; mi++)
#pragma unroll
                for (int nj = 0; nj < 2; nj++) {
                    mma16816(o[mi][nj], ph[mi], vh[nj * 2], vh[nj * 2 + 1]);
                    mma16816(o[mi][nj], ph[mi], vl[nj * 2], vl[nj * 2 + 1]);
                    mma16816(o[mi][nj], pl[mi], vh[nj * 2], vh[nj * 2 + 1]);
                }
        }

        if (kt + 1 < KVTILES) {
            CP_ASYNC_WAIT_ALL();   // K(kt+1) + V(kt+1) landed
        }
        __syncthreads();
    }

    // ---- epilogue: normalize, emit bf16 hi/lo ctx in [B,S,1024] (slot 0) ----
    const int b = bh >> 4, h = bh & 15;
#pragma unroll
    for (int mi = 0; mi < 2; mi++) {
        const int r1 = wm * 32 + mi * 16 + (lane >> 2);
        const float inv0 = 1.0f / lrow[mi][0];
        const float inv1 = 1.0f / lrow[mi][1];
#pragma unroll
        for (int nj = 0; nj < 2; nj++) {
            const int colg = h * DK + wn * 16 + nj * 8 + (lane & 3) * 2;
            const float v00 = o[mi][nj][0] * inv0, v01 = o[mi][nj][1] * inv0;
            const float v10 = o[mi][nj][2] * inv1, v11 = o[mi][nj][3] * inv1;
            const size_t row0 = (size_t)(b * SEQ + qt * 128 + r1);
            *(uint32_t*)(g_ahi + row0 * D_MODEL + colg) = pack_hi(v00, v01);
            *(uint32_t*)(g_alo + row0 * D_MODEL + colg) = pack_lo(v00, v01);
            *(uint32_t*)(g_ahi + (row0 + 8) * D_MODEL + colg) = pack_hi(v10, v11);
            *(uint32_t*)(g_alo + (row0 + 8) * D_MODEL + colg) = pack_lo(v10, v11);
        }
    }
}

// ============================================================================
// launch
// ============================================================================
extern "C" void kernel_launch(void* const* d_in, const int* in_sizes, int n_in,
                              void* d_out, int out_size)
{
    const float* query  = (const float*)d_in[0];
    const float* key_in = (const float*)d_in[1];
    const float* value  = (const float*)d_in[2];
    const float* Wq = (const float*)d_in[3];
    const float* bq = (const float*)d_in[4];
    const float* Wk = (const float*)d_in[5];
    const float* bk = (const float*)d_in[6];
    const float* Wv = (const float*)d_in[7];
    const float* bv = (const float*)d_in[8];
    const float* Wo = (const float*)d_in[9];
    const float* bo = (const float*)d_in[10];
    float* out = (float*)d_out;

    __nv_bfloat16 *qhi, *qlo, *khi, *klo, *vhi, *vlo, *ahi, *alo, *whi, *wlo;
    cudaGetSymbolAddress((void**)&qhi, g_Qhi);
    cudaGetSymbolAddress((void**)&qlo, g_Qlo);
    cudaGetSymbolAddress((void**)&khi, g_Khi);
    cudaGetSymbolAddress((void**)&klo, g_Klo);
    cudaGetSymbolAddress((void**)&vhi, g_Vhi);
    cudaGetSymbolAddress((void**)&vlo, g_Vlo);
    cudaGetSymbolAddress((void**)&ahi, g_ahi);
    cudaGetSymbolAddress((void**)&alo, g_alo);
    cudaGetSymbolAddress((void**)&whi, g_whi);
    cudaGetSymbolAddress((void**)&wlo, g_wlo);

    cudaFuncSetAttribute(gemm_tc, cudaFuncAttributeMaxDynamicSharedMemorySize, GEMM_SMEM);
    cudaFuncSetAttribute(attn_tc, cudaFuncAttributeMaxDynamicSharedMemorySize, ATTN_SMEM);

    const int ACT4 = MROWS * D_MODEL / 4;
    const int W4   = D_MODEL * D_MODEL / 4;
    const size_t ASL = (size_t)MROWS * D_MODEL;   // activation slot stride
    const size_t WSL = (size_t)D_MODEL * D_MODEL; // weight slot stride

    dim3 ggrd(D_MODEL / 128, MROWS / 128), gblk(256);

    // batched conversions: weights (q,k,v,o) and activations (query,key,value)
    conv_hilo4<<<dim3((W4 + 255) / 256, 4), 256>>>(Wq, Wk, Wv, Wo, whi, wlo, W4);
    conv_hilo4<<<dim3((ACT4 + 255) / 256, 3), 256>>>(query, key_in, value, value, ahi, alo, ACT4);

    const float qscale = 0.125f;   // 1/sqrt(DK), folded into Q
    gemm_tc<<<ggrd, gblk, GEMM_SMEM>>>(ahi + 0 * ASL, alo + 0 * ASL, whi + 0 * WSL, wlo + 0 * WSL,
                                       bq, nullptr, qhi, qlo, 1, qscale);
    gemm_tc<<<ggrd, gblk, GEMM_SMEM>>>(ahi + 1 * ASL, alo + 1 * ASL, whi + 1 * WSL, wlo + 1 * WSL,
                                       bk, nullptr, khi, klo, 1, 1.0f);
    gemm_tc<<<ggrd, gblk, GEMM_SMEM>>>(ahi + 2 * ASL, alo + 2 * ASL, whi + 2 * WSL, wlo + 2 * WSL,
                                       bv, nullptr, vhi, vlo, 1, 1.0f);

    // attention (writes ctx hi/lo into activation slot 0)
    attn_tc<<<dim3(KVTILES, BATCH * NUM_HEADS), dim3(512), ATTN_SMEM>>>();

    // output projection
    gemm_tc<<<ggrd, gblk, GEMM_SMEM>>>(ahi, alo, whi + 3 * WSL, wlo + 3 * WSL,
                                       bo, out, nullptr, nullptr, 0, 1.0f);
}

// round 5
// speedup vs baseline: 2.8647x; 1.1479x over previous
#include <cuda_runtime.h>
#include <cuda_bf16.h>
#include <cstdint>

#define D_MODEL 1024
#define NUM_HEADS 16
#define DK 64
#define BATCH 4
#define SEQ 2048
#define MROWS (BATCH * SEQ)   /* 8192 */
#define KVTILES (SEQ / 128)   /* 16 */

// ---------------- scratch (bf16 hi/lo everywhere) ----------------
__device__ __nv_bfloat16 g_Qhi[BATCH * NUM_HEADS * SEQ * DK];
__device__ __nv_bfloat16 g_Qlo[BATCH * NUM_HEADS * SEQ * DK];
__device__ __nv_bfloat16 g_Khi[BATCH * NUM_HEADS * SEQ * DK];
__device__ __nv_bfloat16 g_Klo[BATCH * NUM_HEADS * SEQ * DK];
__device__ __nv_bfloat16 g_Vhi[BATCH * NUM_HEADS * SEQ * DK];
__device__ __nv_bfloat16 g_Vlo[BATCH * NUM_HEADS * SEQ * DK];
__device__ __nv_bfloat16 g_ahi[3 * MROWS * D_MODEL];
__device__ __nv_bfloat16 g_alo[3 * MROWS * D_MODEL];
__device__ __nv_bfloat16 g_whi[4 * D_MODEL * D_MODEL];
__device__ __nv_bfloat16 g_wlo[4 * D_MODEL * D_MODEL];

// ---------------- helpers ----------------
__device__ __forceinline__ uint32_t smem_u32(const void* p) {
    uint32_t a;
    asm("{ .reg .u64 t; cvta.to.shared.u64 t, %1; cvt.u32.u64 %0, t; }" : "=r"(a) : "l"(p));
    return a;
}
#define CP_ASYNC16(saddr, gptr) \
    asm volatile("cp.async.cg.shared.global [%0], [%1], 16;" :: "r"((uint32_t)(saddr)), "l"(gptr))
#define CP_ASYNC_COMMIT()    asm volatile("cp.async.commit_group;" ::: "memory")
#define CP_ASYNC_WAIT_ALL()  asm volatile("cp.async.wait_group 0;" ::: "memory")
#define CP_ASYNC_WAIT_1()    asm volatile("cp.async.wait_group 1;" ::: "memory")

__device__ __forceinline__ void ldsm4(uint32_t r[4], uint32_t a) {
    asm volatile("ldmatrix.sync.aligned.m8n8.x4.shared.b16 {%0,%1,%2,%3}, [%4];"
        : "=r"(r[0]), "=r"(r[1]), "=r"(r[2]), "=r"(r[3]) : "r"(a));
}
__device__ __forceinline__ void ldsm4t(uint32_t r[4], uint32_t a) {
    asm volatile("ldmatrix.sync.aligned.m8n8.x4.trans.shared.b16 {%0,%1,%2,%3}, [%4];"
        : "=r"(r[0]), "=r"(r[1]), "=r"(r[2]), "=r"(r[3]) : "r"(a));
}
__device__ __forceinline__ void mma16816(float c[4], const uint32_t a[4], uint32_t b0, uint32_t b1) {
    asm volatile("mma.sync.aligned.m16n8k16.row.col.f32.bf16.bf16.f32 "
        "{%0,%1,%2,%3}, {%4,%5,%6,%7}, {%8,%9}, {%0,%1,%2,%3};"
        : "+f"(c[0]), "+f"(c[1]), "+f"(c[2]), "+f"(c[3])
        : "r"(a[0]), "r"(a[1]), "r"(a[2]), "r"(a[3]), "r"(b0), "r"(b1));
}
__device__ __forceinline__ uint32_t pack_hi(float x, float y) {
    __nv_bfloat162 h = __floats2bfloat162_rn(x, y);
    return *(uint32_t*)&h;
}
__device__ __forceinline__ uint32_t pack_lo(float x, float y) {
    float xr = x - __bfloat162float(__float2bfloat16(x));
    float yr = y - __bfloat162float(__float2bfloat16(y));
    __nv_bfloat162 h = __floats2bfloat162_rn(xr, yr);
    return *(uint32_t*)&h;
}

// ============================================================================
// Batched fp32 -> (bf16 hi, bf16 lo)
// ============================================================================
__global__ __launch_bounds__(256) void conv_hilo4(
    const float* __restrict__ x0, const float* __restrict__ x1,
    const float* __restrict__ x2, const float* __restrict__ x3,
    __nv_bfloat16* __restrict__ hi, __nv_bfloat16* __restrict__ lo, int n4)
{
    int i = blockIdx.x * blockDim.x + threadIdx.x;
    if (i >= n4) return;
    const float* x = (blockIdx.y == 0) ? x0 : (blockIdx.y == 1) ? x1
                   : (blockIdx.y == 2) ? x2 : x3;
    size_t o = (size_t)blockIdx.y * n4 + i;
    float4 v = ((const float4*)x)[i];
    uint2 H, L;
    H.x = pack_hi(v.x, v.y); H.y = pack_hi(v.z, v.w);
    L.x = pack_lo(v.x, v.y); L.y = pack_lo(v.z, v.w);
    ((uint2*)hi)[o] = H;
    ((uint2*)lo)[o] = L;
}

// ============================================================================
// HMMA GEMM (3-term hi/lo), BM=BN=128, BK=32, 8 warps, 2 CTAs/SM forced.
// ============================================================================
#define BK 32
#define GPAD 40
#define MAT_B (128 * GPAD * 2)
#define STG_B (4 * MAT_B)
#define NIT (D_MODEL / BK)
#define GEMM_SMEM (2 * STG_B)

__global__ __launch_bounds__(256, 2) void gemm_tc(
    const __nv_bfloat16* __restrict__ Ahi, const __nv_bfloat16* __restrict__ Alo,
    const __nv_bfloat16* __restrict__ Whi, const __nv_bfloat16* __restrict__ Wlo,
    const float* __restrict__ bias,
    float* __restrict__ Cf,
    __nv_bfloat16* __restrict__ Chi, __nv_bfloat16* __restrict__ Clo,
    int split, float oscale)
{
    extern __shared__ char smem[];
    const uint32_t sb = smem_u32(smem);
    const int t = threadIdx.x;
    const int lane = t & 31, wid = t >> 5;
    const int wm = wid >> 2, wn = wid & 3;
    const int m0 = blockIdx.y * 128, n0 = blockIdx.x * 128;

    float c[4][4][4];
#pragma unroll
    for (int i = 0; i < 4; i++)
#pragma unroll
        for (int j = 0; j < 4; j++)
#pragma unroll
            for (int k = 0; k < 4; k++) c[i][j][k] = 0.0f;

    auto load_stage = [&](int s, int it) {
        const int k0 = it * BK;
        const uint32_t st = sb + s * STG_B;
#pragma unroll
        for (int j = 0; j < 2; j++) {
            int idx = t + j * 256;
            int r = idx >> 2, cc = idx & 3;
            uint32_t so = (uint32_t)(r * (GPAD * 2) + cc * 16);
            const __nv_bfloat16* ga = Ahi + (size_t)(m0 + r) * D_MODEL + k0 + cc * 8;
            const __nv_bfloat16* gl = Alo + (size_t)(m0 + r) * D_MODEL + k0 + cc * 8;
            const __nv_bfloat16* gw = Whi + (size_t)(n0 + r) * D_MODEL + k0 + cc * 8;
            const __nv_bfloat16* gv = Wlo + (size_t)(n0 + r) * D_MODEL + k0 + cc * 8;
            CP_ASYNC16(st + 0 * MAT_B + so, ga);
            CP_ASYNC16(st + 1 * MAT_B + so, gl);
            CP_ASYNC16(st + 2 * MAT_B + so, gw);
            CP_ASYNC16(st + 3 * MAT_B + so, gv);
        }
    };

    load_stage(0, 0);
    CP_ASYNC_COMMIT();

    for (int it = 0; it < NIT; ++it) {
        const int s = it & 1;
        if (it + 1 < NIT) {
            load_stage(s ^ 1, it + 1);
            CP_ASYNC_COMMIT();
            CP_ASYNC_WAIT_1();
        } else {
            CP_ASYNC_WAIT_ALL();
        }
        __syncthreads();

        const uint32_t st = sb + s * STG_B;
#pragma unroll
        for (int kk = 0; kk < 2; kk++) {
            uint32_t ah[4][4], al[4][4];
#pragma unroll
            for (int mi = 0; mi < 4; mi++) {
                uint32_t ro = (uint32_t)((wm * 64 + mi * 16 + (lane & 15)) * (GPAD * 2)
                                         + (kk * 16 + (lane >> 4) * 8) * 2);
                ldsm4(ah[mi], st + 0 * MAT_B + ro);
                ldsm4(al[mi], st + 1 * MAT_B + ro);
            }
            uint32_t bh_[2][4], bl_[2][4];
#pragma unroll
            for (int nj = 0; nj < 2; nj++) {
                uint32_t ro = (uint32_t)((wn * 32 + nj * 16 + (lane & 7) + ((lane >> 4) * 8)) * (GPAD * 2)
                                         + (kk * 16 + ((lane >> 3) & 1) * 8) * 2);
                ldsm4(bh_[nj], st + 2 * MAT_B + ro);
                ldsm4(bl_[nj], st + 3 * MAT_B + ro);
            }
#pragma unroll
            for (int mi = 0; mi < 4; mi++)
#pragma unroll
                for (int ni = 0; ni < 4; ni++) {
                    const int nj = ni >> 1, ss = (ni & 1) * 2;
                    mma16816(c[mi][ni], ah[mi], bh_[nj][ss], bh_[nj][ss + 1]);
                    mma16816(c[mi][ni], ah[mi], bl_[nj][ss], bl_[nj][ss + 1]);
                    mma16816(c[mi][ni], al[mi], bh_[nj][ss], bh_[nj][ss + 1]);
                }
        }
        __syncthreads();
    }

    // ---- epilogue ----
#pragma unroll
    for (int mi = 0; mi < 4; mi++) {
        const int r0 = m0 + wm * 64 + mi * 16 + (lane >> 2);
#pragma unroll
        for (int ni = 0; ni < 4; ni++) {
            const int col = n0 + wn * 32 + ni * 8 + (lane & 3) * 2;
            const float b0 = bias[col], b1 = bias[col + 1];
            float v00 = (c[mi][ni][0] + b0) * oscale, v01 = (c[mi][ni][1] + b1) * oscale;
            float v10 = (c[mi][ni][2] + b0) * oscale, v11 = (c[mi][ni][3] + b1) * oscale;
            if (!split) {
                float2* d0 = (float2*)(Cf + (size_t)r0 * D_MODEL + col);
                float2* d1 = (float2*)(Cf + (size_t)(r0 + 8) * D_MODEL + col);
                *d0 = make_float2(v00, v01);
                *d1 = make_float2(v10, v11);
            } else {
                const int h = col >> 6, d = col & 63;
#pragma unroll
                for (int rr = 0; rr < 2; rr++) {
                    const int m = r0 + rr * 8;
                    const int b = m >> 11, sdx = m & 2047;
                    const size_t off = (((size_t)(b * NUM_HEADS + h) * SEQ + sdx) * DK + d);
                    const float x = rr ? v10 : v00, y = rr ? v11 : v01;
                    *(uint32_t*)(Chi + off) = pack_hi(x, y);
                    *(uint32_t*)(Clo + off) = pack_lo(x, y);
                }
            }
        }
    }
}

// ============================================================================
// FA2-style HMMA attention: 256 threads (8 warps), warp owns 16 q-rows x ALL
// 128 kv cols. P stays in registers (frag relayout), softmax warp-local,
// ONE __syncthreads per kv iteration. K & V double-buffered.
// ============================================================================
#define AST 144                               /* row stride bytes */
#define A_OFF_QH 0
#define A_OFF_QL (A_OFF_QH + 128 * AST)
#define A_KBASE  (A_OFF_QL + 128 * AST)       /* 36864 */
#define A_OFF_KH(b) (A_KBASE + (b) * (2 * 128 * AST))
#define A_OFF_KL(b) (A_OFF_KH(b) + 128 * AST)
#define A_VBASE  (A_KBASE + 2 * (2 * 128 * AST))
#define A_OFF_VH(b) (A_VBASE + (b) * (2 * 128 * AST))
#define A_OFF_VL(b) (A_OFF_VH(b) + 128 * AST)
#define ATTN_SMEM (A_VBASE + 2 * (2 * 128 * AST))   /* 184320 B */

__global__ __launch_bounds__(256) void attn_tc()
{
    extern __shared__ char smem[];
    const uint32_t sb = smem_u32(smem);
    const int t = threadIdx.x;
    const int lane = t & 31, w = t >> 5;      // 8 warps, warp w owns rows w*16..+15
    const int qt = blockIdx.x, bh = blockIdx.y;

    const __nv_bfloat16* Qh = g_Qhi + ((size_t)bh * SEQ + qt * 128) * DK;
    const __nv_bfloat16* Ql = g_Qlo + ((size_t)bh * SEQ + qt * 128) * DK;
    const __nv_bfloat16* Kh = g_Khi + (size_t)bh * SEQ * DK;
    const __nv_bfloat16* Kl = g_Klo + (size_t)bh * SEQ * DK;
    const __nv_bfloat16* Vh = g_Vhi + (size_t)bh * SEQ * DK;
    const __nv_bfloat16* Vl = g_Vlo + (size_t)bh * SEQ * DK;

    auto ldtile = [&](uint32_t dstoff, const __nv_bfloat16* src) {   // 128x64 bf16
#pragma unroll
        for (int j = 0; j < 4; j++) {
            int idx = t + j * 256;
            int r = idx >> 3, cc = idx & 7;
            CP_ASYNC16(sb + dstoff + r * AST + cc * 16, src + r * DK + cc * 8);
        }
    };

    ldtile(A_OFF_QH, Qh); ldtile(A_OFF_QL, Ql);
    ldtile(A_OFF_KH(0), Kh); ldtile(A_OFF_KL(0), Kl);
    ldtile(A_OFF_VH(0), Vh); ldtile(A_OFF_VL(0), Vl);
    CP_ASYNC_COMMIT();
    CP_ASYNC_WAIT_ALL();
    __syncthreads();

    // preload Q fragments (A-operand) for all 4 k16 chunks
    uint32_t qh[4][4], ql[4][4];
#pragma unroll
    for (int kk = 0; kk < 4; kk++) {
        uint32_t ro = (uint32_t)((w * 16 + (lane & 15)) * AST + (kk * 16 + (lane >> 4) * 8) * 2);
        ldsm4(qh[kk], sb + A_OFF_QH + ro);
        ldsm4(ql[kk], sb + A_OFF_QL + ro);
    }

    float o[8][4];
#pragma unroll
    for (int i = 0; i < 8; i++)
#pragma unroll
        for (int k = 0; k < 4; k++) o[i][k] = 0.0f;
    float m0 = -1e30f, m1 = -1e30f, l0 = 0.0f, l1 = 0.0f;

    for (int kt = 0; kt < KVTILES; kt++) {
        const int vb = kt & 1;

        if (kt + 1 < KVTILES) {
            ldtile(A_OFF_KH(vb ^ 1), Kh + (size_t)(kt + 1) * 128 * DK);
            ldtile(A_OFF_KL(vb ^ 1), Kl + (size_t)(kt + 1) * 128 * DK);
            ldtile(A_OFF_VH(vb ^ 1), Vh + (size_t)(kt + 1) * 128 * DK);
            ldtile(A_OFF_VL(vb ^ 1), Vl + (size_t)(kt + 1) * 128 * DK);
            CP_ASYNC_COMMIT();
        }

        // ---- S = Q K^T : warp strip 16 rows x 128 cols (16 n8-tiles) ----
        float c[16][4];
#pragma unroll
        for (int i = 0; i < 16; i++)
#pragma unroll
            for (int k = 0; k < 4; k++) c[i][k] = 0.0f;

#pragma unroll
        for (int kk = 0; kk < 4; kk++) {
#pragma unroll
            for (int nj = 0; nj < 8; nj++) {
                uint32_t bh_[4], bl_[4];
                uint32_t ro = (uint32_t)((nj * 16 + (lane & 7) + ((lane >> 4) * 8)) * AST
                                         + (kk * 16 + ((lane >> 3) & 1) * 8) * 2);
                ldsm4(bh_, sb + A_OFF_KH(vb) + ro);
                ldsm4(bl_, sb + A_OFF_KL(vb) + ro);
                mma16816(c[2 * nj],     qh[kk], bh_[0], bh_[1]);
                mma16816(c[2 * nj],     qh[kk], bl_[0], bl_[1]);
                mma16816(c[2 * nj],     ql[kk], bh_[0], bh_[1]);
                mma16816(c[2 * nj + 1], qh[kk], bh_[2], bh_[3]);
                mma16816(c[2 * nj + 1], qh[kk], bl_[2], bl_[3]);
                mma16816(c[2 * nj + 1], ql[kk], bh_[2], bh_[3]);
            }
        }

        // ---- warp-local online softmax (rows r=lane>>2 and r+8) ----
        float mx0 = -1e30f, mx1 = -1e30f;
#pragma unroll
        for (int ni = 0; ni < 16; ni++) {
            mx0 = fmaxf(mx0, fmaxf(c[ni][0], c[ni][1]));
            mx1 = fmaxf(mx1, fmaxf(c[ni][2], c[ni][3]));
        }
        mx0 = fmaxf(mx0, __shfl_xor_sync(0xffffffffu, mx0, 1));
        mx0 = fmaxf(mx0, __shfl_xor_sync(0xffffffffu, mx0, 2));
        mx1 = fmaxf(mx1, __shfl_xor_sync(0xffffffffu, mx1, 1));
        mx1 = fmaxf(mx1, __shfl_xor_sync(0xffffffffu, mx1, 2));

        const float nm0 = fmaxf(m0, mx0), nm1 = fmaxf(m1, mx1);
        const float alpha0 = __expf(m0 - nm0), alpha1 = __expf(m1 - nm1);
        m0 = nm0; m1 = nm1;

        float s0 = 0.0f, s1 = 0.0f;
#pragma unroll
        for (int ni = 0; ni < 16; ni++) {
            c[ni][0] = __expf(c[ni][0] - nm0);
            c[ni][1] = __expf(c[ni][1] - nm0);
            c[ni][2] = __expf(c[ni][2] - nm1);
            c[ni][3] = __expf(c[ni][3] - nm1);
            s0 += c[ni][0] + c[ni][1];
            s1 += c[ni][2] + c[ni][3];
        }
        s0 += __shfl_xor_sync(0xffffffffu, s0, 1);
        s0 += __shfl_xor_sync(0xffffffffu, s0, 2);
        s1 += __shfl_xor_sync(0xffffffffu, s1, 1);
        s1 += __shfl_xor_sync(0xffffffffu, s1, 2);
        l0 = l0 * alpha0 + s0;
        l1 = l1 * alpha1 + s1;

        // ---- rescale O ----
#pragma unroll
        for (int i = 0; i < 8; i++) {
            o[i][0] *= alpha0; o[i][1] *= alpha0;
            o[i][2] *= alpha1; o[i][3] *= alpha1;
        }

        // ---- O += P V : P A-frags straight from C-frags (no smem) ----
#pragma unroll
        for (int kk = 0; kk < 8; kk++) {
            uint32_t ph[4], pl[4];
            ph[0] = pack_hi(c[2 * kk][0], c[2 * kk][1]);
            ph[1] = pack_hi(c[2 * kk][2], c[2 * kk][3]);
            ph[2] = pack_hi(c[2 * kk + 1][0], c[2 * kk + 1][1]);
            ph[3] = pack_hi(c[2 * kk + 1][2], c[2 * kk + 1][3]);
            pl[0] = pack_lo(c[2 * kk][0], c[2 * kk][1]);
            pl[1] = pack_lo(c[2 * kk][2], c[2 * kk][3]);
            pl[2] = pack_lo(c[2 * kk + 1][0], c[2 * kk + 1][1]);
            pl[3] = pack_lo(c[2 * kk + 1][2], c[2 * kk + 1][3]);
#pragma unroll
            for (int nj = 0; nj < 4; nj++) {
                uint32_t vh[4], vl[4];
                uint32_t ro = (uint32_t)((kk * 16 + (lane & 15)) * AST
                                         + (nj * 16 + (lane >> 4) * 8) * 2);
                ldsm4t(vh, sb + A_OFF_VH(vb) + ro);
                ldsm4t(vl, sb + A_OFF_VL(vb) + ro);
                mma16816(o[2 * nj],     ph, vh[0], vh[1]);
                mma16816(o[2 * nj],     ph, vl[0], vl[1]);
                mma16816(o[2 * nj],     pl, vh[0], vh[1]);
                mma16816(o[2 * nj + 1], ph, vh[2], vh[3]);
                mma16816(o[2 * nj + 1], ph, vl[2], vl[3]);
                mma16816(o[2 * nj + 1], pl, vh[2], vh[3]);
            }
        }

        if (kt + 1 < KVTILES) CP_ASYNC_WAIT_ALL();
        __syncthreads();   // all warps done reading bufs before next overwrite
    }

    // ---- epilogue: normalize, emit bf16 hi/lo ctx in [B,S,1024] (slot 0) ----
    const int b = bh >> 4, h = bh & 15;
    const float inv0 = 1.0f / l0, inv1 = 1.0f / l1;
    const size_t row0 = (size_t)(b * SEQ + qt * 128 + w * 16 + (lane >> 2));
#pragma unroll
    for (int on = 0; on < 8; on++) {
        const int colg = h * DK + on * 8 + (lane & 3) * 2;
        *(uint32_t*)(g_ahi + row0 * D_MODEL + colg) = pack_hi(o[on][0] * inv0, o[on][1] * inv0);
        *(uint32_t*)(g_alo + row0 * D_MODEL + colg) = pack_lo(o[on][0] * inv0, o[on][1] * inv0);
        *(uint32_t*)(g_ahi + (row0 + 8) * D_MODEL + colg) = pack_hi(o[on][2] * inv1, o[on][3] * inv1);
        *(uint32_t*)(g_alo + (row0 + 8) * D_MODEL + colg) = pack_lo(o[on][2] * inv1, o[on][3] * inv1);
    }
}

// ============================================================================
// launch
// ============================================================================
extern "C" void kernel_launch(void* const* d_in, const int* in_sizes, int n_in,
                              void* d_out, int out_size)
{
    const float* query  = (const float*)d_in[0];
    const float* key_in = (const float*)d_in[1];
    const float* value  = (const float*)d_in[2];
    const float* Wq = (const float*)d_in[3];
    const float* bq = (const float*)d_in[4];
    const float* Wk = (const float*)d_in[5];
    const float* bk = (const float*)d_in[6];
    const float* Wv = (const float*)d_in[7];
    const float* bv = (const float*)d_in[8];
    const float* Wo = (const float*)d_in[9];
    const float* bo = (const float*)d_in[10];
    float* out = (float*)d_out;

    __nv_bfloat16 *qhi, *qlo, *khi, *klo, *vhi, *vlo, *ahi, *alo, *whi, *wlo;
    cudaGetSymbolAddress((void**)&qhi, g_Qhi);
    cudaGetSymbolAddress((void**)&qlo, g_Qlo);
    cudaGetSymbolAddress((void**)&khi, g_Khi);
    cudaGetSymbolAddress((void**)&klo, g_Klo);
    cudaGetSymbolAddress((void**)&vhi, g_Vhi);
    cudaGetSymbolAddress((void**)&vlo, g_Vlo);
    cudaGetSymbolAddress((void**)&ahi, g_ahi);
    cudaGetSymbolAddress((void**)&alo, g_alo);
    cudaGetSymbolAddress((void**)&whi, g_whi);
    cudaGetSymbolAddress((void**)&wlo, g_wlo);

    cudaFuncSetAttribute(gemm_tc, cudaFuncAttributeMaxDynamicSharedMemorySize, GEMM_SMEM);
    cudaFuncSetAttribute(attn_tc, cudaFuncAttributeMaxDynamicSharedMemorySize, ATTN_SMEM);

    const int ACT4 = MROWS * D_MODEL / 4;
    const int W4   = D_MODEL * D_MODEL / 4;
    const size_t ASL = (size_t)MROWS * D_MODEL;
    const size_t WSL = (size_t)D_MODEL * D_MODEL;

    dim3 ggrd(D_MODEL / 128, MROWS / 128), gblk(256);

    conv_hilo4<<<dim3((W4 + 255) / 256, 4), 256>>>(Wq, Wk, Wv, Wo, whi, wlo, W4);
    conv_hilo4<<<dim3((ACT4 + 255) / 256, 3), 256>>>(query, key_in, value, value, ahi, alo, ACT4);

    const float qscale = 0.125f;
    gemm_tc<<<ggrd, gblk, GEMM_SMEM>>>(ahi + 0 * ASL, alo + 0 * ASL, whi + 0 * WSL, wlo + 0 * WSL,
                                       bq, nullptr, qhi, qlo, 1, qscale);
    gemm_tc<<<ggrd, gblk, GEMM_SMEM>>>(ahi + 1 * ASL, alo + 1 * ASL, whi + 1 * WSL, wlo + 1 * WSL,
                                       bk, nullptr, khi, klo, 1, 1.0f);
    gemm_tc<<<ggrd, gblk, GEMM_SMEM>>>(ahi + 2 * ASL, alo + 2 * ASL, whi + 2 * WSL, wlo + 2 * WSL,
                                       bv, nullptr, vhi, vlo, 1, 1.0f);

    attn_tc<<<dim3(SEQ / 128, BATCH * NUM_HEADS), dim3(256), ATTN_SMEM>>>();

    gemm_tc<<<ggrd, gblk, GEMM_SMEM>>>(ahi, alo, whi + 3 * WSL, wlo + 3 * WSL,
                                       bo, out, nullptr, nullptr, 0, 1.0f);
}

// round 6
// speedup vs baseline: 2.9838x; 1.0416x over previous
#include <cuda_runtime.h>
#include <cuda_bf16.h>
#include <cstdint>

#define D_MODEL 1024
#define NUM_HEADS 16
#define DK 64
#define BATCH 4
#define SEQ 2048
#define MROWS (BATCH * SEQ)   /* 8192 */
#define KVTILES (SEQ / 128)   /* 16 */

// ---------------- scratch (bf16 hi/lo everywhere) ----------------
__device__ __nv_bfloat16 g_Qhi[BATCH * NUM_HEADS * SEQ * DK];
__device__ __nv_bfloat16 g_Qlo[BATCH * NUM_HEADS * SEQ * DK];
__device__ __nv_bfloat16 g_Khi[BATCH * NUM_HEADS * SEQ * DK];
__device__ __nv_bfloat16 g_Klo[BATCH * NUM_HEADS * SEQ * DK];
__device__ __nv_bfloat16 g_Vhi[BATCH * NUM_HEADS * SEQ * DK];
__device__ __nv_bfloat16 g_Vlo[BATCH * NUM_HEADS * SEQ * DK];
__device__ __nv_bfloat16 g_ahi[3 * MROWS * D_MODEL];
__device__ __nv_bfloat16 g_alo[3 * MROWS * D_MODEL];
__device__ __nv_bfloat16 g_whi[4 * D_MODEL * D_MODEL];
__device__ __nv_bfloat16 g_wlo[4 * D_MODEL * D_MODEL];

// ---------------- helpers ----------------
__device__ __forceinline__ uint32_t smem_u32(const void* p) {
    uint32_t a;
    asm("{ .reg .u64 t; cvta.to.shared.u64 t, %1; cvt.u32.u64 %0, t; }" : "=r"(a) : "l"(p));
    return a;
}
#define CP_ASYNC16(saddr, gptr) \
    asm volatile("cp.async.cg.shared.global [%0], [%1], 16;" :: "r"((uint32_t)(saddr)), "l"(gptr))
#define CP_ASYNC_COMMIT()    asm volatile("cp.async.commit_group;" ::: "memory")
#define CP_ASYNC_WAIT_ALL()  asm volatile("cp.async.wait_group 0;" ::: "memory")

__device__ __forceinline__ void ldsm4(uint32_t r[4], uint32_t a) {
    asm volatile("ldmatrix.sync.aligned.m8n8.x4.shared.b16 {%0,%1,%2,%3}, [%4];"
        : "=r"(r[0]), "=r"(r[1]), "=r"(r[2]), "=r"(r[3]) : "r"(a));
}
__device__ __forceinline__ void ldsm4t(uint32_t r[4], uint32_t a) {
    asm volatile("ldmatrix.sync.aligned.m8n8.x4.trans.shared.b16 {%0,%1,%2,%3}, [%4];"
        : "=r"(r[0]), "=r"(r[1]), "=r"(r[2]), "=r"(r[3]) : "r"(a));
}
__device__ __forceinline__ void mma16816(float c[4], const uint32_t a[4], uint32_t b0, uint32_t b1) {
    asm volatile("mma.sync.aligned.m16n8k16.row.col.f32.bf16.bf16.f32 "
        "{%0,%1,%2,%3}, {%4,%5,%6,%7}, {%8,%9}, {%0,%1,%2,%3};"
        : "+f"(c[0]), "+f"(c[1]), "+f"(c[2]), "+f"(c[3])
        : "r"(a[0]), "r"(a[1]), "r"(a[2]), "r"(a[3]), "r"(b0), "r"(b1));
}
__device__ __forceinline__ uint32_t pack_hi(float x, float y) {
    __nv_bfloat162 h = __floats2bfloat162_rn(x, y);
    return *(uint32_t*)&h;
}
__device__ __forceinline__ uint32_t pack_lo(float x, float y) {
    float xr = x - __bfloat162float(__float2bfloat16(x));
    float yr = y - __bfloat162float(__float2bfloat16(y));
    __nv_bfloat162 h = __floats2bfloat162_rn(xr, yr);
    return *(uint32_t*)&h;
}

// ============================================================================
// Batched fp32 -> (bf16 hi, bf16 lo)
// ============================================================================
__global__ __launch_bounds__(256) void conv_hilo4(
    const float* __restrict__ x0, const float* __restrict__ x1,
    const float* __restrict__ x2, const float* __restrict__ x3,
    __nv_bfloat16* __restrict__ hi, __nv_bfloat16* __restrict__ lo, int n4)
{
    int i = blockIdx.x * blockDim.x + threadIdx.x;
    if (i >= n4) return;
    const float* x = (blockIdx.y == 0) ? x0 : (blockIdx.y == 1) ? x1
                   : (blockIdx.y == 2) ? x2 : x3;
    size_t o = (size_t)blockIdx.y * n4 + i;
    float4 v = ((const float4*)x)[i];
    uint2 H, L;
    H.x = pack_hi(v.x, v.y); H.y = pack_hi(v.z, v.w);
    L.x = pack_lo(v.x, v.y); L.y = pack_lo(v.z, v.w);
    ((uint2*)hi)[o] = H;
    ((uint2*)lo)[o] = L;
}

// ============================================================================
// Shared GEMM mainloop (3-term hi/lo HMMA), BM=BN=128, BK=32, 8 warps.
// Single __syncthreads per k-iteration (wait -> sync -> issue-next -> compute).
// ============================================================================
#define BK 32
#define GPAD 40
#define MAT_B (128 * GPAD * 2)
#define STG_B (4 * MAT_B)
#define NIT (D_MODEL / BK)
#define GEMM_SMEM (2 * STG_B)

__device__ __forceinline__ void gemm_main(
    uint32_t sb, int t,
    const __nv_bfloat16* __restrict__ Ahi, const __nv_bfloat16* __restrict__ Alo,
    const __nv_bfloat16* __restrict__ Whi, const __nv_bfloat16* __restrict__ Wlo,
    int m0, int n0, float c[4][4][4])
{
    const int lane = t & 31, wid = t >> 5;
    const int wm = wid >> 2, wn = wid & 3;

    auto load_stage = [&](int s, int it) {
        const int k0 = it * BK;
        const uint32_t st = sb + s * STG_B;
#pragma unroll
        for (int j = 0; j < 2; j++) {
            int idx = t + j * 256;
            int r = idx >> 2, cc = idx & 3;
            uint32_t so = (uint32_t)(r * (GPAD * 2) + cc * 16);
            CP_ASYNC16(st + 0 * MAT_B + so, Ahi + (size_t)(m0 + r) * D_MODEL + k0 + cc * 8);
            CP_ASYNC16(st + 1 * MAT_B + so, Alo + (size_t)(m0 + r) * D_MODEL + k0 + cc * 8);
            CP_ASYNC16(st + 2 * MAT_B + so, Whi + (size_t)(n0 + r) * D_MODEL + k0 + cc * 8);
            CP_ASYNC16(st + 3 * MAT_B + so, Wlo + (size_t)(n0 + r) * D_MODEL + k0 + cc * 8);
        }
    };

    load_stage(0, 0);
    CP_ASYNC_COMMIT();

    for (int it = 0; it < NIT; ++it) {
        const int s = it & 1;
        CP_ASYNC_WAIT_ALL();     // stage s data arrived
        __syncthreads();         // everyone done with stage s^1 (prev compute)
        if (it + 1 < NIT) {
            load_stage(s ^ 1, it + 1);
            CP_ASYNC_COMMIT();
        }

        const uint32_t st = sb + s * STG_B;
#pragma unroll
        for (int kk = 0; kk < 2; kk++) {
            uint32_t ah[4][4], al[4][4];
#pragma unroll
            for (int mi = 0; mi < 4; mi++) {
                uint32_t ro = (uint32_t)((wm * 64 + mi * 16 + (lane & 15)) * (GPAD * 2)
                                         + (kk * 16 + (lane >> 4) * 8) * 2);
                ldsm4(ah[mi], st + 0 * MAT_B + ro);
                ldsm4(al[mi], st + 1 * MAT_B + ro);
            }
            uint32_t bh_[2][4], bl_[2][4];
#pragma unroll
            for (int nj = 0; nj < 2; nj++) {
                uint32_t ro = (uint32_t)((wn * 32 + nj * 16 + (lane & 7) + ((lane >> 4) * 8)) * (GPAD * 2)
                                         + (kk * 16 + ((lane >> 3) & 1) * 8) * 2);
                ldsm4(bh_[nj], st + 2 * MAT_B + ro);
                ldsm4(bl_[nj], st + 3 * MAT_B + ro);
            }
#pragma unroll
            for (int mi = 0; mi < 4; mi++)
#pragma unroll
                for (int ni = 0; ni < 4; ni++) {
                    const int nj = ni >> 1, ss = (ni & 1) * 2;
                    mma16816(c[mi][ni], ah[mi], bh_[nj][ss], bh_[nj][ss + 1]);
                    mma16816(c[mi][ni], ah[mi], bl_[nj][ss], bl_[nj][ss + 1]);
                    mma16816(c[mi][ni], al[mi], bh_[nj][ss], bh_[nj][ss + 1]);
                }
        }
    }
}

// ---- fused Q/K/V projection: blockIdx.z selects weight/bias/output ----
__global__ __launch_bounds__(256, 2) void gemm_qkv(
    const __nv_bfloat16* __restrict__ ahi_all, const __nv_bfloat16* __restrict__ alo_all,
    const __nv_bfloat16* __restrict__ whi_all, const __nv_bfloat16* __restrict__ wlo_all,
    const float* __restrict__ bq, const float* __restrict__ bk, const float* __restrict__ bv,
    __nv_bfloat16* __restrict__ qhi, __nv_bfloat16* __restrict__ qlo,
    __nv_bfloat16* __restrict__ khi, __nv_bfloat16* __restrict__ klo,
    __nv_bfloat16* __restrict__ vhi, __nv_bfloat16* __restrict__ vlo)
{
    extern __shared__ char smem[];
    const uint32_t sb = smem_u32(smem);
    const int t = threadIdx.x;
    const int lane = t & 31, wid = t >> 5;
    const int wm = wid >> 2, wn = wid & 3;
    const int m0 = blockIdx.y * 128, n0 = blockIdx.x * 128;
    const int z = blockIdx.z;

    const size_t ASL = (size_t)MROWS * D_MODEL;
    const size_t WSL = (size_t)D_MODEL * D_MODEL;
    const __nv_bfloat16* Ahi = ahi_all + z * ASL;
    const __nv_bfloat16* Alo = alo_all + z * ASL;
    const __nv_bfloat16* Whi = whi_all + z * WSL;
    const __nv_bfloat16* Wlo = wlo_all + z * WSL;
    const float* bias = (z == 0) ? bq : (z == 1) ? bk : bv;
    __nv_bfloat16* Chi = (z == 0) ? qhi : (z == 1) ? khi : vhi;
    __nv_bfloat16* Clo = (z == 0) ? qlo : (z == 1) ? klo : vlo;
    const float oscale = (z == 0) ? 0.125f : 1.0f;

    float c[4][4][4];
#pragma unroll
    for (int i = 0; i < 4; i++)
#pragma unroll
        for (int j = 0; j < 4; j++)
#pragma unroll
            for (int k = 0; k < 4; k++) c[i][j][k] = 0.0f;

    gemm_main(sb, t, Ahi, Alo, Whi, Wlo, m0, n0, c);

#pragma unroll
    for (int mi = 0; mi < 4; mi++) {
        const int r0 = m0 + wm * 64 + mi * 16 + (lane >> 2);
#pragma unroll
        for (int ni = 0; ni < 4; ni++) {
            const int col = n0 + wn * 32 + ni * 8 + (lane & 3) * 2;
            const float b0 = bias[col], b1 = bias[col + 1];
            const int h = col >> 6, d = col & 63;
            float v00 = (c[mi][ni][0] + b0) * oscale, v01 = (c[mi][ni][1] + b1) * oscale;
            float v10 = (c[mi][ni][2] + b0) * oscale, v11 = (c[mi][ni][3] + b1) * oscale;
#pragma unroll
            for (int rr = 0; rr < 2; rr++) {
                const int m = r0 + rr * 8;
                const int b = m >> 11, sdx = m & 2047;
                const size_t off = (((size_t)(b * NUM_HEADS + h) * SEQ + sdx) * DK + d);
                const float x = rr ? v10 : v00, y = rr ? v11 : v01;
                *(uint32_t*)(Chi + off) = pack_hi(x, y);
                *(uint32_t*)(Clo + off) = pack_lo(x, y);
            }
        }
    }
}

// ---- output projection: fp32 row-major ----
__global__ __launch_bounds__(256, 2) void gemm_out(
    const __nv_bfloat16* __restrict__ Ahi, const __nv_bfloat16* __restrict__ Alo,
    const __nv_bfloat16* __restrict__ Whi, const __nv_bfloat16* __restrict__ Wlo,
    const float* __restrict__ bias, float* __restrict__ Cf)
{
    extern __shared__ char smem[];
    const uint32_t sb = smem_u32(smem);
    const int t = threadIdx.x;
    const int lane = t & 31, wid = t >> 5;
    const int wm = wid >> 2, wn = wid & 3;
    const int m0 = blockIdx.y * 128, n0 = blockIdx.x * 128;

    float c[4][4][4];
#pragma unroll
    for (int i = 0; i < 4; i++)
#pragma unroll
        for (int j = 0; j < 4; j++)
#pragma unroll
            for (int k = 0; k < 4; k++) c[i][j][k] = 0.0f;

    gemm_main(sb, t, Ahi, Alo, Whi, Wlo, m0, n0, c);

#pragma unroll
    for (int mi = 0; mi < 4; mi++) {
        const int r0 = m0 + wm * 64 + mi * 16 + (lane >> 2);
#pragma unroll
        for (int ni = 0; ni < 4; ni++) {
            const int col = n0 + wn * 32 + ni * 8 + (lane & 3) * 2;
            const float b0 = bias[col], b1 = bias[col + 1];
            *(float2*)(Cf + (size_t)r0 * D_MODEL + col) =
                make_float2(c[mi][ni][0] + b0, c[mi][ni][1] + b1);
            *(float2*)(Cf + (size_t)(r0 + 8) * D_MODEL + col) =
                make_float2(c[mi][ni][2] + b0, c[mi][ni][3] + b1);
        }
    }
}

// ============================================================================
// FA2 HMMA attention: 512 threads (16 warps), CTA = 256 q-rows.
// Warp owns 16 q-rows x all 128 kv cols; P register-resident; 1 sync/kv-iter.
// ============================================================================
#define AST 144
#define AT_QH 0
#define AT_QL (AT_QH + 256 * AST)
#define AT_KB (AT_QL + 256 * AST)                 /* 73728 */
#define AT_KH(b) (AT_KB + (b) * (2 * 128 * AST))
#define AT_KL(b) (AT_KH(b) + 128 * AST)
#define AT_VB (AT_KB + 2 * (2 * 128 * AST))
#define AT_VH(b) (AT_VB + (b) * (2 * 128 * AST))
#define AT_VL(b) (AT_VH(b) + 128 * AST)
#define ATTN_SMEM (AT_VB + 2 * (2 * 128 * AST))   /* 221184 B */

__global__ __launch_bounds__(512) void attn_tc()
{
    extern __shared__ char smem[];
    const uint32_t sb = smem_u32(smem);
    const int t = threadIdx.x;
    const int lane = t & 31, w = t >> 5;      // 16 warps; warp w owns rows w*16..+15
    const int qt = blockIdx.x, bh = blockIdx.y;

    const __nv_bfloat16* Qh = g_Qhi + ((size_t)bh * SEQ + qt * 256) * DK;
    const __nv_bfloat16* Ql = g_Qlo + ((size_t)bh * SEQ + qt * 256) * DK;
    const __nv_bfloat16* Kh = g_Khi + (size_t)bh * SEQ * DK;
    const __nv_bfloat16* Kl = g_Klo + (size_t)bh * SEQ * DK;
    const __nv_bfloat16* Vh = g_Vhi + (size_t)bh * SEQ * DK;
    const __nv_bfloat16* Vl = g_Vlo + (size_t)bh * SEQ * DK;

    auto ldtile = [&](uint32_t dstoff, const __nv_bfloat16* src) {   // 128x64 bf16
#pragma unroll
        for (int j = 0; j < 2; j++) {
            int idx = t + j * 512;
            int r = idx >> 3, cc = idx & 7;
            CP_ASYNC16(sb + dstoff + r * AST + cc * 16, src + r * DK + cc * 8);
        }
    };
    auto ldtileQ = [&](uint32_t dstoff, const __nv_bfloat16* src) {  // 256x64 bf16
#pragma unroll
        for (int j = 0; j < 4; j++) {
            int idx = t + j * 512;
            int r = idx >> 3, cc = idx & 7;
            CP_ASYNC16(sb + dstoff + r * AST + cc * 16, src + r * DK + cc * 8);
        }
    };

    ldtileQ(AT_QH, Qh); ldtileQ(AT_QL, Ql);
    ldtile(AT_KH(0), Kh); ldtile(AT_KL(0), Kl);
    ldtile(AT_VH(0), Vh); ldtile(AT_VL(0), Vl);
    CP_ASYNC_COMMIT();
    CP_ASYNC_WAIT_ALL();
    __syncthreads();

    float o[8][4];
#pragma unroll
    for (int i = 0; i < 8; i++)
#pragma unroll
        for (int k = 0; k < 4; k++) o[i][k] = 0.0f;
    float m0 = -1e30f, m1 = -1e30f, l0 = 0.0f, l1 = 0.0f;

    for (int kt = 0; kt < KVTILES; kt++) {
        const int vb = kt & 1;

        if (kt + 1 < KVTILES) {
            ldtile(AT_KH(vb ^ 1), Kh + (size_t)(kt + 1) * 128 * DK);
            ldtile(AT_KL(vb ^ 1), Kl + (size_t)(kt + 1) * 128 * DK);
            ldtile(AT_VH(vb ^ 1), Vh + (size_t)(kt + 1) * 128 * DK);
            ldtile(AT_VL(vb ^ 1), Vl + (size_t)(kt + 1) * 128 * DK);
            CP_ASYNC_COMMIT();
        }

        // ---- S = Q K^T : 16 rows x 128 cols ----
        float c[16][4];
#pragma unroll
        for (int i = 0; i < 16; i++)
#pragma unroll
            for (int k = 0; k < 4; k++) c[i][k] = 0.0f;

#pragma unroll
        for (int kk = 0; kk < 4; kk++) {
            uint32_t qh[4], ql[4];   // reload Q frags per chunk (reg pressure)
            {
                uint32_t ro = (uint32_t)((w * 16 + (lane & 15)) * AST
                                         + (kk * 16 + (lane >> 4) * 8) * 2);
                ldsm4(qh, sb + AT_QH + ro);
                ldsm4(ql, sb + AT_QL + ro);
            }
#pragma unroll
            for (int nj = 0; nj < 8; nj++) {
                uint32_t bh_[4], bl_[4];
                uint32_t ro = (uint32_t)((nj * 16 + (lane & 7) + ((lane >> 4) * 8)) * AST
                                         + (kk * 16 + ((lane >> 3) & 1) * 8) * 2);
                ldsm4(bh_, sb + AT_KH(vb) + ro);
                ldsm4(bl_, sb + AT_KL(vb) + ro);
                mma16816(c[2 * nj],     qh, bh_[0], bh_[1]);
                mma16816(c[2 * nj],     qh, bl_[0], bl_[1]);
                mma16816(c[2 * nj],     ql, bh_[0], bh_[1]);
                mma16816(c[2 * nj + 1], qh, bh_[2], bh_[3]);
                mma16816(c[2 * nj + 1], qh, bl_[2], bl_[3]);
                mma16816(c[2 * nj + 1], ql, bh_[2], bh_[3]);
            }
        }

        // ---- warp-local online softmax ----
        float mx0 = -1e30f, mx1 = -1e30f;
#pragma unroll
        for (int ni = 0; ni < 16; ni++) {
            mx0 = fmaxf(mx0, fmaxf(c[ni][0], c[ni][1]));
            mx1 = fmaxf(mx1, fmaxf(c[ni][2], c[ni][3]));
        }
        mx0 = fmaxf(mx0, __shfl_xor_sync(0xffffffffu, mx0, 1));
        mx0 = fmaxf(mx0, __shfl_xor_sync(0xffffffffu, mx0, 2));
        mx1 = fmaxf(mx1, __shfl_xor_sync(0xffffffffu, mx1, 1));
        mx1 = fmaxf(mx1, __shfl_xor_sync(0xffffffffu, mx1, 2));

        const float nm0 = fmaxf(m0, mx0), nm1 = fmaxf(m1, mx1);
        const float alpha0 = __expf(m0 - nm0), alpha1 = __expf(m1 - nm1);
        m0 = nm0; m1 = nm1;

        float s0 = 0.0f, s1 = 0.0f;
#pragma unroll
        for (int ni = 0; ni < 16; ni++) {
            c[ni][0] = __expf(c[ni][0] - nm0);
            c[ni][1] = __expf(c[ni][1] - nm0);
            c[ni][2] = __expf(c[ni][2] - nm1);
            c[ni][3] = __expf(c[ni][3] - nm1);
            s0 += c[ni][0] + c[ni][1];
            s1 += c[ni][2] + c[ni][3];
        }
        s0 += __shfl_xor_sync(0xffffffffu, s0, 1);
        s0 += __shfl_xor_sync(0xffffffffu, s0, 2);
        s1 += __shfl_xor_sync(0xffffffffu, s1, 1);
        s1 += __shfl_xor_sync(0xffffffffu, s1, 2);
        l0 = l0 * alpha0 + s0;
        l1 = l1 * alpha1 + s1;

#pragma unroll
        for (int i = 0; i < 8; i++) {
            o[i][0] *= alpha0; o[i][1] *= alpha0;
            o[i][2] *= alpha1; o[i][3] *= alpha1;
        }

        // ---- O += P V : P A-frags straight from C-frags ----
#pragma unroll
        for (int kk = 0; kk < 8; kk++) {
            uint32_t ph[4], pl[4];
            ph[0] = pack_hi(c[2 * kk][0], c[2 * kk][1]);
            ph[1] = pack_hi(c[2 * kk][2], c[2 * kk][3]);
            ph[2] = pack_hi(c[2 * kk + 1][0], c[2 * kk + 1][1]);
            ph[3] = pack_hi(c[2 * kk + 1][2], c[2 * kk + 1][3]);
            pl[0] = pack_lo(c[2 * kk][0], c[2 * kk][1]);
            pl[1] = pack_lo(c[2 * kk][2], c[2 * kk][3]);
            pl[2] = pack_lo(c[2 * kk + 1][0], c[2 * kk + 1][1]);
            pl[3] = pack_lo(c[2 * kk + 1][2], c[2 * kk + 1][3]);
#pragma unroll
            for (int nj = 0; nj < 4; nj++) {
                uint32_t vh[4], vl[4];
                uint32_t ro = (uint32_t)((kk * 16 + (lane & 15)) * AST
                                         + (nj * 16 + (lane >> 4) * 8) * 2);
                ldsm4t(vh, sb + AT_VH(vb) + ro);
                ldsm4t(vl, sb + AT_VL(vb) + ro);
                mma16816(o[2 * nj],     ph, vh[0], vh[1]);
                mma16816(o[2 * nj],     ph, vl[0], vl[1]);
                mma16816(o[2 * nj],     pl, vh[0], vh[1]);
                mma16816(o[2 * nj + 1], ph, vh[2], vh[3]);
                mma16816(o[2 * nj + 1], ph, vl[2], vl[3]);
                mma16816(o[2 * nj + 1], pl, vh[2], vh[3]);
            }
        }

        if (kt + 1 < KVTILES) CP_ASYNC_WAIT_ALL();
        __syncthreads();
    }

    // ---- epilogue ----
    const int b = bh >> 4, h = bh & 15;
    const float inv0 = 1.0f / l0, inv1 = 1.0f / l1;
    const size_t row0 = (size_t)(b * SEQ + qt * 256 + w * 16 + (lane >> 2));
#pragma unroll
    for (int on = 0; on < 8; on++) {
        const int colg = h * DK + on * 8 + (lane & 3) * 2;
        *(uint32_t*)(g_ahi + row0 * D_MODEL + colg) = pack_hi(o[on][0] * inv0, o[on][1] * inv0);
        *(uint32_t*)(g_alo + row0 * D_MODEL + colg) = pack_lo(o[on][0] * inv0, o[on][1] * inv0);
        *(uint32_t*)(g_ahi + (row0 + 8) * D_MODEL + colg) = pack_hi(o[on][2] * inv1, o[on][3] * inv1);
        *(uint32_t*)(g_alo + (row0 + 8) * D_MODEL + colg) = pack_lo(o[on][2] * inv1, o[on][3] * inv1);
    }
}

// ============================================================================
// launch
// ============================================================================
extern "C" void kernel_launch(void* const* d_in, const int* in_sizes, int n_in,
                              void* d_out, int out_size)
{
    const float* query  = (const float*)d_in[0];
    const float* key_in = (const float*)d_in[1];
    const float* value  = (const float*)d_in[2];
    const float* Wq = (const float*)d_in[3];
    const float* bq = (const float*)d_in[4];
    const float* Wk = (const float*)d_in[5];
    const float* bk = (const float*)d_in[6];
    const float* Wv = (const float*)d_in[7];
    const float* bv = (const float*)d_in[8];
    const float* Wo = (const float*)d_in[9];
    const float* bo = (const float*)d_in[10];
    float* out = (float*)d_out;

    __nv_bfloat16 *qhi, *qlo, *khi, *klo, *vhi, *vlo, *ahi, *alo, *whi, *wlo;
    cudaGetSymbolAddress((void**)&qhi, g_Qhi);
    cudaGetSymbolAddress((void**)&qlo, g_Qlo);
    cudaGetSymbolAddress((void**)&khi, g_Khi);
    cudaGetSymbolAddress((void**)&klo, g_Klo);
    cudaGetSymbolAddress((void**)&vhi, g_Vhi);
    cudaGetSymbolAddress((void**)&vlo, g_Vlo);
    cudaGetSymbolAddress((void**)&ahi, g_ahi);
    cudaGetSymbolAddress((void**)&alo, g_alo);
    cudaGetSymbolAddress((void**)&whi, g_whi);
    cudaGetSymbolAddress((void**)&wlo, g_wlo);

    cudaFuncSetAttribute(gemm_qkv, cudaFuncAttributeMaxDynamicSharedMemorySize, GEMM_SMEM);
    cudaFuncSetAttribute(gemm_out, cudaFuncAttributeMaxDynamicSharedMemorySize, GEMM_SMEM);
    cudaFuncSetAttribute(attn_tc, cudaFuncAttributeMaxDynamicSharedMemorySize, ATTN_SMEM);

    const int ACT4 = MROWS * D_MODEL / 4;
    const int W4   = D_MODEL * D_MODEL / 4;
    const size_t WSL = (size_t)D_MODEL * D_MODEL;

    conv_hilo4<<<dim3((W4 + 255) / 256, 4), 256>>>(Wq, Wk, Wv, Wo, whi, wlo, W4);
    conv_hilo4<<<dim3((ACT4 + 255) / 256, 3), 256>>>(query, key_in, value, value, ahi, alo, ACT4);

    // fused Q/K/V projections
    gemm_qkv<<<dim3(D_MODEL / 128, MROWS / 128, 3), 256, GEMM_SMEM>>>(
        ahi, alo, whi, wlo, bq, bk, bv, qhi, qlo, khi, klo, vhi, vlo);

    // attention (writes ctx hi/lo into activation slot 0)
    attn_tc<<<dim3(SEQ / 256, BATCH * NUM_HEADS), dim3(512), ATTN_SMEM>>>();

    // output projection
    gemm_out<<<dim3(D_MODEL / 128, MROWS / 128), 256, GEMM_SMEM>>>(
        ahi, alo, whi + 3 * WSL, wlo + 3 * WSL, bo, out);
}

// round 7
// speedup vs baseline: 3.5515x; 1.1903x over previous
#include <cuda_runtime.h>
#include <cuda_bf16.h>
#include <cuda_fp16.h>
#include <cstdint>

#define D_MODEL 1024
#define NUM_HEADS 16
#define DK 64
#define BATCH 4
#define SEQ 2048
#define MROWS (BATCH * SEQ)   /* 8192 */
#define KVTILES (SEQ / 128)   /* 16 */

// ---------------- scratch ----------------
// score path (bf16 hi/lo)
__device__ __nv_bfloat16 g_Qhi[BATCH * NUM_HEADS * SEQ * DK];
__device__ __nv_bfloat16 g_Qlo[BATCH * NUM_HEADS * SEQ * DK];
__device__ __nv_bfloat16 g_Khi[BATCH * NUM_HEADS * SEQ * DK];
__device__ __nv_bfloat16 g_Klo[BATCH * NUM_HEADS * SEQ * DK];
__device__ __nv_bfloat16 g_ahi[2 * MROWS * D_MODEL];   // query, key acts
__device__ __nv_bfloat16 g_alo[2 * MROWS * D_MODEL];
__device__ __nv_bfloat16 g_whi[2 * D_MODEL * D_MODEL]; // Wq, Wk
__device__ __nv_bfloat16 g_wlo[2 * D_MODEL * D_MODEL];
// value path (fp16)
__device__ __half g_V16h[BATCH * NUM_HEADS * SEQ * DK];
__device__ __half g_V16l[BATCH * NUM_HEADS * SEQ * DK];
__device__ __half g_ctx16[MROWS * D_MODEL];            // attn output (single fp16)
__device__ __half g_a16[MROWS * D_MODEL];              // value acts (single fp16)
__device__ __half g_w16h[2 * D_MODEL * D_MODEL];       // Wv, Wo hi
__device__ __half g_w16l[2 * D_MODEL * D_MODEL];       // Wv, Wo lo

// ---------------- helpers ----------------
__device__ __forceinline__ uint32_t smem_u32(const void* p) {
    uint32_t a;
    asm("{ .reg .u64 t; cvta.to.shared.u64 t, %1; cvt.u32.u64 %0, t; }" : "=r"(a) : "l"(p));
    return a;
}
#define CP_ASYNC16(saddr, gptr) \
    asm volatile("cp.async.cg.shared.global [%0], [%1], 16;" :: "r"((uint32_t)(saddr)), "l"(gptr))
#define CP_ASYNC_COMMIT()    asm volatile("cp.async.commit_group;" ::: "memory")
#define CP_ASYNC_WAIT_ALL()  asm volatile("cp.async.wait_group 0;" ::: "memory")

__device__ __forceinline__ void ldsm4(uint32_t r[4], uint32_t a) {
    asm volatile("ldmatrix.sync.aligned.m8n8.x4.shared.b16 {%0,%1,%2,%3}, [%4];"
        : "=r"(r[0]), "=r"(r[1]), "=r"(r[2]), "=r"(r[3]) : "r"(a));
}
__device__ __forceinline__ void ldsm4t(uint32_t r[4], uint32_t a) {
    asm volatile("ldmatrix.sync.aligned.m8n8.x4.trans.shared.b16 {%0,%1,%2,%3}, [%4];"
        : "=r"(r[0]), "=r"(r[1]), "=r"(r[2]), "=r"(r[3]) : "r"(a));
}
__device__ __forceinline__ void mma_bf16(float c[4], const uint32_t a[4], uint32_t b0, uint32_t b1) {
    asm volatile("mma.sync.aligned.m16n8k16.row.col.f32.bf16.bf16.f32 "
        "{%0,%1,%2,%3}, {%4,%5,%6,%7}, {%8,%9}, {%0,%1,%2,%3};"
        : "+f"(c[0]), "+f"(c[1]), "+f"(c[2]), "+f"(c[3])
        : "r"(a[0]), "r"(a[1]), "r"(a[2]), "r"(a[3]), "r"(b0), "r"(b1));
}
__device__ __forceinline__ void mma_f16(float c[4], const uint32_t a[4], uint32_t b0, uint32_t b1) {
    asm volatile("mma.sync.aligned.m16n8k16.row.col.f32.f16.f16.f32 "
        "{%0,%1,%2,%3}, {%4,%5,%6,%7}, {%8,%9}, {%0,%1,%2,%3};"
        : "+f"(c[0]), "+f"(c[1]), "+f"(c[2]), "+f"(c[3])
        : "r"(a[0]), "r"(a[1]), "r"(a[2]), "r"(a[3]), "r"(b0), "r"(b1));
}
__device__ __forceinline__ uint32_t pack_hi(float x, float y) {
    __nv_bfloat162 h = __floats2bfloat162_rn(x, y);
    return *(uint32_t*)&h;
}
__device__ __forceinline__ uint32_t pack_lo(float x, float y) {
    float xr = x - __bfloat162float(__float2bfloat16(x));
    float yr = y - __bfloat162float(__float2bfloat16(y));
    __nv_bfloat162 h = __floats2bfloat162_rn(xr, yr);
    return *(uint32_t*)&h;
}
__device__ __forceinline__ uint32_t pack_h16(float x, float y) {
    __half2 h = __floats2half2_rn(x, y);
    return *(uint32_t*)&h;
}
__device__ __forceinline__ uint32_t pack_l16(float x, float y) {
    float xr = x - __half2float(__float2half_rn(x));
    float yr = y - __half2float(__float2half_rn(y));
    __half2 h = __floats2half2_rn(xr, yr);
    return *(uint32_t*)&h;
}

// ============================================================================
// conversions
// ============================================================================
__global__ __launch_bounds__(256) void conv_bf2(
    const float* __restrict__ x0, const float* __restrict__ x1,
    __nv_bfloat16* __restrict__ hi, __nv_bfloat16* __restrict__ lo, int n4)
{
    int i = blockIdx.x * blockDim.x + threadIdx.x;
    if (i >= n4) return;
    const float* x = blockIdx.y ? x1 : x0;
    size_t o = (size_t)blockIdx.y * n4 + i;
    float4 v = ((const float4*)x)[i];
    uint2 H, L;
    H.x = pack_hi(v.x, v.y); H.y = pack_hi(v.z, v.w);
    L.x = pack_lo(v.x, v.y); L.y = pack_lo(v.z, v.w);
    ((uint2*)hi)[o] = H;
    ((uint2*)lo)[o] = L;
}
__global__ __launch_bounds__(256) void conv_f16w(
    const float* __restrict__ x0, const float* __restrict__ x1,
    __half* __restrict__ hi, __half* __restrict__ lo, int n4)
{
    int i = blockIdx.x * blockDim.x + threadIdx.x;
    if (i >= n4) return;
    const float* x = blockIdx.y ? x1 : x0;
    size_t o = (size_t)blockIdx.y * n4 + i;
    float4 v = ((const float4*)x)[i];
    uint2 H, L;
    H.x = pack_h16(v.x, v.y); H.y = pack_h16(v.z, v.w);
    L.x = pack_l16(v.x, v.y); L.y = pack_l16(v.z, v.w);
    ((uint2*)hi)[o] = H;
    ((uint2*)lo)[o] = L;
}
__global__ __launch_bounds__(256) void conv_f16a(
    const float* __restrict__ x, __half* __restrict__ h16, int n4)
{
    int i = blockIdx.x * blockDim.x + threadIdx.x;
    if (i >= n4) return;
    float4 v = ((const float4*)x)[i];
    uint2 H;
    H.x = pack_h16(v.x, v.y); H.y = pack_h16(v.z, v.w);
    ((uint2*)h16)[i] = H;
}

// ============================================================================
// bf16 3-term GEMM (score path): fused Q/K projection, split-head bf16 out
// ============================================================================
#define BK 32
#define GPAD 40
#define MAT_B (128 * GPAD * 2)
#define STG_B (4 * MAT_B)
#define NIT (D_MODEL / BK)
#define GEMM_SMEM (2 * STG_B)

__global__ __launch_bounds__(256, 2) void gemm_qk(
    const __nv_bfloat16* __restrict__ ahi_all, const __nv_bfloat16* __restrict__ alo_all,
    const __nv_bfloat16* __restrict__ whi_all, const __nv_bfloat16* __restrict__ wlo_all,
    const float* __restrict__ bq, const float* __restrict__ bk,
    __nv_bfloat16* __restrict__ qhi, __nv_bfloat16* __restrict__ qlo,
    __nv_bfloat16* __restrict__ khi, __nv_bfloat16* __restrict__ klo)
{
    extern __shared__ char smem[];
    const uint32_t sb = smem_u32(smem);
    const int t = threadIdx.x;
    const int lane = t & 31, wid = t >> 5;
    const int wm = wid >> 2, wn = wid & 3;
    const int m0 = blockIdx.y * 128, n0 = blockIdx.x * 128;
    const int z = blockIdx.z;

    const __nv_bfloat16* Ahi = ahi_all + (size_t)z * MROWS * D_MODEL;
    const __nv_bfloat16* Alo = alo_all + (size_t)z * MROWS * D_MODEL;
    const __nv_bfloat16* Whi = whi_all + (size_t)z * D_MODEL * D_MODEL;
    const __nv_bfloat16* Wlo = wlo_all + (size_t)z * D_MODEL * D_MODEL;
    const float* bias = z ? bk : bq;
    __nv_bfloat16* Chi = z ? khi : qhi;
    __nv_bfloat16* Clo = z ? klo : qlo;
    const float oscale = z ? 1.0f : 0.125f;

    float c[4][4][4];
#pragma unroll
    for (int i = 0; i < 4; i++)
#pragma unroll
        for (int j = 0; j < 4; j++)
#pragma unroll
            for (int k = 0; k < 4; k++) c[i][j][k] = 0.0f;

    auto load_stage = [&](int s, int it) {
        const int k0 = it * BK;
        const uint32_t st = sb + s * STG_B;
#pragma unroll
        for (int j = 0; j < 2; j++) {
            int idx = t + j * 256;
            int r = idx >> 2, cc = idx & 3;
            uint32_t so = (uint32_t)(r * (GPAD * 2) + cc * 16);
            CP_ASYNC16(st + 0 * MAT_B + so, Ahi + (size_t)(m0 + r) * D_MODEL + k0 + cc * 8);
            CP_ASYNC16(st + 1 * MAT_B + so, Alo + (size_t)(m0 + r) * D_MODEL + k0 + cc * 8);
            CP_ASYNC16(st + 2 * MAT_B + so, Whi + (size_t)(n0 + r) * D_MODEL + k0 + cc * 8);
            CP_ASYNC16(st + 3 * MAT_B + so, Wlo + (size_t)(n0 + r) * D_MODEL + k0 + cc * 8);
        }
    };

    load_stage(0, 0);
    CP_ASYNC_COMMIT();

    for (int it = 0; it < NIT; ++it) {
        const int s = it & 1;
        CP_ASYNC_WAIT_ALL();
        __syncthreads();
        if (it + 1 < NIT) {
            load_stage(s ^ 1, it + 1);
            CP_ASYNC_COMMIT();
        }
        const uint32_t st = sb + s * STG_B;
#pragma unroll
        for (int kk = 0; kk < 2; kk++) {
            uint32_t ah[4][4], al[4][4];
#pragma unroll
            for (int mi = 0; mi < 4; mi++) {
                uint32_t ro = (uint32_t)((wm * 64 + mi * 16 + (lane & 15)) * (GPAD * 2)
                                         + (kk * 16 + (lane >> 4) * 8) * 2);
                ldsm4(ah[mi], st + 0 * MAT_B + ro);
                ldsm4(al[mi], st + 1 * MAT_B + ro);
            }
            uint32_t bh_[2][4], bl_[2][4];
#pragma unroll
            for (int nj = 0; nj < 2; nj++) {
                uint32_t ro = (uint32_t)((wn * 32 + nj * 16 + (lane & 7) + ((lane >> 4) * 8)) * (GPAD * 2)
                                         + (kk * 16 + ((lane >> 3) & 1) * 8) * 2);
                ldsm4(bh_[nj], st + 2 * MAT_B + ro);
                ldsm4(bl_[nj], st + 3 * MAT_B + ro);
            }
#pragma unroll
            for (int mi = 0; mi < 4; mi++)
#pragma unroll
                for (int ni = 0; ni < 4; ni++) {
                    const int nj = ni >> 1, ss = (ni & 1) * 2;
                    mma_bf16(c[mi][ni], ah[mi], bh_[nj][ss], bh_[nj][ss + 1]);
                    mma_bf16(c[mi][ni], ah[mi], bl_[nj][ss], bl_[nj][ss + 1]);
                    mma_bf16(c[mi][ni], al[mi], bh_[nj][ss], bh_[nj][ss + 1]);
                }
        }
    }

#pragma unroll
    for (int mi = 0; mi < 4; mi++) {
        const int r0 = m0 + wm * 64 + mi * 16 + (lane >> 2);
#pragma unroll
        for (int ni = 0; ni < 4; ni++) {
            const int col = n0 + wn * 32 + ni * 8 + (lane & 3) * 2;
            const float b0 = bias[col], b1 = bias[col + 1];
            const int h = col >> 6, d = col & 63;
            float v00 = (c[mi][ni][0] + b0) * oscale, v01 = (c[mi][ni][1] + b1) * oscale;
            float v10 = (c[mi][ni][2] + b0) * oscale, v11 = (c[mi][ni][3] + b1) * oscale;
#pragma unroll
            for (int rr = 0; rr < 2; rr++) {
                const int m = r0 + rr * 8;
                const int b = m >> 11, sdx = m & 2047;
                const size_t off = (((size_t)(b * NUM_HEADS + h) * SEQ + sdx) * DK + d);
                const float x = rr ? v10 : v00, y = rr ? v11 : v01;
                *(uint32_t*)(Chi + off) = pack_hi(x, y);
                *(uint32_t*)(Clo + off) = pack_lo(x, y);
            }
        }
    }
}

// ============================================================================
// fp16 2-term GEMM (value path): A single fp16, W hi/lo fp16.
// split==1: V split-head fp16 hi/lo out. split==0: fp32 row-major out.
// ============================================================================
#define MAT16 (128 * GPAD * 2)
#define STG16 (3 * MAT16)
#define GEMM16_SMEM (2 * STG16)

__global__ __launch_bounds__(256, 2) void gemm_f16(
    const __half* __restrict__ A,
    const __half* __restrict__ Wh, const __half* __restrict__ Wl,
    const float* __restrict__ bias,
    float* __restrict__ Cf,
    __half* __restrict__ Chi, __half* __restrict__ Clo, int split)
{
    extern __shared__ char smem[];
    const uint32_t sb = smem_u32(smem);
    const int t = threadIdx.x;
    const int lane = t & 31, wid = t >> 5;
    const int wm = wid >> 2, wn = wid & 3;
    const int m0 = blockIdx.y * 128, n0 = blockIdx.x * 128;

    float c[4][4][4];
#pragma unroll
    for (int i = 0; i < 4; i++)
#pragma unroll
        for (int j = 0; j < 4; j++)
#pragma unroll
            for (int k = 0; k < 4; k++) c[i][j][k] = 0.0f;

    auto load_stage = [&](int s, int it) {
        const int k0 = it * BK;
        const uint32_t st = sb + s * STG16;
#pragma unroll
        for (int j = 0; j < 2; j++) {
            int idx = t + j * 256;
            int r = idx >> 2, cc = idx & 3;
            uint32_t so = (uint32_t)(r * (GPAD * 2) + cc * 16);
            CP_ASYNC16(st + 0 * MAT16 + so, A  + (size_t)(m0 + r) * D_MODEL + k0 + cc * 8);
            CP_ASYNC16(st + 1 * MAT16 + so, Wh + (size_t)(n0 + r) * D_MODEL + k0 + cc * 8);
            CP_ASYNC16(st + 2 * MAT16 + so, Wl + (size_t)(n0 + r) * D_MODEL + k0 + cc * 8);
        }
    };

    load_stage(0, 0);
    CP_ASYNC_COMMIT();

    for (int it = 0; it < NIT; ++it) {
        const int s = it & 1;
        CP_ASYNC_WAIT_ALL();
        __syncthreads();
        if (it + 1 < NIT) {
            load_stage(s ^ 1, it + 1);
            CP_ASYNC_COMMIT();
        }
        const uint32_t st = sb + s * STG16;
#pragma unroll
        for (int kk = 0; kk < 2; kk++) {
            uint32_t ah[4][4];
#pragma unroll
            for (int mi = 0; mi < 4; mi++) {
                uint32_t ro = (uint32_t)((wm * 64 + mi * 16 + (lane & 15)) * (GPAD * 2)
                                         + (kk * 16 + (lane >> 4) * 8) * 2);
                ldsm4(ah[mi], st + 0 * MAT16 + ro);
            }
            uint32_t bh_[2][4], bl_[2][4];
#pragma unroll
            for (int nj = 0; nj < 2; nj++) {
                uint32_t ro = (uint32_t)((wn * 32 + nj * 16 + (lane & 7) + ((lane >> 4) * 8)) * (GPAD * 2)
                                         + (kk * 16 + ((lane >> 3) & 1) * 8) * 2);
                ldsm4(bh_[nj], st + 1 * MAT16 + ro);
                ldsm4(bl_[nj], st + 2 * MAT16 + ro);
            }
#pragma unroll
            for (int mi = 0; mi < 4; mi++)
#pragma unroll
                for (int ni = 0; ni < 4; ni++) {
                    const int nj = ni >> 1, ss = (ni & 1) * 2;
                    mma_f16(c[mi][ni], ah[mi], bh_[nj][ss], bh_[nj][ss + 1]);
                    mma_f16(c[mi][ni], ah[mi], bl_[nj][ss], bl_[nj][ss + 1]);
                }
        }
    }

#pragma unroll
    for (int mi = 0; mi < 4; mi++) {
        const int r0 = m0 + wm * 64 + mi * 16 + (lane >> 2);
#pragma unroll
        for (int ni = 0; ni < 4; ni++) {
            const int col = n0 + wn * 32 + ni * 8 + (lane & 3) * 2;
            const float b0 = bias[col], b1 = bias[col + 1];
            float v00 = c[mi][ni][0] + b0, v01 = c[mi][ni][1] + b1;
            float v10 = c[mi][ni][2] + b0, v11 = c[mi][ni][3] + b1;
            if (!split) {
                *(float2*)(Cf + (size_t)r0 * D_MODEL + col) = make_float2(v00, v01);
                *(float2*)(Cf + (size_t)(r0 + 8) * D_MODEL + col) = make_float2(v10, v11);
            } else {
                const int h = col >> 6, d = col & 63;
#pragma unroll
                for (int rr = 0; rr < 2; rr++) {
                    const int m = r0 + rr * 8;
                    const int b = m >> 11, sdx = m & 2047;
                    const size_t off = (((size_t)(b * NUM_HEADS + h) * SEQ + sdx) * DK + d);
                    const float x = rr ? v10 : v00, y = rr ? v11 : v01;
                    *(uint32_t*)(Chi + off) = pack_h16(x, y);
                    *(uint32_t*)(Clo + off) = pack_l16(x, y);
                }
            }
        }
    }
}

// ============================================================================
// FA2 attention: QK bf16 3-term, PV fp16 (P single, V hi/lo) 2-term.
// 512 threads, CTA = 256 q-rows, ctx out = single fp16.
// ============================================================================
#define AST 144
#define AT_QH 0
#define AT_QL (AT_QH + 256 * AST)
#define AT_KB (AT_QL + 256 * AST)
#define AT_KH(b) (AT_KB + (b) * (2 * 128 * AST))
#define AT_KL(b) (AT_KH(b) + 128 * AST)
#define AT_VB (AT_KB + 2 * (2 * 128 * AST))
#define AT_VH(b) (AT_VB + (b) * (2 * 128 * AST))
#define AT_VL(b) (AT_VH(b) + 128 * AST)
#define ATTN_SMEM (AT_VB + 2 * (2 * 128 * AST))   /* 221184 B */

__global__ __launch_bounds__(512) void attn_tc()
{
    extern __shared__ char smem[];
    const uint32_t sb = smem_u32(smem);
    const int t = threadIdx.x;
    const int lane = t & 31, w = t >> 5;
    const int qt = blockIdx.x, bh = blockIdx.y;

    const __nv_bfloat16* Qh = g_Qhi + ((size_t)bh * SEQ + qt * 256) * DK;
    const __nv_bfloat16* Ql = g_Qlo + ((size_t)bh * SEQ + qt * 256) * DK;
    const __nv_bfloat16* Kh = g_Khi + (size_t)bh * SEQ * DK;
    const __nv_bfloat16* Kl = g_Klo + (size_t)bh * SEQ * DK;
    const __half* Vh = g_V16h + (size_t)bh * SEQ * DK;
    const __half* Vl = g_V16l + (size_t)bh * SEQ * DK;

    auto ldtile = [&](uint32_t dstoff, const void* src_v) {   // 128x64 x16bit
        const char* src = (const char*)src_v;
#pragma unroll
        for (int j = 0; j < 2; j++) {
            int idx = t + j * 512;
            int r = idx >> 3, cc = idx & 7;
            CP_ASYNC16(sb + dstoff + r * AST + cc * 16, src + (r * DK + cc * 8) * 2);
        }
    };
    auto ldtileQ = [&](uint32_t dstoff, const __nv_bfloat16* src) {  // 256x64
#pragma unroll
        for (int j = 0; j < 4; j++) {
            int idx = t + j * 512;
            int r = idx >> 3, cc = idx & 7;
            CP_ASYNC16(sb + dstoff + r * AST + cc * 16, src + r * DK + cc * 8);
        }
    };

    ldtileQ(AT_QH, Qh); ldtileQ(AT_QL, Ql);
    ldtile(AT_KH(0), Kh); ldtile(AT_KL(0), Kl);
    ldtile(AT_VH(0), Vh); ldtile(AT_VL(0), Vl);
    CP_ASYNC_COMMIT();
    CP_ASYNC_WAIT_ALL();
    __syncthreads();

    float o[8][4];
#pragma unroll
    for (int i = 0; i < 8; i++)
#pragma unroll
        for (int k = 0; k < 4; k++) o[i][k] = 0.0f;
    float m0 = -1e30f, m1 = -1e30f, l0 = 0.0f, l1 = 0.0f;

    for (int kt = 0; kt < KVTILES; kt++) {
        const int vb = kt & 1;

        if (kt + 1 < KVTILES) {
            ldtile(AT_KH(vb ^ 1), Kh + (size_t)(kt + 1) * 128 * DK);
            ldtile(AT_KL(vb ^ 1), Kl + (size_t)(kt + 1) * 128 * DK);
            ldtile(AT_VH(vb ^ 1), Vh + (size_t)(kt + 1) * 128 * DK);
            ldtile(AT_VL(vb ^ 1), Vl + (size_t)(kt + 1) * 128 * DK);
            CP_ASYNC_COMMIT();
        }

        // ---- S = Q K^T (bf16 3-term) ----
        float c[16][4];
#pragma unroll
        for (int i = 0; i < 16; i++)
#pragma unroll
            for (int k = 0; k < 4; k++) c[i][k] = 0.0f;

#pragma unroll
        for (int kk = 0; kk < 4; kk++) {
            uint32_t qh[4], ql[4];
            {
                uint32_t ro = (uint32_t)((w * 16 + (lane & 15)) * AST
                                         + (kk * 16 + (lane >> 4) * 8) * 2);
                ldsm4(qh, sb + AT_QH + ro);
                ldsm4(ql, sb + AT_QL + ro);
            }
#pragma unroll
            for (int nj = 0; nj < 8; nj++) {
                uint32_t bh_[4], bl_[4];
                uint32_t ro = (uint32_t)((nj * 16 + (lane & 7) + ((lane >> 4) * 8)) * AST
                                         + (kk * 16 + ((lane >> 3) & 1) * 8) * 2);
                ldsm4(bh_, sb + AT_KH(vb) + ro);
                ldsm4(bl_, sb + AT_KL(vb) + ro);
                mma_bf16(c[2 * nj],     qh, bh_[0], bh_[1]);
                mma_bf16(c[2 * nj],     qh, bl_[0], bl_[1]);
                mma_bf16(c[2 * nj],     ql, bh_[0], bh_[1]);
                mma_bf16(c[2 * nj + 1], qh, bh_[2], bh_[3]);
                mma_bf16(c[2 * nj + 1], qh, bl_[2], bl_[3]);
                mma_bf16(c[2 * nj + 1], ql, bh_[2], bh_[3]);
            }
        }

        // ---- warp-local online softmax ----
        float mx0 = -1e30f, mx1 = -1e30f;
#pragma unroll
        for (int ni = 0; ni < 16; ni++) {
            mx0 = fmaxf(mx0, fmaxf(c[ni][0], c[ni][1]));
            mx1 = fmaxf(mx1, fmaxf(c[ni][2], c[ni][3]));
        }
        mx0 = fmaxf(mx0, __shfl_xor_sync(0xffffffffu, mx0, 1));
        mx0 = fmaxf(mx0, __shfl_xor_sync(0xffffffffu, mx0, 2));
        mx1 = fmaxf(mx1, __shfl_xor_sync(0xffffffffu, mx1, 1));
        mx1 = fmaxf(mx1, __shfl_xor_sync(0xffffffffu, mx1, 2));

        const float nm0 = fmaxf(m0, mx0), nm1 = fmaxf(m1, mx1);
        const float alpha0 = __expf(m0 - nm0), alpha1 = __expf(m1 - nm1);
        m0 = nm0; m1 = nm1;

        float s0 = 0.0f, s1 = 0.0f;
#pragma unroll
        for (int ni = 0; ni < 16; ni++) {
            c[ni][0] = __expf(c[ni][0] - nm0);
            c[ni][1] = __expf(c[ni][1] - nm0);
            c[ni][2] = __expf(c[ni][2] - nm1);
            c[ni][3] = __expf(c[ni][3] - nm1);
            s0 += c[ni][0] + c[ni][1];
            s1 += c[ni][2] + c[ni][3];
        }
        s0 += __shfl_xor_sync(0xffffffffu, s0, 1);
        s0 += __shfl_xor_sync(0xffffffffu, s0, 2);
        s1 += __shfl_xor_sync(0xffffffffu, s1, 1);
        s1 += __shfl_xor_sync(0xffffffffu, s1, 2);
        l0 = l0 * alpha0 + s0;
        l1 = l1 * alpha1 + s1;

#pragma unroll
        for (int i = 0; i < 8; i++) {
            o[i][0] *= alpha0; o[i][1] *= alpha0;
            o[i][2] *= alpha1; o[i][3] *= alpha1;
        }

        // ---- O += P V : P single fp16 from C-frags, V fp16 hi/lo ----
#pragma unroll
        for (int kk = 0; kk < 8; kk++) {
            uint32_t ph[4];
            ph[0] = pack_h16(c[2 * kk][0], c[2 * kk][1]);
            ph[1] = pack_h16(c[2 * kk][2], c[2 * kk][3]);
            ph[2] = pack_h16(c[2 * kk + 1][0], c[2 * kk + 1][1]);
            ph[3] = pack_h16(c[2 * kk + 1][2], c[2 * kk + 1][3]);
#pragma unroll
            for (int nj = 0; nj < 4; nj++) {
                uint32_t vh[4], vl[4];
                uint32_t ro = (uint32_t)((kk * 16 + (lane & 15)) * AST
                                         + (nj * 16 + (lane >> 4) * 8) * 2);
                ldsm4t(vh, sb + AT_VH(vb) + ro);
                ldsm4t(vl, sb + AT_VL(vb) + ro);
                mma_f16(o[2 * nj],     ph, vh[0], vh[1]);
                mma_f16(o[2 * nj],     ph, vl[0], vl[1]);
                mma_f16(o[2 * nj + 1], ph, vh[2], vh[3]);
                mma_f16(o[2 * nj + 1], ph, vl[2], vl[3]);
            }
        }

        if (kt + 1 < KVTILES) CP_ASYNC_WAIT_ALL();
        __syncthreads();
    }

    // ---- epilogue: normalize, emit single fp16 ctx [B,S,1024] ----
    const int b = bh >> 4, h = bh & 15;
    const float inv0 = 1.0f / l0, inv1 = 1.0f / l1;
    const size_t row0 = (size_t)(b * SEQ + qt * 256 + w * 16 + (lane >> 2));
#pragma unroll
    for (int on = 0; on < 8; on++) {
        const int colg = h * DK + on * 8 + (lane & 3) * 2;
        *(uint32_t*)(g_ctx16 + row0 * D_MODEL + colg) = pack_h16(o[on][0] * inv0, o[on][1] * inv0);
        *(uint32_t*)(g_ctx16 + (row0 + 8) * D_MODEL + colg) = pack_h16(o[on][2] * inv1, o[on][3] * inv1);
    }
}

// ============================================================================
// launch
// ============================================================================
extern "C" void kernel_launch(void* const* d_in, const int* in_sizes, int n_in,
                              void* d_out, int out_size)
{
    const float* query  = (const float*)d_in[0];
    const float* key_in = (const float*)d_in[1];
    const float* value  = (const float*)d_in[2];
    const float* Wq = (const float*)d_in[3];
    const float* bq = (const float*)d_in[4];
    const float* Wk = (const float*)d_in[5];
    const float* bk = (const float*)d_in[6];
    const float* Wv = (const float*)d_in[7];
    const float* bv = (const float*)d_in[8];
    const float* Wo = (const float*)d_in[9];
    const float* bo = (const float*)d_in[10];
    float* out = (float*)d_out;

    __nv_bfloat16 *qhi, *qlo, *khi, *klo, *ahi, *alo, *whi, *wlo;
    __half *v16h, *v16l, *ctx16, *a16, *w16h, *w16l;
    cudaGetSymbolAddress((void**)&qhi, g_Qhi);
    cudaGetSymbolAddress((void**)&qlo, g_Qlo);
    cudaGetSymbolAddress((void**)&khi, g_Khi);
    cudaGetSymbolAddress((void**)&klo, g_Klo);
    cudaGetSymbolAddress((void**)&ahi, g_ahi);
    cudaGetSymbolAddress((void**)&alo, g_alo);
    cudaGetSymbolAddress((void**)&whi, g_whi);
    cudaGetSymbolAddress((void**)&wlo, g_wlo);
    cudaGetSymbolAddress((void**)&v16h, g_V16h);
    cudaGetSymbolAddress((void**)&v16l, g_V16l);
    cudaGetSymbolAddress((void**)&ctx16, g_ctx16);
    cudaGetSymbolAddress((void**)&a16, g_a16);
    cudaGetSymbolAddress((void**)&w16h, g_w16h);
    cudaGetSymbolAddress((void**)&w16l, g_w16l);

    cudaFuncSetAttribute(gemm_qk, cudaFuncAttributeMaxDynamicSharedMemorySize, GEMM_SMEM);
    cudaFuncSetAttribute(gemm_f16, cudaFuncAttributeMaxDynamicSharedMemorySize, GEMM16_SMEM);
    cudaFuncSetAttribute(attn_tc, cudaFuncAttributeMaxDynamicSharedMemorySize, ATTN_SMEM);

    const int ACT4 = MROWS * D_MODEL / 4;
    const int W4   = D_MODEL * D_MODEL / 4;
    const size_t WSL = (size_t)D_MODEL * D_MODEL;

    // conversions
    conv_bf2<<<dim3((W4 + 255) / 256, 2), 256>>>(Wq, Wk, whi, wlo, W4);
    conv_bf2<<<dim3((ACT4 + 255) / 256, 2), 256>>>(query, key_in, ahi, alo, ACT4);
    conv_f16w<<<dim3((W4 + 255) / 256, 2), 256>>>(Wv, Wo, w16h, w16l, W4);
    conv_f16a<<<dim3((ACT4 + 255) / 256), 256>>>(value, a16, ACT4);

    // Q/K projections (bf16 3-term, fused)
    gemm_qk<<<dim3(D_MODEL / 128, MROWS / 128, 2), 256, GEMM_SMEM>>>(
        ahi, alo, whi, wlo, bq, bk, qhi, qlo, khi, klo);

    // V projection (fp16 2-term, split-head fp16 hi/lo out)
    gemm_f16<<<dim3(D_MODEL / 128, MROWS / 128), 256, GEMM16_SMEM>>>(
        a16, w16h, w16l, bv, nullptr, v16h, v16l, 1);

    // attention
    attn_tc<<<dim3(SEQ / 256, BATCH * NUM_HEADS), dim3(512), ATTN_SMEM>>>();

    // output projection (fp16 2-term, fp32 out)
    gemm_f16<<<dim3(D_MODEL / 128, MROWS / 128), 256, GEMM16_SMEM>>>(
        ctx16, w16h + WSL, w16l + WSL, bo, out, nullptr, nullptr, 0);
}

// round 8
// speedup vs baseline: 4.2936x; 1.2089x over previous
#include <cuda_runtime.h>
#include <cuda_fp16.h>
#include <cstdint>

#define D_MODEL 1024
#define NUM_HEADS 16
#define DK 64
#define BATCH 4
#define SEQ 2048
#define MROWS (BATCH * SEQ)   /* 8192 */
#define KVTILES (SEQ / 128)   /* 16 */

// ---------------- scratch (all fp16) ----------------
__device__ __half g_Q16 [BATCH * NUM_HEADS * SEQ * DK];   // single (A of QK^T)
__device__ __half g_K16h[BATCH * NUM_HEADS * SEQ * DK];
__device__ __half g_K16l[BATCH * NUM_HEADS * SEQ * DK];
__device__ __half g_V16h[BATCH * NUM_HEADS * SEQ * DK];
__device__ __half g_V16l[BATCH * NUM_HEADS * SEQ * DK];
__device__ __half g_ctx16[MROWS * D_MODEL];               // attn out (single)
__device__ __half g_a16[3 * MROWS * D_MODEL];             // query,key,value acts
__device__ __half g_w16h[4 * D_MODEL * D_MODEL];          // Wq,Wk,Wv,Wo hi
__device__ __half g_w16l[4 * D_MODEL * D_MODEL];          // Wq,Wk,Wv,Wo lo

// ---------------- helpers ----------------
__device__ __forceinline__ uint32_t smem_u32(const void* p) {
    uint32_t a;
    asm("{ .reg .u64 t; cvta.to.shared.u64 t, %1; cvt.u32.u64 %0, t; }" : "=r"(a) : "l"(p));
    return a;
}
#define CP_ASYNC16(saddr, gptr) \
    asm volatile("cp.async.cg.shared.global [%0], [%1], 16;" :: "r"((uint32_t)(saddr)), "l"(gptr))
#define CP_ASYNC_COMMIT()    asm volatile("cp.async.commit_group;" ::: "memory")
#define CP_ASYNC_WAIT_ALL()  asm volatile("cp.async.wait_group 0;" ::: "memory")

__device__ __forceinline__ void ldsm4(uint32_t r[4], uint32_t a) {
    asm volatile("ldmatrix.sync.aligned.m8n8.x4.shared.b16 {%0,%1,%2,%3}, [%4];"
        : "=r"(r[0]), "=r"(r[1]), "=r"(r[2]), "=r"(r[3]) : "r"(a));
}
__device__ __forceinline__ void ldsm4t(uint32_t r[4], uint32_t a) {
    asm volatile("ldmatrix.sync.aligned.m8n8.x4.trans.shared.b16 {%0,%1,%2,%3}, [%4];"
        : "=r"(r[0]), "=r"(r[1]), "=r"(r[2]), "=r"(r[3]) : "r"(a));
}
__device__ __forceinline__ void mma_f16(float c[4], const uint32_t a[4], uint32_t b0, uint32_t b1) {
    asm volatile("mma.sync.aligned.m16n8k16.row.col.f32.f16.f16.f32 "
        "{%0,%1,%2,%3}, {%4,%5,%6,%7}, {%8,%9}, {%0,%1,%2,%3};"
        : "+f"(c[0]), "+f"(c[1]), "+f"(c[2]), "+f"(c[3])
        : "r"(a[0]), "r"(a[1]), "r"(a[2]), "r"(a[3]), "r"(b0), "r"(b1));
}
__device__ __forceinline__ uint32_t pack_h16(float x, float y) {
    __half2 h = __floats2half2_rn(x, y);
    return *(uint32_t*)&h;
}
__device__ __forceinline__ uint32_t pack_l16(float x, float y) {
    float xr = x - __half2float(__float2half_rn(x));
    float yr = y - __half2float(__float2half_rn(y));
    __half2 h = __floats2half2_rn(xr, yr);
    return *(uint32_t*)&h;
}

// ============================================================================
// conversions
// ============================================================================
__global__ __launch_bounds__(256) void conv_w4(
    const float* __restrict__ x0, const float* __restrict__ x1,
    const float* __restrict__ x2, const float* __restrict__ x3,
    __half* __restrict__ hi, __half* __restrict__ lo, int n4)
{
    int i = blockIdx.x * blockDim.x + threadIdx.x;
    if (i >= n4) return;
    const float* x = (blockIdx.y == 0) ? x0 : (blockIdx.y == 1) ? x1
                   : (blockIdx.y == 2) ? x2 : x3;
    size_t o = (size_t)blockIdx.y * n4 + i;
    float4 v = ((const float4*)x)[i];
    uint2 H, L;
    H.x = pack_h16(v.x, v.y); H.y = pack_h16(v.z, v.w);
    L.x = pack_l16(v.x, v.y); L.y = pack_l16(v.z, v.w);
    ((uint2*)hi)[o] = H;
    ((uint2*)lo)[o] = L;
}
__global__ __launch_bounds__(256) void conv_a3(
    const float* __restrict__ x0, const float* __restrict__ x1,
    const float* __restrict__ x2, __half* __restrict__ h16, int n4)
{
    int i = blockIdx.x * blockDim.x + threadIdx.x;
    if (i >= n4) return;
    const float* x = (blockIdx.y == 0) ? x0 : (blockIdx.y == 1) ? x1 : x2;
    size_t o = (size_t)blockIdx.y * n4 + i;
    float4 v = ((const float4*)x)[i];
    uint2 H;
    H.x = pack_h16(v.x, v.y); H.y = pack_h16(v.z, v.w);
    ((uint2*)h16)[o] = H;
}

// ============================================================================
// fp16 2-term GEMM mainloop: A single fp16, W fp16 hi/lo. BM=BN=128, BK=32.
// ============================================================================
#define BK 32
#define GPAD 40
#define MAT16 (128 * GPAD * 2)
#define STG16 (3 * MAT16)
#define NIT (D_MODEL / BK)
#define GEMM16_SMEM (2 * STG16)

__device__ __forceinline__ void gemm16_main(
    uint32_t sb, int t,
    const __half* __restrict__ A,
    const __half* __restrict__ Wh, const __half* __restrict__ Wl,
    int m0, int n0, float c[4][4][4])
{
    const int lane = t & 31, wid = t >> 5;
    const int wm = wid >> 2, wn = wid & 3;

    auto load_stage = [&](int s, int it) {
        const int k0 = it * BK;
        const uint32_t st = sb + s * STG16;
#pragma unroll
        for (int j = 0; j < 2; j++) {
            int idx = t + j * 256;
            int r = idx >> 2, cc = idx & 3;
            uint32_t so = (uint32_t)(r * (GPAD * 2) + cc * 16);
            CP_ASYNC16(st + 0 * MAT16 + so, A  + (size_t)(m0 + r) * D_MODEL + k0 + cc * 8);
            CP_ASYNC16(st + 1 * MAT16 + so, Wh + (size_t)(n0 + r) * D_MODEL + k0 + cc * 8);
            CP_ASYNC16(st + 2 * MAT16 + so, Wl + (size_t)(n0 + r) * D_MODEL + k0 + cc * 8);
        }
    };

    load_stage(0, 0);
    CP_ASYNC_COMMIT();

    for (int it = 0; it < NIT; ++it) {
        const int s = it & 1;
        CP_ASYNC_WAIT_ALL();
        __syncthreads();
        if (it + 1 < NIT) {
            load_stage(s ^ 1, it + 1);
            CP_ASYNC_COMMIT();
        }
        const uint32_t st = sb + s * STG16;
#pragma unroll
        for (int kk = 0; kk < 2; kk++) {
            uint32_t ah[4][4];
#pragma unroll
            for (int mi = 0; mi < 4; mi++) {
                uint32_t ro = (uint32_t)((wm * 64 + mi * 16 + (lane & 15)) * (GPAD * 2)
                                         + (kk * 16 + (lane >> 4) * 8) * 2);
                ldsm4(ah[mi], st + 0 * MAT16 + ro);
            }
            uint32_t bh_[2][4], bl_[2][4];
#pragma unroll
            for (int nj = 0; nj < 2; nj++) {
                uint32_t ro = (uint32_t)((wn * 32 + nj * 16 + (lane & 7) + ((lane >> 4) * 8)) * (GPAD * 2)
                                         + (kk * 16 + ((lane >> 3) & 1) * 8) * 2);
                ldsm4(bh_[nj], st + 1 * MAT16 + ro);
                ldsm4(bl_[nj], st + 2 * MAT16 + ro);
            }
#pragma unroll
            for (int mi = 0; mi < 4; mi++)
#pragma unroll
                for (int ni = 0; ni < 4; ni++) {
                    const int nj = ni >> 1, ss = (ni & 1) * 2;
                    mma_f16(c[mi][ni], ah[mi], bh_[nj][ss], bh_[nj][ss + 1]);
                    mma_f16(c[mi][ni], ah[mi], bl_[nj][ss], bl_[nj][ss + 1]);
                }
        }
    }
}

// ---- fused Q/K/V projections: z selects act slot, weight slot, epilogue ----
__global__ __launch_bounds__(256, 2) void gemm_qkv16(
    const __half* __restrict__ a16, const __half* __restrict__ w16h,
    const __half* __restrict__ w16l,
    const float* __restrict__ bq, const float* __restrict__ bk,
    const float* __restrict__ bv,
    __half* __restrict__ q16,
    __half* __restrict__ k16h, __half* __restrict__ k16l,
    __half* __restrict__ v16h, __half* __restrict__ v16l)
{
    extern __shared__ char smem[];
    const uint32_t sb = smem_u32(smem);
    const int t = threadIdx.x;
    const int lane = t & 31, wid = t >> 5;
    const int wm = wid >> 2, wn = wid & 3;
    const int m0 = blockIdx.y * 128, n0 = blockIdx.x * 128;
    const int z = blockIdx.z;

    const __half* A  = a16  + (size_t)z * MROWS * D_MODEL;
    const __half* Wh = w16h + (size_t)z * D_MODEL * D_MODEL;
    const __half* Wl = w16l + (size_t)z * D_MODEL * D_MODEL;
    const float* bias = (z == 0) ? bq : (z == 1) ? bk : bv;
    const float oscale = (z == 0) ? 0.125f : 1.0f;

    float c[4][4][4];
#pragma unroll
    for (int i = 0; i < 4; i++)
#pragma unroll
        for (int j = 0; j < 4; j++)
#pragma unroll
            for (int k = 0; k < 4; k++) c[i][j][k] = 0.0f;

    gemm16_main(sb, t, A, Wh, Wl, m0, n0, c);

#pragma unroll
    for (int mi = 0; mi < 4; mi++) {
        const int r0 = m0 + wm * 64 + mi * 16 + (lane >> 2);
#pragma unroll
        for (int ni = 0; ni < 4; ni++) {
            const int col = n0 + wn * 32 + ni * 8 + (lane & 3) * 2;
            const float b0 = bias[col], b1 = bias[col + 1];
            const int h = col >> 6, d = col & 63;
            float v00 = (c[mi][ni][0] + b0) * oscale, v01 = (c[mi][ni][1] + b1) * oscale;
            float v10 = (c[mi][ni][2] + b0) * oscale, v11 = (c[mi][ni][3] + b1) * oscale;
#pragma unroll
            for (int rr = 0; rr < 2; rr++) {
                const int m = r0 + rr * 8;
                const int b = m >> 11, sdx = m & 2047;
                const size_t off = (((size_t)(b * NUM_HEADS + h) * SEQ + sdx) * DK + d);
                const float x = rr ? v10 : v00, y = rr ? v11 : v01;
                if (z == 0) {
                    *(uint32_t*)(q16 + off) = pack_h16(x, y);
                } else {
                    __half* Chi = (z == 1) ? k16h : v16h;
                    __half* Clo = (z == 1) ? k16l : v16l;
                    *(uint32_t*)(Chi + off) = pack_h16(x, y);
                    *(uint32_t*)(Clo + off) = pack_l16(x, y);
                }
            }
        }
    }
}

// ---- output projection: ctx16 @ Wo^T + bo -> fp32 ----
__global__ __launch_bounds__(256, 2) void gemm_out16(
    const __half* __restrict__ A,
    const __half* __restrict__ Wh, const __half* __restrict__ Wl,
    const float* __restrict__ bias, float* __restrict__ Cf)
{
    extern __shared__ char smem[];
    const uint32_t sb = smem_u32(smem);
    const int t = threadIdx.x;
    const int lane = t & 31, wid = t >> 5;
    const int wm = wid >> 2, wn = wid & 3;
    const int m0 = blockIdx.y * 128, n0 = blockIdx.x * 128;

    float c[4][4][4];
#pragma unroll
    for (int i = 0; i < 4; i++)
#pragma unroll
        for (int j = 0; j < 4; j++)
#pragma unroll
            for (int k = 0; k < 4; k++) c[i][j][k] = 0.0f;

    gemm16_main(sb, t, A, Wh, Wl, m0, n0, c);

#pragma unroll
    for (int mi = 0; mi < 4; mi++) {
        const int r0 = m0 + wm * 64 + mi * 16 + (lane >> 2);
#pragma unroll
        for (int ni = 0; ni < 4; ni++) {
            const int col = n0 + wn * 32 + ni * 8 + (lane & 3) * 2;
            const float b0 = bias[col], b1 = bias[col + 1];
            *(float2*)(Cf + (size_t)r0 * D_MODEL + col) =
                make_float2(c[mi][ni][0] + b0, c[mi][ni][1] + b1);
            *(float2*)(Cf + (size_t)(r0 + 8) * D_MODEL + col) =
                make_float2(c[mi][ni][2] + b0, c[mi][ni][3] + b1);
        }
    }
}

// ============================================================================
// FA2 attention, all fp16 2-term: Q single, K hi/lo; P single, V hi/lo.
// 512 threads, CTA = 256 q-rows, 1 sync/kv-iter, K/V double-buffered.
// ============================================================================
#define AST 144
#define AT_Q  0
#define AT_KB (AT_Q + 256 * AST)                  /* 36864 */
#define AT_KH(b) (AT_KB + (b) * (2 * 128 * AST))
#define AT_KL(b) (AT_KH(b) + 128 * AST)
#define AT_VB (AT_KB + 2 * (2 * 128 * AST))       /* 110592 */
#define AT_VH(b) (AT_VB + (b) * (2 * 128 * AST))
#define AT_VL(b) (AT_VH(b) + 128 * AST)
#define ATTN_SMEM (AT_VB + 2 * (2 * 128 * AST))   /* 184320 B */

__global__ __launch_bounds__(512) void attn_tc()
{
    extern __shared__ char smem[];
    const uint32_t sb = smem_u32(smem);
    const int t = threadIdx.x;
    const int lane = t & 31, w = t >> 5;
    const int qt = blockIdx.x, bh = blockIdx.y;

    const __half* Qs = g_Q16  + ((size_t)bh * SEQ + qt * 256) * DK;
    const __half* Kh = g_K16h + (size_t)bh * SEQ * DK;
    const __half* Kl = g_K16l + (size_t)bh * SEQ * DK;
    const __half* Vh = g_V16h + (size_t)bh * SEQ * DK;
    const __half* Vl = g_V16l + (size_t)bh * SEQ * DK;

    auto ldtile = [&](uint32_t dstoff, const __half* src) {   // 128x64 fp16
#pragma unroll
        for (int j = 0; j < 2; j++) {
            int idx = t + j * 512;
            int r = idx >> 3, cc = idx & 7;
            CP_ASYNC16(sb + dstoff + r * AST + cc * 16, src + r * DK + cc * 8);
        }
    };
    auto ldtileQ = [&](uint32_t dstoff, const __half* src) {  // 256x64 fp16
#pragma unroll
        for (int j = 0; j < 4; j++) {
            int idx = t + j * 512;
            int r = idx >> 3, cc = idx & 7;
            CP_ASYNC16(sb + dstoff + r * AST + cc * 16, src + r * DK + cc * 8);
        }
    };

    ldtileQ(AT_Q, Qs);
    ldtile(AT_KH(0), Kh); ldtile(AT_KL(0), Kl);
    ldtile(AT_VH(0), Vh); ldtile(AT_VL(0), Vl);
    CP_ASYNC_COMMIT();
    CP_ASYNC_WAIT_ALL();
    __syncthreads();

    float o[8][4];
#pragma unroll
    for (int i = 0; i < 8; i++)
#pragma unroll
        for (int k = 0; k < 4; k++) o[i][k] = 0.0f;
    float m0 = -1e30f, m1 = -1e30f, l0 = 0.0f, l1 = 0.0f;

    for (int kt = 0; kt < KVTILES; kt++) {
        const int vb = kt & 1;

        if (kt + 1 < KVTILES) {
            ldtile(AT_KH(vb ^ 1), Kh + (size_t)(kt + 1) * 128 * DK);
            ldtile(AT_KL(vb ^ 1), Kl + (size_t)(kt + 1) * 128 * DK);
            ldtile(AT_VH(vb ^ 1), Vh + (size_t)(kt + 1) * 128 * DK);
            ldtile(AT_VL(vb ^ 1), Vl + (size_t)(kt + 1) * 128 * DK);
            CP_ASYNC_COMMIT();
        }

        // ---- S = Q K^T : Q single fp16, K hi/lo (2 MMAs per n8) ----
        float c[16][4];
#pragma unroll
        for (int i = 0; i < 16; i++)
#pragma unroll
            for (int k = 0; k < 4; k++) c[i][k] = 0.0f;

#pragma unroll
        for (int kk = 0; kk < 4; kk++) {
            uint32_t q[4];
            {
                uint32_t ro = (uint32_t)((w * 16 + (lane & 15)) * AST
                                         + (kk * 16 + (lane >> 4) * 8) * 2);
                ldsm4(q, sb + AT_Q + ro);
            }
#pragma unroll
            for (int nj = 0; nj < 8; nj++) {
                uint32_t bh_[4], bl_[4];
                uint32_t ro = (uint32_t)((nj * 16 + (lane & 7) + ((lane >> 4) * 8)) * AST
                                         + (kk * 16 + ((lane >> 3) & 1) * 8) * 2);
                ldsm4(bh_, sb + AT_KH(vb) + ro);
                ldsm4(bl_, sb + AT_KL(vb) + ro);
                mma_f16(c[2 * nj],     q, bh_[0], bh_[1]);
                mma_f16(c[2 * nj],     q, bl_[0], bl_[1]);
                mma_f16(c[2 * nj + 1], q, bh_[2], bh_[3]);
                mma_f16(c[2 * nj + 1], q, bl_[2], bl_[3]);
            }
        }

        // ---- warp-local online softmax ----
        float mx0 = -1e30f, mx1 = -1e30f;
#pragma unroll
        for (int ni = 0; ni < 16; ni++) {
            mx0 = fmaxf(mx0, fmaxf(c[ni][0], c[ni][1]));
            mx1 = fmaxf(mx1, fmaxf(c[ni][2], c[ni][3]));
        }
        mx0 = fmaxf(mx0, __shfl_xor_sync(0xffffffffu, mx0, 1));
        mx0 = fmaxf(mx0, __shfl_xor_sync(0xffffffffu, mx0, 2));
        mx1 = fmaxf(mx1, __shfl_xor_sync(0xffffffffu, mx1, 1));
        mx1 = fmaxf(mx1, __shfl_xor_sync(0xffffffffu, mx1, 2));

        const float nm0 = fmaxf(m0, mx0), nm1 = fmaxf(m1, mx1);
        const float alpha0 = __expf(m0 - nm0), alpha1 = __expf(m1 - nm1);
        m0 = nm0; m1 = nm1;

        float s0 = 0.0f, s1 = 0.0f;
#pragma unroll
        for (int ni = 0; ni < 16; ni++) {
            c[ni][0] = __expf(c[ni][0] - nm0);
            c[ni][1] = __expf(c[ni][1] - nm0);
            c[ni][2] = __expf(c[ni][2] - nm1);
            c[ni][3] = __expf(c[ni][3] - nm1);
            s0 += c[ni][0] + c[ni][1];
            s1 += c[ni][2] + c[ni][3];
        }
        s0 += __shfl_xor_sync(0xffffffffu, s0, 1);
        s0 += __shfl_xor_sync(0xffffffffu, s0, 2);
        s1 += __shfl_xor_sync(0xffffffffu, s1, 1);
        s1 += __shfl_xor_sync(0xffffffffu, s1, 2);
        l0 = l0 * alpha0 + s0;
        l1 = l1 * alpha1 + s1;

#pragma unroll
        for (int i = 0; i < 8; i++) {
            o[i][0] *= alpha0; o[i][1] *= alpha0;
            o[i][2] *= alpha1; o[i][3] *= alpha1;
        }

        // ---- O += P V : P single fp16 from C-frags, V fp16 hi/lo ----
#pragma unroll
        for (int kk = 0; kk < 8; kk++) {
            uint32_t ph[4];
            ph[0] = pack_h16(c[2 * kk][0], c[2 * kk][1]);
            ph[1] = pack_h16(c[2 * kk][2], c[2 * kk][3]);
            ph[2] = pack_h16(c[2 * kk + 1][0], c[2 * kk + 1][1]);
            ph[3] = pack_h16(c[2 * kk + 1][2], c[2 * kk + 1][3]);
#pragma unroll
            for (int nj = 0; nj < 4; nj++) {
                uint32_t vh[4], vl[4];
                uint32_t ro = (uint32_t)((kk * 16 + (lane & 15)) * AST
                                         + (nj * 16 + (lane >> 4) * 8) * 2);
                ldsm4t(vh, sb + AT_VH(vb) + ro);
                ldsm4t(vl, sb + AT_VL(vb) + ro);
                mma_f16(o[2 * nj],     ph, vh[0], vh[1]);
                mma_f16(o[2 * nj],     ph, vl[0], vl[1]);
                mma_f16(o[2 * nj + 1], ph, vh[2], vh[3]);
                mma_f16(o[2 * nj + 1], ph, vl[2], vl[3]);
            }
        }

        if (kt + 1 < KVTILES) CP_ASYNC_WAIT_ALL();
        __syncthreads();
    }

    // ---- epilogue: normalize, emit single fp16 ctx [B,S,1024] ----
    const int b = bh >> 4, h = bh & 15;
    const float inv0 = 1.0f / l0, inv1 = 1.0f / l1;
    const size_t row0 = (size_t)(b * SEQ + qt * 256 + w * 16 + (lane >> 2));
#pragma unroll
    for (int on = 0; on < 8; on++) {
        const int colg = h * DK + on * 8 + (lane & 3) * 2;
        *(uint32_t*)(g_ctx16 + row0 * D_MODEL + colg) = pack_h16(o[on][0] * inv0, o[on][1] * inv0);
        *(uint32_t*)(g_ctx16 + (row0 + 8) * D_MODEL + colg) = pack_h16(o[on][2] * inv1, o[on][3] * inv1);
    }
}

// ============================================================================
// launch
// ============================================================================
extern "C" void kernel_launch(void* const* d_in, const int* in_sizes, int n_in,
                              void* d_out, int out_size)
{
    const float* query  = (const float*)d_in[0];
    const float* key_in = (const float*)d_in[1];
    const float* value  = (const float*)d_in[2];
    const float* Wq = (const float*)d_in[3];
    const float* bq = (const float*)d_in[4];
    const float* Wk = (const float*)d_in[5];
    const float* bk = (const float*)d_in[6];
    const float* Wv = (const float*)d_in[7];
    const float* bv = (const float*)d_in[8];
    const float* Wo = (const float*)d_in[9];
    const float* bo = (const float*)d_in[10];
    float* out = (float*)d_out;

    __half *q16, *k16h, *k16l, *v16h, *v16l, *ctx16, *a16, *w16h, *w16l;
    cudaGetSymbolAddress((void**)&q16, g_Q16);
    cudaGetSymbolAddress((void**)&k16h, g_K16h);
    cudaGetSymbolAddress((void**)&k16l, g_K16l);
    cudaGetSymbolAddress((void**)&v16h, g_V16h);
    cudaGetSymbolAddress((void**)&v16l, g_V16l);
    cudaGetSymbolAddress((void**)&ctx16, g_ctx16);
    cudaGetSymbolAddress((void**)&a16, g_a16);
    cudaGetSymbolAddress((void**)&w16h, g_w16h);
    cudaGetSymbolAddress((void**)&w16l, g_w16l);

    cudaFuncSetAttribute(gemm_qkv16, cudaFuncAttributeMaxDynamicSharedMemorySize, GEMM16_SMEM);
    cudaFuncSetAttribute(gemm_out16, cudaFuncAttributeMaxDynamicSharedMemorySize, GEMM16_SMEM);
    cudaFuncSetAttribute(attn_tc, cudaFuncAttributeMaxDynamicSharedMemorySize, ATTN_SMEM);

    const int ACT4 = MROWS * D_MODEL / 4;
    const int W4   = D_MODEL * D_MODEL / 4;
    const size_t WSL = (size_t)D_MODEL * D_MODEL;

    // conversions
    conv_w4<<<dim3((W4 + 255) / 256, 4), 256>>>(Wq, Wk, Wv, Wo, w16h, w16l, W4);
    conv_a3<<<dim3((ACT4 + 255) / 256, 3), 256>>>(query, key_in, value, a16, ACT4);

    // fused Q/K/V projections (fp16 2-term)
    gemm_qkv16<<<dim3(D_MODEL / 128, MROWS / 128, 3), 256, GEMM16_SMEM>>>(
        a16, w16h, w16l, bq, bk, bv, q16, k16h, k16l, v16h, v16l);

    // attention
    attn_tc<<<dim3(SEQ / 256, BATCH * NUM_HEADS), dim3(512), ATTN_SMEM>>>();

    // output projection
    gemm_out16<<<dim3(D_MODEL / 128, MROWS / 128), 256, GEMM16_SMEM>>>(
        ctx16, w16h + 3 * WSL, w16l + 3 * WSL, bo, out);
}

// round 9
// speedup vs baseline: 5.5347x; 1.2891x over previous
#include <cuda_runtime.h>
#include <cuda_fp16.h>
#include <cstdint>

#define D_MODEL 1024
#define NUM_HEADS 16
#define DK 64
#define BATCH 4
#define SEQ 2048
#define MROWS (BATCH * SEQ)   /* 8192 */
#define KVTILES (SEQ / 128)   /* 16 */

// ---------------- scratch (all fp16) ----------------
__device__ __half g_Q16[BATCH * NUM_HEADS * SEQ * DK];    // single
__device__ __half g_K16[BATCH * NUM_HEADS * SEQ * DK];    // single
__device__ __half g_V16[BATCH * NUM_HEADS * SEQ * DK];    // single
__device__ __half g_ctx16[MROWS * D_MODEL];               // attn out (single)
__device__ __half g_a16[3 * MROWS * D_MODEL];             // query,key,value acts
__device__ __half g_w16h[4 * D_MODEL * D_MODEL];          // Wq,Wk,Wv,Wo hi
__device__ __half g_w16l[4 * D_MODEL * D_MODEL];          // Wq,Wk,Wv lo (Wo unused)

// ---------------- helpers ----------------
__device__ __forceinline__ uint32_t smem_u32(const void* p) {
    uint32_t a;
    asm("{ .reg .u64 t; cvta.to.shared.u64 t, %1; cvt.u32.u64 %0, t; }" : "=r"(a) : "l"(p));
    return a;
}
#define CP_ASYNC16(saddr, gptr) \
    asm volatile("cp.async.cg.shared.global [%0], [%1], 16;" :: "r"((uint32_t)(saddr)), "l"(gptr))
#define CP_ASYNC_COMMIT()    asm volatile("cp.async.commit_group;" ::: "memory")
#define CP_ASYNC_WAIT_ALL()  asm volatile("cp.async.wait_group 0;" ::: "memory")

__device__ __forceinline__ void ldsm4(uint32_t r[4], uint32_t a) {
    asm volatile("ldmatrix.sync.aligned.m8n8.x4.shared.b16 {%0,%1,%2,%3}, [%4];"
        : "=r"(r[0]), "=r"(r[1]), "=r"(r[2]), "=r"(r[3]) : "r"(a));
}
__device__ __forceinline__ void ldsm4t(uint32_t r[4], uint32_t a) {
    asm volatile("ldmatrix.sync.aligned.m8n8.x4.trans.shared.b16 {%0,%1,%2,%3}, [%4];"
        : "=r"(r[0]), "=r"(r[1]), "=r"(r[2]), "=r"(r[3]) : "r"(a));
}
__device__ __forceinline__ void mma_f16(float c[4], const uint32_t a[4], uint32_t b0, uint32_t b1) {
    asm volatile("mma.sync.aligned.m16n8k16.row.col.f32.f16.f16.f32 "
        "{%0,%1,%2,%3}, {%4,%5,%6,%7}, {%8,%9}, {%0,%1,%2,%3};"
        : "+f"(c[0]), "+f"(c[1]), "+f"(c[2]), "+f"(c[3])
        : "r"(a[0]), "r"(a[1]), "r"(a[2]), "r"(a[3]), "r"(b0), "r"(b1));
}
__device__ __forceinline__ uint32_t pack_h16(float x, float y) {
    __half2 h = __floats2half2_rn(x, y);
    return *(uint32_t*)&h;
}
__device__ __forceinline__ uint32_t pack_l16(float x, float y) {
    float xr = x - __half2float(__float2half_rn(x));
    float yr = y - __half2float(__float2half_rn(y));
    __half2 h = __floats2half2_rn(xr, yr);
    return *(uint32_t*)&h;
}

// ============================================================================
// conversions
// ============================================================================
__global__ __launch_bounds__(256) void conv_w4(
    const float* __restrict__ x0, const float* __restrict__ x1,
    const float* __restrict__ x2, const float* __restrict__ x3,
    __half* __restrict__ hi, __half* __restrict__ lo, int n4)
{
    int i = blockIdx.x * blockDim.x + threadIdx.x;
    if (i >= n4) return;
    const float* x = (blockIdx.y == 0) ? x0 : (blockIdx.y == 1) ? x1
                   : (blockIdx.y == 2) ? x2 : x3;
    size_t o = (size_t)blockIdx.y * n4 + i;
    float4 v = ((const float4*)x)[i];
    uint2 H;
    H.x = pack_h16(v.x, v.y); H.y = pack_h16(v.z, v.w);
    ((uint2*)hi)[o] = H;
    if (blockIdx.y < 3) {     // lo only needed for Wq, Wk, Wv
        uint2 L;
        L.x = pack_l16(v.x, v.y); L.y = pack_l16(v.z, v.w);
        ((uint2*)lo)[o] = L;
    }
}
__global__ __launch_bounds__(256) void conv_a3(
    const float* __restrict__ x0, const float* __restrict__ x1,
    const float* __restrict__ x2, __half* __restrict__ h16, int n4)
{
    int i = blockIdx.x * blockDim.x + threadIdx.x;
    if (i >= n4) return;
    const float* x = (blockIdx.y == 0) ? x0 : (blockIdx.y == 1) ? x1 : x2;
    size_t o = (size_t)blockIdx.y * n4 + i;
    float4 v = ((const float4*)x)[i];
    uint2 H;
    H.x = pack_h16(v.x, v.y); H.y = pack_h16(v.z, v.w);
    ((uint2*)h16)[o] = H;
}

// ============================================================================
// fp16 GEMM mainloop, NT = number of W terms (1 or 2). BM=BN=128, BK=32.
// ============================================================================
#define BK 32
#define GPAD 40
#define MAT16 (128 * GPAD * 2)
#define NIT (D_MODEL / BK)
#define STG(NT) ((1 + (NT)) * MAT16)
#define GEMM_SMEM(NT) (2 * STG(NT))

template <int NT>
__device__ __forceinline__ void gemm16_main(
    uint32_t sb, int t,
    const __half* __restrict__ A,
    const __half* __restrict__ Wh, const __half* __restrict__ Wl,
    int m0, int n0, float c[4][4][4])
{
    const int lane = t & 31, wid = t >> 5;
    const int wm = wid >> 2, wn = wid & 3;
    const uint32_t stg = STG(NT);

    auto load_stage = [&](int s, int it) {
        const int k0 = it * BK;
        const uint32_t st = sb + s * stg;
#pragma unroll
        for (int j = 0; j < 2; j++) {
            int idx = t + j * 256;
            int r = idx >> 2, cc = idx & 3;
            uint32_t so = (uint32_t)(r * (GPAD * 2) + cc * 16);
            CP_ASYNC16(st + 0 * MAT16 + so, A  + (size_t)(m0 + r) * D_MODEL + k0 + cc * 8);
            CP_ASYNC16(st + 1 * MAT16 + so, Wh + (size_t)(n0 + r) * D_MODEL + k0 + cc * 8);
            if (NT == 2)
                CP_ASYNC16(st + 2 * MAT16 + so, Wl + (size_t)(n0 + r) * D_MODEL + k0 + cc * 8);
        }
    };

    load_stage(0, 0);
    CP_ASYNC_COMMIT();

    for (int it = 0; it < NIT; ++it) {
        const int s = it & 1;
        CP_ASYNC_WAIT_ALL();
        __syncthreads();
        if (it + 1 < NIT) {
            load_stage(s ^ 1, it + 1);
            CP_ASYNC_COMMIT();
        }
        const uint32_t st = sb + s * stg;
#pragma unroll
        for (int kk = 0; kk < 2; kk++) {
            uint32_t ah[4][4];
#pragma unroll
            for (int mi = 0; mi < 4; mi++) {
                uint32_t ro = (uint32_t)((wm * 64 + mi * 16 + (lane & 15)) * (GPAD * 2)
                                         + (kk * 16 + (lane >> 4) * 8) * 2);
                ldsm4(ah[mi], st + 0 * MAT16 + ro);
            }
            uint32_t bh_[2][4], bl_[2][4];
#pragma unroll
            for (int nj = 0; nj < 2; nj++) {
                uint32_t ro = (uint32_t)((wn * 32 + nj * 16 + (lane & 7) + ((lane >> 4) * 8)) * (GPAD * 2)
                                         + (kk * 16 + ((lane >> 3) & 1) * 8) * 2);
                ldsm4(bh_[nj], st + 1 * MAT16 + ro);
                if (NT == 2) ldsm4(bl_[nj], st + 2 * MAT16 + ro);
            }
#pragma unroll
            for (int mi = 0; mi < 4; mi++)
#pragma unroll
                for (int ni = 0; ni < 4; ni++) {
                    const int nj = ni >> 1, ss = (ni & 1) * 2;
                    mma_f16(c[mi][ni], ah[mi], bh_[nj][ss], bh_[nj][ss + 1]);
                    if (NT == 2)
                        mma_f16(c[mi][ni], ah[mi], bl_[nj][ss], bl_[nj][ss + 1]);
                }
        }
    }
}

// ---- fused Q/K/V projections (2-term W), single fp16 split-head outputs ----
__global__ __launch_bounds__(256, 2) void gemm_qkv16(
    const __half* __restrict__ a16, const __half* __restrict__ w16h,
    const __half* __restrict__ w16l,
    const float* __restrict__ bq, const float* __restrict__ bk,
    const float* __restrict__ bv,
    __half* __restrict__ q16, __half* __restrict__ k16, __half* __restrict__ v16)
{
    extern __shared__ char smem[];
    const uint32_t sb = smem_u32(smem);
    const int t = threadIdx.x;
    const int lane = t & 31, wid = t >> 5;
    const int wm = wid >> 2, wn = wid & 3;
    const int m0 = blockIdx.y * 128, n0 = blockIdx.x * 128;
    const int z = blockIdx.z;

    const __half* A  = a16  + (size_t)z * MROWS * D_MODEL;
    const __half* Wh = w16h + (size_t)z * D_MODEL * D_MODEL;
    const __half* Wl = w16l + (size_t)z * D_MODEL * D_MODEL;
    const float* bias = (z == 0) ? bq : (z == 1) ? bk : bv;
    __half* C = (z == 0) ? q16 : (z == 1) ? k16 : v16;
    const float oscale = (z == 0) ? 0.125f : 1.0f;

    float c[4][4][4];
#pragma unroll
    for (int i = 0; i < 4; i++)
#pragma unroll
        for (int j = 0; j < 4; j++)
#pragma unroll
            for (int k = 0; k < 4; k++) c[i][j][k] = 0.0f;

    gemm16_main<2>(sb, t, A, Wh, Wl, m0, n0, c);

#pragma unroll
    for (int mi = 0; mi < 4; mi++) {
        const int r0 = m0 + wm * 64 + mi * 16 + (lane >> 2);
#pragma unroll
        for (int ni = 0; ni < 4; ni++) {
            const int col = n0 + wn * 32 + ni * 8 + (lane & 3) * 2;
            const float b0 = bias[col], b1 = bias[col + 1];
            const int h = col >> 6, d = col & 63;
            float v00 = (c[mi][ni][0] + b0) * oscale, v01 = (c[mi][ni][1] + b1) * oscale;
            float v10 = (c[mi][ni][2] + b0) * oscale, v11 = (c[mi][ni][3] + b1) * oscale;
#pragma unroll
            for (int rr = 0; rr < 2; rr++) {
                const int m = r0 + rr * 8;
                const int b = m >> 11, sdx = m & 2047;
                const size_t off = (((size_t)(b * NUM_HEADS + h) * SEQ + sdx) * DK + d);
                *(uint32_t*)(C + off) = pack_h16(rr ? v10 : v00, rr ? v11 : v01);
            }
        }
    }
}

// ---- output projection: 1-term W, fp32 row-major out ----
__global__ __launch_bounds__(256, 2) void gemm_out16(
    const __half* __restrict__ A, const __half* __restrict__ Wh,
    const float* __restrict__ bias, float* __restrict__ Cf)
{
    extern __shared__ char smem[];
    const uint32_t sb = smem_u32(smem);
    const int t = threadIdx.x;
    const int lane = t & 31, wid = t >> 5;
    const int wm = wid >> 2, wn = wid & 3;
    const int m0 = blockIdx.y * 128, n0 = blockIdx.x * 128;

    float c[4][4][4];
#pragma unroll
    for (int i = 0; i < 4; i++)
#pragma unroll
        for (int j = 0; j < 4; j++)
#pragma unroll
            for (int k = 0; k < 4; k++) c[i][j][k] = 0.0f;

    gemm16_main<1>(sb, t, A, Wh, nullptr, m0, n0, c);

#pragma unroll
    for (int mi = 0; mi < 4; mi++) {
        const int r0 = m0 + wm * 64 + mi * 16 + (lane >> 2);
#pragma unroll
        for (int ni = 0; ni < 4; ni++) {
            const int col = n0 + wn * 32 + ni * 8 + (lane & 3) * 2;
            const float b0 = bias[col], b1 = bias[col + 1];
            *(float2*)(Cf + (size_t)r0 * D_MODEL + col) =
                make_float2(c[mi][ni][0] + b0, c[mi][ni][1] + b1);
            *(float2*)(Cf + (size_t)(r0 + 8) * D_MODEL + col) =
                make_float2(c[mi][ni][2] + b0, c[mi][ni][3] + b1);
        }
    }
}

// ============================================================================
// FA2 attention, all single fp16: Q, K, V, P. 512 threads, CTA = 256 q-rows,
// 1 sync/kv-iter, K/V double-buffered. smem 110.6 KB.
// ============================================================================
#define AST 144
#define AT_Q  0
#define AT_K(b) (AT_Q + 256 * AST + (b) * (128 * AST))
#define AT_V(b) (AT_Q + 256 * AST + 2 * (128 * AST) + (b) * (128 * AST))
#define ATTN_SMEM (256 * AST + 4 * (128 * AST))   /* 110592 B */

__global__ __launch_bounds__(512) void attn_tc()
{
    extern __shared__ char smem[];
    const uint32_t sb = smem_u32(smem);
    const int t = threadIdx.x;
    const int lane = t & 31, w = t >> 5;
    const int qt = blockIdx.x, bh = blockIdx.y;

    const __half* Qs = g_Q16 + ((size_t)bh * SEQ + qt * 256) * DK;
    const __half* Kg = g_K16 + (size_t)bh * SEQ * DK;
    const __half* Vg = g_V16 + (size_t)bh * SEQ * DK;

    auto ldtile = [&](uint32_t dstoff, const __half* src) {   // 128x64 fp16
#pragma unroll
        for (int j = 0; j < 2; j++) {
            int idx = t + j * 512;
            int r = idx >> 3, cc = idx & 7;
            CP_ASYNC16(sb + dstoff + r * AST + cc * 16, src + r * DK + cc * 8);
        }
    };
    auto ldtileQ = [&](uint32_t dstoff, const __half* src) {  // 256x64 fp16
#pragma unroll
        for (int j = 0; j < 4; j++) {
            int idx = t + j * 512;
            int r = idx >> 3, cc = idx & 7;
            CP_ASYNC16(sb + dstoff + r * AST + cc * 16, src + r * DK + cc * 8);
        }
    };

    ldtileQ(AT_Q, Qs);
    ldtile(AT_K(0), Kg);
    ldtile(AT_V(0), Vg);
    CP_ASYNC_COMMIT();
    CP_ASYNC_WAIT_ALL();
    __syncthreads();

    float o[8][4];
#pragma unroll
    for (int i = 0; i < 8; i++)
#pragma unroll
        for (int k = 0; k < 4; k++) o[i][k] = 0.0f;
    float m0 = -1e30f, m1 = -1e30f, l0 = 0.0f, l1 = 0.0f;

    for (int kt = 0; kt < KVTILES; kt++) {
        const int vb = kt & 1;

        if (kt + 1 < KVTILES) {
            ldtile(AT_K(vb ^ 1), Kg + (size_t)(kt + 1) * 128 * DK);
            ldtile(AT_V(vb ^ 1), Vg + (size_t)(kt + 1) * 128 * DK);
            CP_ASYNC_COMMIT();
        }

        // ---- S = Q K^T : single fp16 both sides ----
        float c[16][4];
#pragma unroll
        for (int i = 0; i < 16; i++)
#pragma unroll
            for (int k = 0; k < 4; k++) c[i][k] = 0.0f;

#pragma unroll
        for (int kk = 0; kk < 4; kk++) {
            uint32_t q[4];
            {
                uint32_t ro = (uint32_t)((w * 16 + (lane & 15)) * AST
                                         + (kk * 16 + (lane >> 4) * 8) * 2);
                ldsm4(q, sb + AT_Q + ro);
            }
#pragma unroll
            for (int nj = 0; nj < 8; nj++) {
                uint32_t bk_[4];
                uint32_t ro = (uint32_t)((nj * 16 + (lane & 7) + ((lane >> 4) * 8)) * AST
                                         + (kk * 16 + ((lane >> 3) & 1) * 8) * 2);
                ldsm4(bk_, sb + AT_K(vb) + ro);
                mma_f16(c[2 * nj],     q, bk_[0], bk_[1]);
                mma_f16(c[2 * nj + 1], q, bk_[2], bk_[3]);
            }
        }

        // ---- warp-local online softmax ----
        float mx0 = -1e30f, mx1 = -1e30f;
#pragma unroll
        for (int ni = 0; ni < 16; ni++) {
            mx0 = fmaxf(mx0, fmaxf(c[ni][0], c[ni][1]));
            mx1 = fmaxf(mx1, fmaxf(c[ni][2], c[ni][3]));
        }
        mx0 = fmaxf(mx0, __shfl_xor_sync(0xffffffffu, mx0, 1));
        mx0 = fmaxf(mx0, __shfl_xor_sync(0xffffffffu, mx0, 2));
        mx1 = fmaxf(mx1, __shfl_xor_sync(0xffffffffu, mx1, 1));
        mx1 = fmaxf(mx1, __shfl_xor_sync(0xffffffffu, mx1, 2));

        const float nm0 = fmaxf(m0, mx0), nm1 = fmaxf(m1, mx1);
        const float alpha0 = __expf(m0 - nm0), alpha1 = __expf(m1 - nm1);
        m0 = nm0; m1 = nm1;

        float s0 = 0.0f, s1 = 0.0f;
#pragma unroll
        for (int ni = 0; ni < 16; ni++) {
            c[ni][0] = __expf(c[ni][0] - nm0);
            c[ni][1] = __expf(c[ni][1] - nm0);
            c[ni][2] = __expf(c[ni][2] - nm1);
            c[ni][3] = __expf(c[ni][3] - nm1);
            s0 += c[ni][0] + c[ni][1];
            s1 += c[ni][2] + c[ni][3];
        }
        s0 += __shfl_xor_sync(0xffffffffu, s0, 1);
        s0 += __shfl_xor_sync(0xffffffffu, s0, 2);
        s1 += __shfl_xor_sync(0xffffffffu, s1, 1);
        s1 += __shfl_xor_sync(0xffffffffu, s1, 2);
        l0 = l0 * alpha0 + s0;
        l1 = l1 * alpha1 + s1;

#pragma unroll
        for (int i = 0; i < 8; i++) {
            o[i][0] *= alpha0; o[i][1] *= alpha0;
            o[i][2] *= alpha1; o[i][3] *= alpha1;
        }

        // ---- O += P V : P single fp16 from C-frags, V single fp16 ----
#pragma unroll
        for (int kk = 0; kk < 8; kk++) {
            uint32_t ph[4];
            ph[0] = pack_h16(c[2 * kk][0], c[2 * kk][1]);
            ph[1] = pack_h16(c[2 * kk][2], c[2 * kk][3]);
            ph[2] = pack_h16(c[2 * kk + 1][0], c[2 * kk + 1][1]);
            ph[3] = pack_h16(c[2 * kk + 1][2], c[2 * kk + 1][3]);
#pragma unroll
            for (int nj = 0; nj < 4; nj++) {
                uint32_t vh[4];
                uint32_t ro = (uint32_t)((kk * 16 + (lane & 15)) * AST
                                         + (nj * 16 + (lane >> 4) * 8) * 2);
                ldsm4t(vh, sb + AT_V(vb) + ro);
                mma_f16(o[2 * nj],     ph, vh[0], vh[1]);
                mma_f16(o[2 * nj + 1], ph, vh[2], vh[3]);
            }
        }

        if (kt + 1 < KVTILES) CP_ASYNC_WAIT_ALL();
        __syncthreads();
    }

    // ---- epilogue: normalize, emit single fp16 ctx [B,S,1024] ----
    const int b = bh >> 4, h = bh & 15;
    const float inv0 = 1.0f / l0, inv1 = 1.0f / l1;
    const size_t row0 = (size_t)(b * SEQ + qt * 256 + w * 16 + (lane >> 2));
#pragma unroll
    for (int on = 0; on < 8; on++) {
        const int colg = h * DK + on * 8 + (lane & 3) * 2;
        *(uint32_t*)(g_ctx16 + row0 * D_MODEL + colg) = pack_h16(o[on][0] * inv0, o[on][1] * inv0);
        *(uint32_t*)(g_ctx16 + (row0 + 8) * D_MODEL + colg) = pack_h16(o[on][2] * inv1, o[on][3] * inv1);
    }
}

// ============================================================================
// launch
// ============================================================================
extern "C" void kernel_launch(void* const* d_in, const int* in_sizes, int n_in,
                              void* d_out, int out_size)
{
    const float* query  = (const float*)d_in[0];
    const float* key_in = (const float*)d_in[1];
    const float* value  = (const float*)d_in[2];
    const float* Wq = (const float*)d_in[3];
    const float* bq = (const float*)d_in[4];
    const float* Wk = (const float*)d_in[5];
    const float* bk = (const float*)d_in[6];
    const float* Wv = (const float*)d_in[7];
    const float* bv = (const float*)d_in[8];
    const float* Wo = (const float*)d_in[9];
    const float* bo = (const float*)d_in[10];
    float* out = (float*)d_out;

    __half *q16, *k16, *v16, *ctx16, *a16, *w16h, *w16l;
    cudaGetSymbolAddress((void**)&q16, g_Q16);
    cudaGetSymbolAddress((void**)&k16, g_K16);
    cudaGetSymbolAddress((void**)&v16, g_V16);
    cudaGetSymbolAddress((void**)&ctx16, g_ctx16);
    cudaGetSymbolAddress((void**)&a16, g_a16);
    cudaGetSymbolAddress((void**)&w16h, g_w16h);
    cudaGetSymbolAddress((void**)&w16l, g_w16l);

    cudaFuncSetAttribute(gemm_qkv16, cudaFuncAttributeMaxDynamicSharedMemorySize, GEMM_SMEM(2));
    cudaFuncSetAttribute(gemm_out16, cudaFuncAttributeMaxDynamicSharedMemorySize, GEMM_SMEM(1));
    cudaFuncSetAttribute(attn_tc, cudaFuncAttributeMaxDynamicSharedMemorySize, ATTN_SMEM);

    const int ACT4 = MROWS * D_MODEL / 4;
    const int W4   = D_MODEL * D_MODEL / 4;
    const size_t WSL = (size_t)D_MODEL * D_MODEL;

    // conversions
    conv_w4<<<dim3((W4 + 255) / 256, 4), 256>>>(Wq, Wk, Wv, Wo, w16h, w16l, W4);
    conv_a3<<<dim3((ACT4 + 255) / 256, 3), 256>>>(query, key_in, value, a16, ACT4);

    // fused Q/K/V projections (fp16, 2-term W)
    gemm_qkv16<<<dim3(D_MODEL / 128, MROWS / 128, 3), 256, GEMM_SMEM(2)>>>(
        a16, w16h, w16l, bq, bk, bv, q16, k16, v16);

    // attention (all single fp16)
    attn_tc<<<dim3(SEQ / 256, BATCH * NUM_HEADS), dim3(512), ATTN_SMEM>>>();

    // output projection (1-term W)
    gemm_out16<<<dim3(D_MODEL / 128, MROWS / 128), 256, GEMM_SMEM(1)>>>(
        ctx16, w16h + 3 * WSL, bo, out);
}

// round 10
// speedup vs baseline: 6.9174x; 1.2498x over previous
#include <cuda_runtime.h>
#include <cuda_fp16.h>
#include <cstdint>

#define D_MODEL 1024
#define NUM_HEADS 16
#define DK 64
#define BATCH 4
#define SEQ 2048
#define MROWS (BATCH * SEQ)   /* 8192 */
#define KVTILES (SEQ / 128)   /* 16 */

// ---------------- scratch (all single fp16) ----------------
__device__ __half g_Q16[BATCH * NUM_HEADS * SEQ * DK];
__device__ __half g_K16[BATCH * NUM_HEADS * SEQ * DK];
__device__ __half g_V16[BATCH * NUM_HEADS * SEQ * DK];
__device__ __half g_ctx16[MROWS * D_MODEL];
__device__ __half g_a16[3 * MROWS * D_MODEL];     // query,key,value acts
__device__ __half g_w16[4 * D_MODEL * D_MODEL];   // Wq,Wk,Wv,Wo

// ---------------- helpers ----------------
__device__ __forceinline__ uint32_t smem_u32(const void* p) {
    uint32_t a;
    asm("{ .reg .u64 t; cvta.to.shared.u64 t, %1; cvt.u32.u64 %0, t; }" : "=r"(a) : "l"(p));
    return a;
}
#define CP_ASYNC16(saddr, gptr) \
    asm volatile("cp.async.cg.shared.global [%0], [%1], 16;" :: "r"((uint32_t)(saddr)), "l"(gptr))
#define CP_ASYNC_COMMIT()    asm volatile("cp.async.commit_group;" ::: "memory")
#define CP_ASYNC_WAIT_ALL()  asm volatile("cp.async.wait_group 0;" ::: "memory")

__device__ __forceinline__ void ldsm4(uint32_t r[4], uint32_t a) {
    asm volatile("ldmatrix.sync.aligned.m8n8.x4.shared.b16 {%0,%1,%2,%3}, [%4];"
        : "=r"(r[0]), "=r"(r[1]), "=r"(r[2]), "=r"(r[3]) : "r"(a));
}
__device__ __forceinline__ void ldsm4t(uint32_t r[4], uint32_t a) {
    asm volatile("ldmatrix.sync.aligned.m8n8.x4.trans.shared.b16 {%0,%1,%2,%3}, [%4];"
        : "=r"(r[0]), "=r"(r[1]), "=r"(r[2]), "=r"(r[3]) : "r"(a));
}
__device__ __forceinline__ void mma_f16(float c[4], const uint32_t a[4], uint32_t b0, uint32_t b1) {
    asm volatile("mma.sync.aligned.m16n8k16.row.col.f32.f16.f16.f32 "
        "{%0,%1,%2,%3}, {%4,%5,%6,%7}, {%8,%9}, {%0,%1,%2,%3};"
        : "+f"(c[0]), "+f"(c[1]), "+f"(c[2]), "+f"(c[3])
        : "r"(a[0]), "r"(a[1]), "r"(a[2]), "r"(a[3]), "r"(b0), "r"(b1));
}
__device__ __forceinline__ uint32_t pack_h16(float x, float y) {
    __half2 h = __floats2half2_rn(x, y);
    return *(uint32_t*)&h;
}

// ============================================================================
// conversions (single fp16 only)
// ============================================================================
__global__ __launch_bounds__(256) void conv_w4(
    const float* __restrict__ x0, const float* __restrict__ x1,
    const float* __restrict__ x2, const float* __restrict__ x3,
    __half* __restrict__ h16, int n4)
{
    int i = blockIdx.x * blockDim.x + threadIdx.x;
    if (i >= n4) return;
    const float* x = (blockIdx.y == 0) ? x0 : (blockIdx.y == 1) ? x1
                   : (blockIdx.y == 2) ? x2 : x3;
    size_t o = (size_t)blockIdx.y * n4 + i;
    float4 v = ((const float4*)x)[i];
    uint2 H;
    H.x = pack_h16(v.x, v.y); H.y = pack_h16(v.z, v.w);
    ((uint2*)h16)[o] = H;
}
__global__ __launch_bounds__(256) void conv_a3(
    const float* __restrict__ x0, const float* __restrict__ x1,
    const float* __restrict__ x2, __half* __restrict__ h16, int n4)
{
    int i = blockIdx.x * blockDim.x + threadIdx.x;
    if (i >= n4) return;
    const float* x = (blockIdx.y == 0) ? x0 : (blockIdx.y == 1) ? x1 : x2;
    size_t o = (size_t)blockIdx.y * n4 + i;
    float4 v = ((const float4*)x)[i];
    uint2 H;
    H.x = pack_h16(v.x, v.y); H.y = pack_h16(v.z, v.w);
    ((uint2*)h16)[o] = H;
}

// ============================================================================
// fp16 1-term GEMM mainloop. BM=BN=128, BK=32, 8 warps, double-buffered.
// ============================================================================
#define BK 32
#define GPAD 40
#define MAT16 (128 * GPAD * 2)
#define NIT (D_MODEL / BK)
#define STG16 (2 * MAT16)
#define GEMM16_SMEM (2 * STG16)    /* 40960 B */

__device__ __forceinline__ void gemm16_main(
    uint32_t sb, int t,
    const __half* __restrict__ A, const __half* __restrict__ W,
    int m0, int n0, float c[4][4][4])
{
    const int lane = t & 31, wid = t >> 5;
    const int wm = wid >> 2, wn = wid & 3;

    auto load_stage = [&](int s, int it) {
        const int k0 = it * BK;
        const uint32_t st = sb + s * STG16;
#pragma unroll
        for (int j = 0; j < 2; j++) {
            int idx = t + j * 256;
            int r = idx >> 2, cc = idx & 3;
            uint32_t so = (uint32_t)(r * (GPAD * 2) + cc * 16);
            CP_ASYNC16(st + 0 * MAT16 + so, A + (size_t)(m0 + r) * D_MODEL + k0 + cc * 8);
            CP_ASYNC16(st + 1 * MAT16 + so, W + (size_t)(n0 + r) * D_MODEL + k0 + cc * 8);
        }
    };

    load_stage(0, 0);
    CP_ASYNC_COMMIT();

    for (int it = 0; it < NIT; ++it) {
        const int s = it & 1;
        CP_ASYNC_WAIT_ALL();
        __syncthreads();
        if (it + 1 < NIT) {
            load_stage(s ^ 1, it + 1);
            CP_ASYNC_COMMIT();
        }
        const uint32_t st = sb + s * STG16;
#pragma unroll
        for (int kk = 0; kk < 2; kk++) {
            uint32_t ah[4][4];
#pragma unroll
            for (int mi = 0; mi < 4; mi++) {
                uint32_t ro = (uint32_t)((wm * 64 + mi * 16 + (lane & 15)) * (GPAD * 2)
                                         + (kk * 16 + (lane >> 4) * 8) * 2);
                ldsm4(ah[mi], st + 0 * MAT16 + ro);
            }
            uint32_t bh_[2][4];
#pragma unroll
            for (int nj = 0; nj < 2; nj++) {
                uint32_t ro = (uint32_t)((wn * 32 + nj * 16 + (lane & 7) + ((lane >> 4) * 8)) * (GPAD * 2)
                                         + (kk * 16 + ((lane >> 3) & 1) * 8) * 2);
                ldsm4(bh_[nj], st + 1 * MAT16 + ro);
            }
#pragma unroll
            for (int mi = 0; mi < 4; mi++)
#pragma unroll
                for (int ni = 0; ni < 4; ni++) {
                    const int nj = ni >> 1, ss = (ni & 1) * 2;
                    mma_f16(c[mi][ni], ah[mi], bh_[nj][ss], bh_[nj][ss + 1]);
                }
        }
    }
}

// ---- fused Q/K/V projections (1-term W), single fp16 split-head outputs ----
__global__ __launch_bounds__(256, 2) void gemm_qkv16(
    const __half* __restrict__ a16, const __half* __restrict__ w16,
    const float* __restrict__ bq, const float* __restrict__ bk,
    const float* __restrict__ bv,
    __half* __restrict__ q16, __half* __restrict__ k16, __half* __restrict__ v16)
{
    extern __shared__ char smem[];
    const uint32_t sb = smem_u32(smem);
    const int t = threadIdx.x;
    const int lane = t & 31, wid = t >> 5;
    const int wm = wid >> 2, wn = wid & 3;
    const int m0 = blockIdx.y * 128, n0 = blockIdx.x * 128;
    const int z = blockIdx.z;

    const __half* A = a16 + (size_t)z * MROWS * D_MODEL;
    const __half* W = w16 + (size_t)z * D_MODEL * D_MODEL;
    const float* bias = (z == 0) ? bq : (z == 1) ? bk : bv;
    __half* C = (z == 0) ? q16 : (z == 1) ? k16 : v16;
    const float oscale = (z == 0) ? 0.125f : 1.0f;

    float c[4][4][4];
#pragma unroll
    for (int i = 0; i < 4; i++)
#pragma unroll
        for (int j = 0; j < 4; j++)
#pragma unroll
            for (int k = 0; k < 4; k++) c[i][j][k] = 0.0f;

    gemm16_main(sb, t, A, W, m0, n0, c);

#pragma unroll
    for (int mi = 0; mi < 4; mi++) {
        const int r0 = m0 + wm * 64 + mi * 16 + (lane >> 2);
#pragma unroll
        for (int ni = 0; ni < 4; ni++) {
            const int col = n0 + wn * 32 + ni * 8 + (lane & 3) * 2;
            const float b0 = bias[col], b1 = bias[col + 1];
            const int h = col >> 6, d = col & 63;
            float v00 = (c[mi][ni][0] + b0) * oscale, v01 = (c[mi][ni][1] + b1) * oscale;
            float v10 = (c[mi][ni][2] + b0) * oscale, v11 = (c[mi][ni][3] + b1) * oscale;
#pragma unroll
            for (int rr = 0; rr < 2; rr++) {
                const int m = r0 + rr * 8;
                const int b = m >> 11, sdx = m & 2047;
                const size_t off = (((size_t)(b * NUM_HEADS + h) * SEQ + sdx) * DK + d);
                *(uint32_t*)(C + off) = pack_h16(rr ? v10 : v00, rr ? v11 : v01);
            }
        }
    }
}

// ---- output projection: 1-term W, fp32 row-major out ----
__global__ __launch_bounds__(256, 2) void gemm_out16(
    const __half* __restrict__ A, const __half* __restrict__ W,
    const float* __restrict__ bias, float* __restrict__ Cf)
{
    extern __shared__ char smem[];
    const uint32_t sb = smem_u32(smem);
    const int t = threadIdx.x;
    const int lane = t & 31, wid = t >> 5;
    const int wm = wid >> 2, wn = wid & 3;
    const int m0 = blockIdx.y * 128, n0 = blockIdx.x * 128;

    float c[4][4][4];
#pragma unroll
    for (int i = 0; i < 4; i++)
#pragma unroll
        for (int j = 0; j < 4; j++)
#pragma unroll
            for (int k = 0; k < 4; k++) c[i][j][k] = 0.0f;

    gemm16_main(sb, t, A, W, m0, n0, c);

#pragma unroll
    for (int mi = 0; mi < 4; mi++) {
        const int r0 = m0 + wm * 64 + mi * 16 + (lane >> 2);
#pragma unroll
        for (int ni = 0; ni < 4; ni++) {
            const int col = n0 + wn * 32 + ni * 8 + (lane & 3) * 2;
            const float b0 = bias[col], b1 = bias[col + 1];
            *(float2*)(Cf + (size_t)r0 * D_MODEL + col) =
                make_float2(c[mi][ni][0] + b0, c[mi][ni][1] + b1);
            *(float2*)(Cf + (size_t)(r0 + 8) * D_MODEL + col) =
                make_float2(c[mi][ni][2] + b0, c[mi][ni][3] + b1);
        }
    }
}

// ============================================================================
// FA2 attention, all single fp16 (unchanged from R9 — 253 us, verified).
// ============================================================================
#define AST 144
#define AT_Q  0
#define AT_K(b) (AT_Q + 256 * AST + (b) * (128 * AST))
#define AT_V(b) (AT_Q + 256 * AST + 2 * (128 * AST) + (b) * (128 * AST))
#define ATTN_SMEM (256 * AST + 4 * (128 * AST))   /* 110592 B */

__global__ __launch_bounds__(512) void attn_tc()
{
    extern __shared__ char smem[];
    const uint32_t sb = smem_u32(smem);
    const int t = threadIdx.x;
    const int lane = t & 31, w = t >> 5;
    const int qt = blockIdx.x, bh = blockIdx.y;

    const __half* Qs = g_Q16 + ((size_t)bh * SEQ + qt * 256) * DK;
    const __half* Kg = g_K16 + (size_t)bh * SEQ * DK;
    const __half* Vg = g_V16 + (size_t)bh * SEQ * DK;

    auto ldtile = [&](uint32_t dstoff, const __half* src) {
#pragma unroll
        for (int j = 0; j < 2; j++) {
            int idx = t + j * 512;
            int r = idx >> 3, cc = idx & 7;
            CP_ASYNC16(sb + dstoff + r * AST + cc * 16, src + r * DK + cc * 8);
        }
    };
    auto ldtileQ = [&](uint32_t dstoff, const __half* src) {
#pragma unroll
        for (int j = 0; j < 4; j++) {
            int idx = t + j * 512;
            int r = idx >> 3, cc = idx & 7;
            CP_ASYNC16(sb + dstoff + r * AST + cc * 16, src + r * DK + cc * 8);
        }
    };

    ldtileQ(AT_Q, Qs);
    ldtile(AT_K(0), Kg);
    ldtile(AT_V(0), Vg);
    CP_ASYNC_COMMIT();
    CP_ASYNC_WAIT_ALL();
    __syncthreads();

    float o[8][4];
#pragma unroll
    for (int i = 0; i < 8; i++)
#pragma unroll
        for (int k = 0; k < 4; k++) o[i][k] = 0.0f;
    float m0 = -1e30f, m1 = -1e30f, l0 = 0.0f, l1 = 0.0f;

    for (int kt = 0; kt < KVTILES; kt++) {
        const int vb = kt & 1;

        if (kt + 1 < KVTILES) {
            ldtile(AT_K(vb ^ 1), Kg + (size_t)(kt + 1) * 128 * DK);
            ldtile(AT_V(vb ^ 1), Vg + (size_t)(kt + 1) * 128 * DK);
            CP_ASYNC_COMMIT();
        }

        float c[16][4];
#pragma unroll
        for (int i = 0; i < 16; i++)
#pragma unroll
            for (int k = 0; k < 4; k++) c[i][k] = 0.0f;

#pragma unroll
        for (int kk = 0; kk < 4; kk++) {
            uint32_t q[4];
            {
                uint32_t ro = (uint32_t)((w * 16 + (lane & 15)) * AST
                                         + (kk * 16 + (lane >> 4) * 8) * 2);
                ldsm4(q, sb + AT_Q + ro);
            }
#pragma unroll
            for (int nj = 0; nj < 8; nj++) {
                uint32_t bk_[4];
                uint32_t ro = (uint32_t)((nj * 16 + (lane & 7) + ((lane >> 4) * 8)) * AST
                                         + (kk * 16 + ((lane >> 3) & 1) * 8) * 2);
                ldsm4(bk_, sb + AT_K(vb) + ro);
                mma_f16(c[2 * nj],     q, bk_[0], bk_[1]);
                mma_f16(c[2 * nj + 1], q, bk_[2], bk_[3]);
            }
        }

        float mx0 = -1e30f, mx1 = -1e30f;
#pragma unroll
        for (int ni = 0; ni < 16; ni++) {
            mx0 = fmaxf(mx0, fmaxf(c[ni][0], c[ni][1]));
            mx1 = fmaxf(mx1, fmaxf(c[ni][2], c[ni][3]));
        }
        mx0 = fmaxf(mx0, __shfl_xor_sync(0xffffffffu, mx0, 1));
        mx0 = fmaxf(mx0, __shfl_xor_sync(0xffffffffu, mx0, 2));
        mx1 = fmaxf(mx1, __shfl_xor_sync(0xffffffffu, mx1, 1));
        mx1 = fmaxf(mx1, __shfl_xor_sync(0xffffffffu, mx1, 2));

        const float nm0 = fmaxf(m0, mx0), nm1 = fmaxf(m1, mx1);
        const float alpha0 = __expf(m0 - nm0), alpha1 = __expf(m1 - nm1);
        m0 = nm0; m1 = nm1;

        float s0 = 0.0f, s1 = 0.0f;
#pragma unroll
        for (int ni = 0; ni < 16; ni++) {
            c[ni][0] = __expf(c[ni][0] - nm0);
            c[ni][1] = __expf(c[ni][1] - nm0);
            c[ni][2] = __expf(c[ni][2] - nm1);
            c[ni][3] = __expf(c[ni][3] - nm1);
            s0 += c[ni][0] + c[ni][1];
            s1 += c[ni][2] + c[ni][3];
        }
        s0 += __shfl_xor_sync(0xffffffffu, s0, 1);
        s0 += __shfl_xor_sync(0xffffffffu, s0, 2);
        s1 += __shfl_xor_sync(0xffffffffu, s1, 1);
        s1 += __shfl_xor_sync(0xffffffffu, s1, 2);
        l0 = l0 * alpha0 + s0;
        l1 = l1 * alpha1 + s1;

#pragma unroll
        for (int i = 0; i < 8; i++) {
            o[i][0] *= alpha0; o[i][1] *= alpha0;
            o[i][2] *= alpha1; o[i][3] *= alpha1;
        }

#pragma unroll
        for (int kk = 0; kk < 8; kk++) {
            uint32_t ph[4];
            ph[0] = pack_h16(c[2 * kk][0], c[2 * kk][1]);
            ph[1] = pack_h16(c[2 * kk][2], c[2 * kk][3]);
            ph[2] = pack_h16(c[2 * kk + 1][0], c[2 * kk + 1][1]);
            ph[3] = pack_h16(c[2 * kk + 1][2], c[2 * kk + 1][3]);
#pragma unroll
            for (int nj = 0; nj < 4; nj++) {
                uint32_t vh[4];
                uint32_t ro = (uint32_t)((kk * 16 + (lane & 15)) * AST
                                         + (nj * 16 + (lane >> 4) * 8) * 2);
                ldsm4t(vh, sb + AT_V(vb) + ro);
                mma_f16(o[2 * nj],     ph, vh[0], vh[1]);
                mma_f16(o[2 * nj + 1], ph, vh[2], vh[3]);
            }
        }

        if (kt + 1 < KVTILES) CP_ASYNC_WAIT_ALL();
        __syncthreads();
    }

    const int b = bh >> 4, h = bh & 15;
    const float inv0 = 1.0f / l0, inv1 = 1.0f / l1;
    const size_t row0 = (size_t)(b * SEQ + qt * 256 + w * 16 + (lane >> 2));
#pragma unroll
    for (int on = 0; on < 8; on++) {
        const int colg = h * DK + on * 8 + (lane & 3) * 2;
        *(uint32_t*)(g_ctx16 + row0 * D_MODEL + colg) = pack_h16(o[on][0] * inv0, o[on][1] * inv0);
        *(uint32_t*)(g_ctx16 + (row0 + 8) * D_MODEL + colg) = pack_h16(o[on][2] * inv1, o[on][3] * inv1);
    }
}

// ============================================================================
// launch
// ============================================================================
extern "C" void kernel_launch(void* const* d_in, const int* in_sizes, int n_in,
                              void* d_out, int out_size)
{
    const float* query  = (const float*)d_in[0];
    const float* key_in = (const float*)d_in[1];
    const float* value  = (const float*)d_in[2];
    const float* Wq = (const float*)d_in[3];
    const float* bq = (const float*)d_in[4];
    const float* Wk = (const float*)d_in[5];
    const float* bk = (const float*)d_in[6];
    const float* Wv = (const float*)d_in[7];
    const float* bv = (const float*)d_in[8];
    const float* Wo = (const float*)d_in[9];
    const float* bo = (const float*)d_in[10];
    float* out = (float*)d_out;

    __half *q16, *k16, *v16, *ctx16, *a16, *w16;
    cudaGetSymbolAddress((void**)&q16, g_Q16);
    cudaGetSymbolAddress((void**)&k16, g_K16);
    cudaGetSymbolAddress((void**)&v16, g_V16);
    cudaGetSymbolAddress((void**)&ctx16, g_ctx16);
    cudaGetSymbolAddress((void**)&a16, g_a16);
    cudaGetSymbolAddress((void**)&w16, g_w16);

    cudaFuncSetAttribute(gemm_qkv16, cudaFuncAttributeMaxDynamicSharedMemorySize, GEMM16_SMEM);
    cudaFuncSetAttribute(gemm_out16, cudaFuncAttributeMaxDynamicSharedMemorySize, GEMM16_SMEM);
    cudaFuncSetAttribute(attn_tc, cudaFuncAttributeMaxDynamicSharedMemorySize, ATTN_SMEM);

    const int ACT4 = MROWS * D_MODEL / 4;
    const int W4   = D_MODEL * D_MODEL / 4;
    const size_t WSL = (size_t)D_MODEL * D_MODEL;

    // conversions (single fp16)
    conv_w4<<<dim3((W4 + 255) / 256, 4), 256>>>(Wq, Wk, Wv, Wo, w16, W4);
    conv_a3<<<dim3((ACT4 + 255) / 256, 3), 256>>>(query, key_in, value, a16, ACT4);

    // fused Q/K/V projections (pure fp16)
    gemm_qkv16<<<dim3(D_MODEL / 128, MROWS / 128, 3), 256, GEMM16_SMEM>>>(
        a16, w16, bq, bk, bv, q16, k16, v16);

    // attention
    attn_tc<<<dim3(SEQ / 256, BATCH * NUM_HEADS), dim3(512), ATTN_SMEM>>>();

    // output projection
    gemm_out16<<<dim3(D_MODEL / 128, MROWS / 128), 256, GEMM16_SMEM>>>(
        ctx16, w16 + 3 * WSL, bo, out);
}

// round 11
// speedup vs baseline: 7.2872x; 1.0535x over previous
#include <cuda_runtime.h>
#include <cuda_fp16.h>
#include <cstdint>

#define D_MODEL 1024
#define NUM_HEADS 16
#define DK 64
#define BATCH 4
#define SEQ 2048
#define MROWS (BATCH * SEQ)   /* 8192 */
#define KVTILES (SEQ / 128)   /* 16 */

// ---------------- scratch (all single fp16) ----------------
__device__ __half g_Q16[BATCH * NUM_HEADS * SEQ * DK];
__device__ __half g_K16[BATCH * NUM_HEADS * SEQ * DK];
__device__ __half g_V16[BATCH * NUM_HEADS * SEQ * DK];
__device__ __half g_ctx16[MROWS * D_MODEL];
__device__ __half g_a16[3 * MROWS * D_MODEL];     // query,key,value acts
__device__ __half g_w16[4 * D_MODEL * D_MODEL];   // Wq,Wk,Wv,Wo

// ---------------- helpers ----------------
__device__ __forceinline__ uint32_t smem_u32(const void* p) {
    uint32_t a;
    asm("{ .reg .u64 t; cvta.to.shared.u64 t, %1; cvt.u32.u64 %0, t; }" : "=r"(a) : "l"(p));
    return a;
}
#define CP_ASYNC16(saddr, gptr) \
    asm volatile("cp.async.cg.shared.global [%0], [%1], 16;" :: "r"((uint32_t)(saddr)), "l"(gptr))
#define CP_ASYNC_COMMIT()    asm volatile("cp.async.commit_group;" ::: "memory")
#define CP_ASYNC_WAIT_ALL()  asm volatile("cp.async.wait_group 0;" ::: "memory")
#define CP_ASYNC_WAIT_1()    asm volatile("cp.async.wait_group 1;" ::: "memory")

__device__ __forceinline__ void ldsm4(uint32_t r[4], uint32_t a) {
    asm volatile("ldmatrix.sync.aligned.m8n8.x4.shared.b16 {%0,%1,%2,%3}, [%4];"
        : "=r"(r[0]), "=r"(r[1]), "=r"(r[2]), "=r"(r[3]) : "r"(a));
}
__device__ __forceinline__ void ldsm4t(uint32_t r[4], uint32_t a) {
    asm volatile("ldmatrix.sync.aligned.m8n8.x4.trans.shared.b16 {%0,%1,%2,%3}, [%4];"
        : "=r"(r[0]), "=r"(r[1]), "=r"(r[2]), "=r"(r[3]) : "r"(a));
}
__device__ __forceinline__ void mma_f16(float c[4], const uint32_t a[4], uint32_t b0, uint32_t b1) {
    asm volatile("mma.sync.aligned.m16n8k16.row.col.f32.f16.f16.f32 "
        "{%0,%1,%2,%3}, {%4,%5,%6,%7}, {%8,%9}, {%0,%1,%2,%3};"
        : "+f"(c[0]), "+f"(c[1]), "+f"(c[2]), "+f"(c[3])
        : "r"(a[0]), "r"(a[1]), "r"(a[2]), "r"(a[3]), "r"(b0), "r"(b1));
}
__device__ __forceinline__ uint32_t pack_h16(float x, float y) {
    __half2 h = __floats2half2_rn(x, y);
    return *(uint32_t*)&h;
}

// ============================================================================
// conversions (single fp16 only)
// ============================================================================
__global__ __launch_bounds__(256) void conv_w4(
    const float* __restrict__ x0, const float* __restrict__ x1,
    const float* __restrict__ x2, const float* __restrict__ x3,
    __half* __restrict__ h16, int n4)
{
    int i = blockIdx.x * blockDim.x + threadIdx.x;
    if (i >= n4) return;
    const float* x = (blockIdx.y == 0) ? x0 : (blockIdx.y == 1) ? x1
                   : (blockIdx.y == 2) ? x2 : x3;
    size_t o = (size_t)blockIdx.y * n4 + i;
    float4 v = ((const float4*)x)[i];
    uint2 H;
    H.x = pack_h16(v.x, v.y); H.y = pack_h16(v.z, v.w);
    ((uint2*)h16)[o] = H;
}
__global__ __launch_bounds__(256) void conv_a3(
    const float* __restrict__ x0, const float* __restrict__ x1,
    const float* __restrict__ x2, __half* __restrict__ h16, int n4)
{
    int i = blockIdx.x * blockDim.x + threadIdx.x;
    if (i >= n4) return;
    const float* x = (blockIdx.y == 0) ? x0 : (blockIdx.y == 1) ? x1 : x2;
    size_t o = (size_t)blockIdx.y * n4 + i;
    float4 v = ((const float4*)x)[i];
    uint2 H;
    H.x = pack_h16(v.x, v.y); H.y = pack_h16(v.z, v.w);
    ((uint2*)h16)[o] = H;
}

// ============================================================================
// fp16 1-term GEMM. BM=BN=128, BK=64, 8 warps, 3-stage cp.async pipeline.
// ============================================================================
#define BK 64
#define GST 144                    /* row stride bytes: (64+8) fp16 */
#define MAT16 (128 * GST)          /* 18432 B */
#define STG16 (2 * MAT16)          /* 36864 B per stage */
#define NIT (D_MODEL / BK)         /* 16 */
#define NSTG 3
#define GEMM16_SMEM (NSTG * STG16) /* 110592 B */

__device__ __forceinline__ void gemm16_main(
    uint32_t sb, int t,
    const __half* __restrict__ A, const __half* __restrict__ W,
    int m0, int n0, float c[4][4][4])
{
    const int lane = t & 31, wid = t >> 5;
    const int wm = wid >> 2, wn = wid & 3;

    auto load_stage = [&](int s, int it) {
        const int k0 = it * BK;
        const uint32_t st = sb + s * STG16;
#pragma unroll
        for (int j = 0; j < 4; j++) {
            int idx = t + j * 256;
            int r = idx >> 3, cc = idx & 7;
            uint32_t so = (uint32_t)(r * GST + cc * 16);
            CP_ASYNC16(st + 0 * MAT16 + so, A + (size_t)(m0 + r) * D_MODEL + k0 + cc * 8);
            CP_ASYNC16(st + 1 * MAT16 + so, W + (size_t)(n0 + r) * D_MODEL + k0 + cc * 8);
        }
    };

    load_stage(0, 0);
    CP_ASYNC_COMMIT();
    load_stage(1, 1);
    CP_ASYNC_COMMIT();

    for (int it = 0; it < NIT; ++it) {
        const int s = it % NSTG;
        CP_ASYNC_WAIT_1();       // stage it landed (≤1 group pending)
        __syncthreads();         // all warps done with stage (it-1) -> safe reuse
        if (it + 2 < NIT) {
            load_stage((it + 2) % NSTG, it + 2);
            CP_ASYNC_COMMIT();
        }
        const uint32_t st = sb + s * STG16;
#pragma unroll
        for (int kk = 0; kk < 4; kk++) {
            uint32_t ah[4][4];
#pragma unroll
            for (int mi = 0; mi < 4; mi++) {
                uint32_t ro = (uint32_t)((wm * 64 + mi * 16 + (lane & 15)) * GST
                                         + (kk * 16 + (lane >> 4) * 8) * 2);
                ldsm4(ah[mi], st + 0 * MAT16 + ro);
            }
            uint32_t bh_[2][4];
#pragma unroll
            for (int nj = 0; nj < 2; nj++) {
                uint32_t ro = (uint32_t)((wn * 32 + nj * 16 + (lane & 7) + ((lane >> 4) * 8)) * GST
                                         + (kk * 16 + ((lane >> 3) & 1) * 8) * 2);
                ldsm4(bh_[nj], st + 1 * MAT16 + ro);
            }
#pragma unroll
            for (int mi = 0; mi < 4; mi++)
#pragma unroll
                for (int ni = 0; ni < 4; ni++) {
                    const int nj = ni >> 1, ss = (ni & 1) * 2;
                    mma_f16(c[mi][ni], ah[mi], bh_[nj][ss], bh_[nj][ss + 1]);
                }
        }
    }
}

// ---- fused Q/K/V projections, single fp16 split-head outputs ----
// Q epilogue scale = 0.125 * log2(e): softmax runs in exp2 domain.
__global__ __launch_bounds__(256, 2) void gemm_qkv16(
    const __half* __restrict__ a16, const __half* __restrict__ w16,
    const float* __restrict__ bq, const float* __restrict__ bk,
    const float* __restrict__ bv,
    __half* __restrict__ q16, __half* __restrict__ k16, __half* __restrict__ v16)
{
    extern __shared__ char smem[];
    const uint32_t sb = smem_u32(smem);
    const int t = threadIdx.x;
    const int lane = t & 31, wid = t >> 5;
    const int wm = wid >> 2, wn = wid & 3;
    const int m0 = blockIdx.y * 128, n0 = blockIdx.x * 128;
    const int z = blockIdx.z;

    const __half* A = a16 + (size_t)z * MROWS * D_MODEL;
    const __half* W = w16 + (size_t)z * D_MODEL * D_MODEL;
    const float* bias = (z == 0) ? bq : (z == 1) ? bk : bv;
    __half* C = (z == 0) ? q16 : (z == 1) ? k16 : v16;
    const float oscale = (z == 0) ? 0.125f * 1.44269504088896f : 1.0f;

    float c[4][4][4];
#pragma unroll
    for (int i = 0; i < 4; i++)
#pragma unroll
        for (int j = 0; j < 4; j++)
#pragma unroll
            for (int k = 0; k < 4; k++) c[i][j][k] = 0.0f;

    gemm16_main(sb, t, A, W, m0, n0, c);

#pragma unroll
    for (int mi = 0; mi < 4; mi++) {
        const int r0 = m0 + wm * 64 + mi * 16 + (lane >> 2);
#pragma unroll
        for (int ni = 0; ni < 4; ni++) {
            const int col = n0 + wn * 32 + ni * 8 + (lane & 3) * 2;
            const float b0 = bias[col], b1 = bias[col + 1];
            const int h = col >> 6, d = col & 63;
            float v00 = (c[mi][ni][0] + b0) * oscale, v01 = (c[mi][ni][1] + b1) * oscale;
            float v10 = (c[mi][ni][2] + b0) * oscale, v11 = (c[mi][ni][3] + b1) * oscale;
#pragma unroll
            for (int rr = 0; rr < 2; rr++) {
                const int m = r0 + rr * 8;
                const int b = m >> 11, sdx = m & 2047;
                const size_t off = (((size_t)(b * NUM_HEADS + h) * SEQ + sdx) * DK + d);
                *(uint32_t*)(C + off) = pack_h16(rr ? v10 : v00, rr ? v11 : v01);
            }
        }
    }
}

// ---- output projection: fp32 row-major out ----
__global__ __launch_bounds__(256, 2) void gemm_out16(
    const __half* __restrict__ A, const __half* __restrict__ W,
    const float* __restrict__ bias, float* __restrict__ Cf)
{
    extern __shared__ char smem[];
    const uint32_t sb = smem_u32(smem);
    const int t = threadIdx.x;
    const int lane = t & 31, wid = t >> 5;
    const int wm = wid >> 2, wn = wid & 3;
    const int m0 = blockIdx.y * 128, n0 = blockIdx.x * 128;

    float c[4][4][4];
#pragma unroll
    for (int i = 0; i < 4; i++)
#pragma unroll
        for (int j = 0; j < 4; j++)
#pragma unroll
            for (int k = 0; k < 4; k++) c[i][j][k] = 0.0f;

    gemm16_main(sb, t, A, W, m0, n0, c);

#pragma unroll
    for (int mi = 0; mi < 4; mi++) {
        const int r0 = m0 + wm * 64 + mi * 16 + (lane >> 2);
#pragma unroll
        for (int ni = 0; ni < 4; ni++) {
            const int col = n0 + wn * 32 + ni * 8 + (lane & 3) * 2;
            const float b0 = bias[col], b1 = bias[col + 1];
            *(float2*)(Cf + (size_t)r0 * D_MODEL + col) =
                make_float2(c[mi][ni][0] + b0, c[mi][ni][1] + b1);
            *(float2*)(Cf + (size_t)(r0 + 8) * D_MODEL + col) =
                make_float2(c[mi][ni][2] + b0, c[mi][ni][3] + b1);
        }
    }
}

// ============================================================================
// FA2 attention (exp2-domain softmax; scores arrive pre-scaled by 0.125*log2e)
// ============================================================================
#define AST 144
#define AT_Q  0
#define AT_K(b) (AT_Q + 256 * AST + (b) * (128 * AST))
#define AT_V(b) (AT_Q + 256 * AST + 2 * (128 * AST) + (b) * (128 * AST))
#define ATTN_SMEM (256 * AST + 4 * (128 * AST))   /* 110592 B */

__global__ __launch_bounds__(512) void attn_tc()
{
    extern __shared__ char smem[];
    const uint32_t sb = smem_u32(smem);
    const int t = threadIdx.x;
    const int lane = t & 31, w = t >> 5;
    const int qt = blockIdx.x, bh = blockIdx.y;

    const __half* Qs = g_Q16 + ((size_t)bh * SEQ + qt * 256) * DK;
    const __half* Kg = g_K16 + (size_t)bh * SEQ * DK;
    const __half* Vg = g_V16 + (size_t)bh * SEQ * DK;

    auto ldtile = [&](uint32_t dstoff, const __half* src) {
#pragma unroll
        for (int j = 0; j < 2; j++) {
            int idx = t + j * 512;
            int r = idx >> 3, cc = idx & 7;
            CP_ASYNC16(sb + dstoff + r * AST + cc * 16, src + r * DK + cc * 8);
        }
    };
    auto ldtileQ = [&](uint32_t dstoff, const __half* src) {
#pragma unroll
        for (int j = 0; j < 4; j++) {
            int idx = t + j * 512;
            int r = idx >> 3, cc = idx & 7;
            CP_ASYNC16(sb + dstoff + r * AST + cc * 16, src + r * DK + cc * 8);
        }
    };

    ldtileQ(AT_Q, Qs);
    ldtile(AT_K(0), Kg);
    ldtile(AT_V(0), Vg);
    CP_ASYNC_COMMIT();
    CP_ASYNC_WAIT_ALL();
    __syncthreads();

    float o[8][4];
#pragma unroll
    for (int i = 0; i < 8; i++)
#pragma unroll
        for (int k = 0; k < 4; k++) o[i][k] = 0.0f;
    float m0 = -1e30f, m1 = -1e30f, l0 = 0.0f, l1 = 0.0f;

    for (int kt = 0; kt < KVTILES; kt++) {
        const int vb = kt & 1;

        if (kt + 1 < KVTILES) {
            ldtile(AT_K(vb ^ 1), Kg + (size_t)(kt + 1) * 128 * DK);
            ldtile(AT_V(vb ^ 1), Vg + (size_t)(kt + 1) * 128 * DK);
            CP_ASYNC_COMMIT();
        }

        // ---- S' = Q' K^T  (already in log2 units) ----
        float c[16][4];
#pragma unroll
        for (int i = 0; i < 16; i++)
#pragma unroll
            for (int k = 0; k < 4; k++) c[i][k] = 0.0f;

#pragma unroll
        for (int kk = 0; kk < 4; kk++) {
            uint32_t q[4];
            {
                uint32_t ro = (uint32_t)((w * 16 + (lane & 15)) * AST
                                         + (kk * 16 + (lane >> 4) * 8) * 2);
                ldsm4(q, sb + AT_Q + ro);
            }
#pragma unroll
            for (int nj = 0; nj < 8; nj++) {
                uint32_t bk_[4];
                uint32_t ro = (uint32_t)((nj * 16 + (lane & 7) + ((lane >> 4) * 8)) * AST
                                         + (kk * 16 + ((lane >> 3) & 1) * 8) * 2);
                ldsm4(bk_, sb + AT_K(vb) + ro);
                mma_f16(c[2 * nj],     q, bk_[0], bk_[1]);
                mma_f16(c[2 * nj + 1], q, bk_[2], bk_[3]);
            }
        }

        // ---- warp-local online softmax (exp2 domain) ----
        float mx0 = -1e30f, mx1 = -1e30f;
#pragma unroll
        for (int ni = 0; ni < 16; ni++) {
            mx0 = fmaxf(mx0, fmaxf(c[ni][0], c[ni][1]));
            mx1 = fmaxf(mx1, fmaxf(c[ni][2], c[ni][3]));
        }
        mx0 = fmaxf(mx0, __shfl_xor_sync(0xffffffffu, mx0, 1));
        mx0 = fmaxf(mx0, __shfl_xor_sync(0xffffffffu, mx0, 2));
        mx1 = fmaxf(mx1, __shfl_xor_sync(0xffffffffu, mx1, 1));
        mx1 = fmaxf(mx1, __shfl_xor_sync(0xffffffffu, mx1, 2));

        const float nm0 = fmaxf(m0, mx0), nm1 = fmaxf(m1, mx1);
        const float alpha0 = exp2f(m0 - nm0), alpha1 = exp2f(m1 - nm1);
        m0 = nm0; m1 = nm1;

        float s0 = 0.0f, s1 = 0.0f;
#pragma unroll
        for (int ni = 0; ni < 16; ni++) {
            c[ni][0] = exp2f(c[ni][0] - nm0);
            c[ni][1] = exp2f(c[ni][1] - nm0);
            c[ni][2] = exp2f(c[ni][2] - nm1);
            c[ni][3] = exp2f(c[ni][3] - nm1);
            s0 += c[ni][0] + c[ni][1];
            s1 += c[ni][2] + c[ni][3];
        }
        s0 += __shfl_xor_sync(0xffffffffu, s0, 1);
        s0 += __shfl_xor_sync(0xffffffffu, s0, 2);
        s1 += __shfl_xor_sync(0xffffffffu, s1, 1);
        s1 += __shfl_xor_sync(0xffffffffu, s1, 2);
        l0 = l0 * alpha0 + s0;
        l1 = l1 * alpha1 + s1;

#pragma unroll
        for (int i = 0; i < 8; i++) {
            o[i][0] *= alpha0; o[i][1] *= alpha0;
            o[i][2] *= alpha1; o[i][3] *= alpha1;
        }

        // ---- O += P V ----
#pragma unroll
        for (int kk = 0; kk < 8; kk++) {
            uint32_t ph[4];
            ph[0] = pack_h16(c[2 * kk][0], c[2 * kk][1]);
            ph[1] = pack_h16(c[2 * kk][2], c[2 * kk][3]);
            ph[2] = pack_h16(c[2 * kk + 1][0], c[2 * kk + 1][1]);
            ph[3] = pack_h16(c[2 * kk + 1][2], c[2 * kk + 1][3]);
#pragma unroll
            for (int nj = 0; nj < 4; nj++) {
                uint32_t vh[4];
                uint32_t ro = (uint32_t)((kk * 16 + (lane & 15)) * AST
                                         + (nj * 16 + (lane >> 4) * 8) * 2);
                ldsm4t(vh, sb + AT_V(vb) + ro);
                mma_f16(o[2 * nj],     ph, vh[0], vh[1]);
                mma_f16(o[2 * nj + 1], ph, vh[2], vh[3]);
            }
        }

        if (kt + 1 < KVTILES) CP_ASYNC_WAIT_ALL();
        __syncthreads();
    }

    const int b = bh >> 4, h = bh & 15;
    const float inv0 = 1.0f / l0, inv1 = 1.0f / l1;
    const size_t row0 = (size_t)(b * SEQ + qt * 256 + w * 16 + (lane >> 2));
#pragma unroll
    for (int on = 0; on < 8; on++) {
        const int colg = h * DK + on * 8 + (lane & 3) * 2;
        *(uint32_t*)(g_ctx16 + row0 * D_MODEL + colg) = pack_h16(o[on][0] * inv0, o[on][1] * inv0);
        *(uint32_t*)(g_ctx16 + (row0 + 8) * D_MODEL + colg) = pack_h16(o[on][2] * inv1, o[on][3] * inv1);
    }
}

// ============================================================================
// launch
// ============================================================================
extern "C" void kernel_launch(void* const* d_in, const int* in_sizes, int n_in,
                              void* d_out, int out_size)
{
    const float* query  = (const float*)d_in[0];
    const float* key_in = (const float*)d_in[1];
    const float* value  = (const float*)d_in[2];
    const float* Wq = (const float*)d_in[3];
    const float* bq = (const float*)d_in[4];
    const float* Wk = (const float*)d_in[5];
    const float* bk = (const float*)d_in[6];
    const float* Wv = (const float*)d_in[7];
    const float* bv = (const float*)d_in[8];
    const float* Wo = (const float*)d_in[9];
    const float* bo = (const float*)d_in[10];
    float* out = (float*)d_out;

    __half *q16, *k16, *v16, *ctx16, *a16, *w16;
    cudaGetSymbolAddress((void**)&q16, g_Q16);
    cudaGetSymbolAddress((void**)&k16, g_K16);
    cudaGetSymbolAddress((void**)&v16, g_V16);
    cudaGetSymbolAddress((void**)&ctx16, g_ctx16);
    cudaGetSymbolAddress((void**)&a16, g_a16);
    cudaGetSymbolAddress((void**)&w16, g_w16);

    cudaFuncSetAttribute(gemm_qkv16, cudaFuncAttributeMaxDynamicSharedMemorySize, GEMM16_SMEM);
    cudaFuncSetAttribute(gemm_out16, cudaFuncAttributeMaxDynamicSharedMemorySize, GEMM16_SMEM);
    cudaFuncSetAttribute(attn_tc, cudaFuncAttributeMaxDynamicSharedMemorySize, ATTN_SMEM);

    const int ACT4 = MROWS * D_MODEL / 4;
    const int W4   = D_MODEL * D_MODEL / 4;
    const size_t WSL = (size_t)D_MODEL * D_MODEL;

    conv_w4<<<dim3((W4 + 255) / 256, 4), 256>>>(Wq, Wk, Wv, Wo, w16, W4);
    conv_a3<<<dim3((ACT4 + 255) / 256, 3), 256>>>(query, key_in, value, a16, ACT4);

    gemm_qkv16<<<dim3(D_MODEL / 128, MROWS / 128, 3), 256, GEMM16_SMEM>>>(
        a16, w16, bq, bk, bv, q16, k16, v16);

    attn_tc<<<dim3(SEQ / 256, BATCH * NUM_HEADS), dim3(512), ATTN_SMEM>>>();

    gemm_out16<<<dim3(D_MODEL / 128, MROWS / 128), 256, GEMM16_SMEM>>>(
        ctx16, w16 + 3 * WSL, bo, out);
}

// round 12
// speedup vs baseline: 7.7008x; 1.0568x over previous
#include <cuda_runtime.h>
#include <cuda_fp16.h>
#include <cstdint>

#define D_MODEL 1024
#define NUM_HEADS 16
#define DK 64
#define BATCH 4
#define SEQ 2048
#define MROWS (BATCH * SEQ)   /* 8192 */
#define KVTILES (SEQ / 128)   /* 16 */

// ---------------- scratch (all single fp16) ----------------
__device__ __half g_Q16[BATCH * NUM_HEADS * SEQ * DK];
__device__ __half g_K16[BATCH * NUM_HEADS * SEQ * DK];
__device__ __half g_V16[BATCH * NUM_HEADS * SEQ * DK];
__device__ __half g_ctx16[MROWS * D_MODEL];
__device__ __half g_a16[3 * MROWS * D_MODEL];     // query,key,value acts
__device__ __half g_w16[4 * D_MODEL * D_MODEL];   // Wq,Wk,Wv,Wo

// ---------------- helpers ----------------
__device__ __forceinline__ uint32_t smem_u32(const void* p) {
    uint32_t a;
    asm("{ .reg .u64 t; cvta.to.shared.u64 t, %1; cvt.u32.u64 %0, t; }" : "=r"(a) : "l"(p));
    return a;
}
#define CP_ASYNC16(saddr, gptr) \
    asm volatile("cp.async.cg.shared.global [%0], [%1], 16;" :: "r"((uint32_t)(saddr)), "l"(gptr))
#define CP_ASYNC_COMMIT()    asm volatile("cp.async.commit_group;" ::: "memory")
#define CP_ASYNC_WAIT_ALL()  asm volatile("cp.async.wait_group 0;" ::: "memory")
#define CP_ASYNC_WAIT_1()    asm volatile("cp.async.wait_group 1;" ::: "memory")

__device__ __forceinline__ void ldsm4(uint32_t r[4], uint32_t a) {
    asm volatile("ldmatrix.sync.aligned.m8n8.x4.shared.b16 {%0,%1,%2,%3}, [%4];"
        : "=r"(r[0]), "=r"(r[1]), "=r"(r[2]), "=r"(r[3]) : "r"(a));
}
__device__ __forceinline__ void ldsm4t(uint32_t r[4], uint32_t a) {
    asm volatile("ldmatrix.sync.aligned.m8n8.x4.trans.shared.b16 {%0,%1,%2,%3}, [%4];"
        : "=r"(r[0]), "=r"(r[1]), "=r"(r[2]), "=r"(r[3]) : "r"(a));
}
__device__ __forceinline__ void mma_f16(float c[4], const uint32_t a[4], uint32_t b0, uint32_t b1) {
    asm volatile("mma.sync.aligned.m16n8k16.row.col.f32.f16.f16.f32 "
        "{%0,%1,%2,%3}, {%4,%5,%6,%7}, {%8,%9}, {%0,%1,%2,%3};"
        : "+f"(c[0]), "+f"(c[1]), "+f"(c[2]), "+f"(c[3])
        : "r"(a[0]), "r"(a[1]), "r"(a[2]), "r"(a[3]), "r"(b0), "r"(b1));
}
__device__ __forceinline__ uint32_t pack_h16(float x, float y) {
    __half2 h = __floats2half2_rn(x, y);
    return *(uint32_t*)&h;
}

// ============================================================================
// conversions (single fp16 only)
// ============================================================================
__global__ __launch_bounds__(256) void conv_w4(
    const float* __restrict__ x0, const float* __restrict__ x1,
    const float* __restrict__ x2, const float* __restrict__ x3,
    __half* __restrict__ h16, int n4)
{
    int i = blockIdx.x * blockDim.x + threadIdx.x;
    if (i >= n4) return;
    const float* x = (blockIdx.y == 0) ? x0 : (blockIdx.y == 1) ? x1
                   : (blockIdx.y == 2) ? x2 : x3;
    size_t o = (size_t)blockIdx.y * n4 + i;
    float4 v = ((const float4*)x)[i];
    uint2 H;
    H.x = pack_h16(v.x, v.y); H.y = pack_h16(v.z, v.w);
    ((uint2*)h16)[o] = H;
}
__global__ __launch_bounds__(256) void conv_a3(
    const float* __restrict__ x0, const float* __restrict__ x1,
    const float* __restrict__ x2, __half* __restrict__ h16, int n4)
{
    int i = blockIdx.x * blockDim.x + threadIdx.x;
    if (i >= n4) return;
    const float* x = (blockIdx.y == 0) ? x0 : (blockIdx.y == 1) ? x1 : x2;
    size_t o = (size_t)blockIdx.y * n4 + i;
    float4 v = ((const float4*)x)[i];
    uint2 H;
    H.x = pack_h16(v.x, v.y); H.y = pack_h16(v.z, v.w);
    ((uint2*)h16)[o] = H;
}

// ============================================================================
// fp16 1-term GEMM. BM=BN=128, BK=64, 8 warps, 3-stage cp.async pipeline.
// ============================================================================
#define BK 64
#define GST 144
#define MAT16 (128 * GST)
#define STG16 (2 * MAT16)
#define NIT (D_MODEL / BK)
#define NSTG 3
#define GEMM16_SMEM (NSTG * STG16)

__device__ __forceinline__ void gemm16_main(
    uint32_t sb, int t,
    const __half* __restrict__ A, const __half* __restrict__ W,
    int m0, int n0, float c[4][4][4])
{
    const int lane = t & 31, wid = t >> 5;
    const int wm = wid >> 2, wn = wid & 3;

    auto load_stage = [&](int s, int it) {
        const int k0 = it * BK;
        const uint32_t st = sb + s * STG16;
#pragma unroll
        for (int j = 0; j < 4; j++) {
            int idx = t + j * 256;
            int r = idx >> 3, cc = idx & 7;
            uint32_t so = (uint32_t)(r * GST + cc * 16);
            CP_ASYNC16(st + 0 * MAT16 + so, A + (size_t)(m0 + r) * D_MODEL + k0 + cc * 8);
            CP_ASYNC16(st + 1 * MAT16 + so, W + (size_t)(n0 + r) * D_MODEL + k0 + cc * 8);
        }
    };

    load_stage(0, 0);
    CP_ASYNC_COMMIT();
    load_stage(1, 1);
    CP_ASYNC_COMMIT();

    for (int it = 0; it < NIT; ++it) {
        const int s = it % NSTG;
        CP_ASYNC_WAIT_1();
        __syncthreads();
        if (it + 2 < NIT) {
            load_stage((it + 2) % NSTG, it + 2);
            CP_ASYNC_COMMIT();
        }
        const uint32_t st = sb + s * STG16;
#pragma unroll
        for (int kk = 0; kk < 4; kk++) {
            uint32_t ah[4][4];
#pragma unroll
            for (int mi = 0; mi < 4; mi++) {
                uint32_t ro = (uint32_t)((wm * 64 + mi * 16 + (lane & 15)) * GST
                                         + (kk * 16 + (lane >> 4) * 8) * 2);
                ldsm4(ah[mi], st + 0 * MAT16 + ro);
            }
            uint32_t bh_[2][4];
#pragma unroll
            for (int nj = 0; nj < 2; nj++) {
                uint32_t ro = (uint32_t)((wn * 32 + nj * 16 + (lane & 7) + ((lane >> 4) * 8)) * GST
                                         + (kk * 16 + ((lane >> 3) & 1) * 8) * 2);
                ldsm4(bh_[nj], st + 1 * MAT16 + ro);
            }
#pragma unroll
            for (int mi = 0; mi < 4; mi++)
#pragma unroll
                for (int ni = 0; ni < 4; ni++) {
                    const int nj = ni >> 1, ss = (ni & 1) * 2;
                    mma_f16(c[mi][ni], ah[mi], bh_[nj][ss], bh_[nj][ss + 1]);
                }
        }
    }
}

// ---- fused Q/K/V projections (Q scaled by 0.125*log2e for exp2 softmax) ----
__global__ __launch_bounds__(256, 2) void gemm_qkv16(
    const __half* __restrict__ a16, const __half* __restrict__ w16,
    const float* __restrict__ bq, const float* __restrict__ bk,
    const float* __restrict__ bv,
    __half* __restrict__ q16, __half* __restrict__ k16, __half* __restrict__ v16)
{
    extern __shared__ char smem[];
    const uint32_t sb = smem_u32(smem);
    const int t = threadIdx.x;
    const int lane = t & 31, wid = t >> 5;
    const int wm = wid >> 2, wn = wid & 3;
    const int m0 = blockIdx.y * 128, n0 = blockIdx.x * 128;
    const int z = blockIdx.z;

    const __half* A = a16 + (size_t)z * MROWS * D_MODEL;
    const __half* W = w16 + (size_t)z * D_MODEL * D_MODEL;
    const float* bias = (z == 0) ? bq : (z == 1) ? bk : bv;
    __half* C = (z == 0) ? q16 : (z == 1) ? k16 : v16;
    const float oscale = (z == 0) ? 0.125f * 1.44269504088896f : 1.0f;

    float c[4][4][4];
#pragma unroll
    for (int i = 0; i < 4; i++)
#pragma unroll
        for (int j = 0; j < 4; j++)
#pragma unroll
            for (int k = 0; k < 4; k++) c[i][j][k] = 0.0f;

    gemm16_main(sb, t, A, W, m0, n0, c);

#pragma unroll
    for (int mi = 0; mi < 4; mi++) {
        const int r0 = m0 + wm * 64 + mi * 16 + (lane >> 2);
#pragma unroll
        for (int ni = 0; ni < 4; ni++) {
            const int col = n0 + wn * 32 + ni * 8 + (lane & 3) * 2;
            const float b0 = bias[col], b1 = bias[col + 1];
            const int h = col >> 6, d = col & 63;
            float v00 = (c[mi][ni][0] + b0) * oscale, v01 = (c[mi][ni][1] + b1) * oscale;
            float v10 = (c[mi][ni][2] + b0) * oscale, v11 = (c[mi][ni][3] + b1) * oscale;
#pragma unroll
            for (int rr = 0; rr < 2; rr++) {
                const int m = r0 + rr * 8;
                const int b = m >> 11, sdx = m & 2047;
                const size_t off = (((size_t)(b * NUM_HEADS + h) * SEQ + sdx) * DK + d);
                *(uint32_t*)(C + off) = pack_h16(rr ? v10 : v00, rr ? v11 : v01);
            }
        }
    }
}

// ---- output projection: fp32 row-major out ----
__global__ __launch_bounds__(256, 2) void gemm_out16(
    const __half* __restrict__ A, const __half* __restrict__ W,
    const float* __restrict__ bias, float* __restrict__ Cf)
{
    extern __shared__ char smem[];
    const uint32_t sb = smem_u32(smem);
    const int t = threadIdx.x;
    const int lane = t & 31, wid = t >> 5;
    const int wm = wid >> 2, wn = wid & 3;
    const int m0 = blockIdx.y * 128, n0 = blockIdx.x * 128;

    float c[4][4][4];
#pragma unroll
    for (int i = 0; i < 4; i++)
#pragma unroll
        for (int j = 0; j < 4; j++)
#pragma unroll
            for (int k = 0; k < 4; k++) c[i][j][k] = 0.0f;

    gemm16_main(sb, t, A, W, m0, n0, c);

#pragma unroll
    for (int mi = 0; mi < 4; mi++) {
        const int r0 = m0 + wm * 64 + mi * 16 + (lane >> 2);
#pragma unroll
        for (int ni = 0; ni < 4; ni++) {
            const int col = n0 + wn * 32 + ni * 8 + (lane & 3) * 2;
            const float b0 = bias[col], b1 = bias[col + 1];
            *(float2*)(Cf + (size_t)r0 * D_MODEL + col) =
                make_float2(c[mi][ni][0] + b0, c[mi][ni][1] + b1);
            *(float2*)(Cf + (size_t)(r0 + 8) * D_MODEL + col) =
                make_float2(c[mi][ni][2] + b0, c[mi][ni][3] + b1);
        }
    }
}

// ============================================================================
// FA2 attention: 256 threads / 8 warps / 128 q-rows per CTA, 2 CTAs/SM.
// Per-warp tile unchanged (16 rows x 128 cols, register-resident P).
// exp2-domain softmax (Q pre-scaled). smem 92.2 KB.
// ============================================================================
#define AST 144
#define AT_Q  0
#define AT_K(b) (AT_Q + 128 * AST + (b) * (128 * AST))
#define AT_V(b) (AT_Q + 128 * AST + 2 * (128 * AST) + (b) * (128 * AST))
#define ATTN_SMEM (128 * AST + 4 * (128 * AST))   /* 92160 B */

__global__ __launch_bounds__(256, 2) void attn_tc()
{
    extern __shared__ char smem[];
    const uint32_t sb = smem_u32(smem);
    const int t = threadIdx.x;
    const int lane = t & 31, w = t >> 5;     // 8 warps; warp w owns rows w*16..+15
    const int qt = blockIdx.x, bh = blockIdx.y;

    const __half* Qs = g_Q16 + ((size_t)bh * SEQ + qt * 128) * DK;
    const __half* Kg = g_K16 + (size_t)bh * SEQ * DK;
    const __half* Vg = g_V16 + (size_t)bh * SEQ * DK;

    auto ldtile = [&](uint32_t dstoff, const __half* src) {   // 128x64 fp16
#pragma unroll
        for (int j = 0; j < 4; j++) {
            int idx = t + j * 256;
            int r = idx >> 3, cc = idx & 7;
            CP_ASYNC16(sb + dstoff + r * AST + cc * 16, src + r * DK + cc * 8);
        }
    };

    ldtile(AT_Q, Qs);
    ldtile(AT_K(0), Kg);
    ldtile(AT_V(0), Vg);
    CP_ASYNC_COMMIT();
    CP_ASYNC_WAIT_ALL();
    __syncthreads();

    float o[8][4];
#pragma unroll
    for (int i = 0; i < 8; i++)
#pragma unroll
        for (int k = 0; k < 4; k++) o[i][k] = 0.0f;
    float m0 = -1e30f, m1 = -1e30f, l0 = 0.0f, l1 = 0.0f;

    for (int kt = 0; kt < KVTILES; kt++) {
        const int vb = kt & 1;

        if (kt + 1 < KVTILES) {
            ldtile(AT_K(vb ^ 1), Kg + (size_t)(kt + 1) * 128 * DK);
            ldtile(AT_V(vb ^ 1), Vg + (size_t)(kt + 1) * 128 * DK);
            CP_ASYNC_COMMIT();
        }

        // ---- S' = Q' K^T  (log2 units) ----
        float c[16][4];
#pragma unroll
        for (int i = 0; i < 16; i++)
#pragma unroll
            for (int k = 0; k < 4; k++) c[i][k] = 0.0f;

#pragma unroll
        for (int kk = 0; kk < 4; kk++) {
            uint32_t q[4];
            {
                uint32_t ro = (uint32_t)((w * 16 + (lane & 15)) * AST
                                         + (kk * 16 + (lane >> 4) * 8) * 2);
                ldsm4(q, sb + AT_Q + ro);
            }
#pragma unroll
            for (int nj = 0; nj < 8; nj++) {
                uint32_t bk_[4];
                uint32_t ro = (uint32_t)((nj * 16 + (lane & 7) + ((lane >> 4) * 8)) * AST
                                         + (kk * 16 + ((lane >> 3) & 1) * 8) * 2);
                ldsm4(bk_, sb + AT_K(vb) + ro);
                mma_f16(c[2 * nj],     q, bk_[0], bk_[1]);
                mma_f16(c[2 * nj + 1], q, bk_[2], bk_[3]);
            }
        }

        // ---- warp-local online softmax (exp2 domain) ----
        float mx0 = -1e30f, mx1 = -1e30f;
#pragma unroll
        for (int ni = 0; ni < 16; ni++) {
            mx0 = fmaxf(mx0, fmaxf(c[ni][0], c[ni][1]));
            mx1 = fmaxf(mx1, fmaxf(c[ni][2], c[ni][3]));
        }
        mx0 = fmaxf(mx0, __shfl_xor_sync(0xffffffffu, mx0, 1));
        mx0 = fmaxf(mx0, __shfl_xor_sync(0xffffffffu, mx0, 2));
        mx1 = fmaxf(mx1, __shfl_xor_sync(0xffffffffu, mx1, 1));
        mx1 = fmaxf(mx1, __shfl_xor_sync(0xffffffffu, mx1, 2));

        const float nm0 = fmaxf(m0, mx0), nm1 = fmaxf(m1, mx1);
        const float alpha0 = exp2f(m0 - nm0), alpha1 = exp2f(m1 - nm1);
        m0 = nm0; m1 = nm1;

        float s0 = 0.0f, s1 = 0.0f;
#pragma unroll
        for (int ni = 0; ni < 16; ni++) {
            c[ni][0] = exp2f(c[ni][0] - nm0);
            c[ni][1] = exp2f(c[ni][1] - nm0);
            c[ni][2] = exp2f(c[ni][2] - nm1);
            c[ni][3] = exp2f(c[ni][3] - nm1);
            s0 += c[ni][0] + c[ni][1];
            s1 += c[ni][2] + c[ni][3];
        }
        s0 += __shfl_xor_sync(0xffffffffu, s0, 1);
        s0 += __shfl_xor_sync(0xffffffffu, s0, 2);
        s1 += __shfl_xor_sync(0xffffffffu, s1, 1);
        s1 += __shfl_xor_sync(0xffffffffu, s1, 2);
        l0 = l0 * alpha0 + s0;
        l1 = l1 * alpha1 + s1;

#pragma unroll
        for (int i = 0; i < 8; i++) {
            o[i][0] *= alpha0; o[i][1] *= alpha0;
            o[i][2] *= alpha1; o[i][3] *= alpha1;
        }

        // ---- O += P V ----
#pragma unroll
        for (int kk = 0; kk < 8; kk++) {
            uint32_t ph[4];
            ph[0] = pack_h16(c[2 * kk][0], c[2 * kk][1]);
            ph[1] = pack_h16(c[2 * kk][2], c[2 * kk][3]);
            ph[2] = pack_h16(c[2 * kk + 1][0], c[2 * kk + 1][1]);
            ph[3] = pack_h16(c[2 * kk + 1][2], c[2 * kk + 1][3]);
#pragma unroll
            for (int nj = 0; nj < 4; nj++) {
                uint32_t vh[4];
                uint32_t ro = (uint32_t)((kk * 16 + (lane & 15)) * AST
                                         + (nj * 16 + (lane >> 4) * 8) * 2);
                ldsm4t(vh, sb + AT_V(vb) + ro);
                mma_f16(o[2 * nj],     ph, vh[0], vh[1]);
                mma_f16(o[2 * nj + 1], ph, vh[2], vh[3]);
            }
        }

        if (kt + 1 < KVTILES) CP_ASYNC_WAIT_ALL();
        __syncthreads();
    }

    // ---- epilogue ----
    const int b = bh >> 4, h = bh & 15;
    const float inv0 = 1.0f / l0, inv1 = 1.0f / l1;
    const size_t row0 = (size_t)(b * SEQ + qt * 128 + w * 16 + (lane >> 2));
#pragma unroll
    for (int on = 0; on < 8; on++) {
        const int colg = h * DK + on * 8 + (lane & 3) * 2;
        *(uint32_t*)(g_ctx16 + row0 * D_MODEL + colg) = pack_h16(o[on][0] * inv0, o[on][1] * inv0);
        *(uint32_t*)(g_ctx16 + (row0 + 8) * D_MODEL + colg) = pack_h16(o[on][2] * inv1, o[on][3] * inv1);
    }
}

// ============================================================================
// launch
// ============================================================================
extern "C" void kernel_launch(void* const* d_in, const int* in_sizes, int n_in,
                              void* d_out, int out_size)
{
    const float* query  = (const float*)d_in[0];
    const float* key_in = (const float*)d_in[1];
    const float* value  = (const float*)d_in[2];
    const float* Wq = (const float*)d_in[3];
    const float* bq = (const float*)d_in[4];
    const float* Wk = (const float*)d_in[5];
    const float* bk = (const float*)d_in[6];
    const float* Wv = (const float*)d_in[7];
    const float* bv = (const float*)d_in[8];
    const float* Wo = (const float*)d_in[9];
    const float* bo = (const float*)d_in[10];
    float* out = (float*)d_out;

    __half *q16, *k16, *v16, *ctx16, *a16, *w16;
    cudaGetSymbolAddress((void**)&q16, g_Q16);
    cudaGetSymbolAddress((void**)&k16, g_K16);
    cudaGetSymbolAddress((void**)&v16, g_V16);
    cudaGetSymbolAddress((void**)&ctx16, g_ctx16);
    cudaGetSymbolAddress((void**)&a16, g_a16);
    cudaGetSymbolAddress((void**)&w16, g_w16);

    cudaFuncSetAttribute(gemm_qkv16, cudaFuncAttributeMaxDynamicSharedMemorySize, GEMM16_SMEM);
    cudaFuncSetAttribute(gemm_out16, cudaFuncAttributeMaxDynamicSharedMemorySize, GEMM16_SMEM);
    cudaFuncSetAttribute(attn_tc, cudaFuncAttributeMaxDynamicSharedMemorySize, ATTN_SMEM);

    const int ACT4 = MROWS * D_MODEL / 4;
    const int W4   = D_MODEL * D_MODEL / 4;
    const size_t WSL = (size_t)D_MODEL * D_MODEL;

    conv_w4<<<dim3((W4 + 255) / 256, 4), 256>>>(Wq, Wk, Wv, Wo, w16, W4);
    conv_a3<<<dim3((ACT4 + 255) / 256, 3), 256>>>(query, key_in, value, a16, ACT4);

    gemm_qkv16<<<dim3(D_MODEL / 128, MROWS / 128, 3), 256, GEMM16_SMEM>>>(
        a16, w16, bq, bk, bv, q16, k16, v16);

    // attention: 128 q-rows/CTA, 2 CTAs/SM
    attn_tc<<<dim3(SEQ / 128, BATCH * NUM_HEADS), dim3(256), ATTN_SMEM>>>();

    gemm_out16<<<dim3(D_MODEL / 128, MROWS / 128), 256, GEMM16_SMEM>>>(
        ctx16, w16 + 3 * WSL, bo, out);
}